// round 3
// baseline (speedup 1.0000x reference)
#include <cuda_runtime.h>

typedef unsigned long long ull;

// ---------------- problem constants ----------------
constexpr int B    = 64;
constexpr int N    = 512;
constexpr int R    = B * N;      // 32768 rows

// ---------------- device scratch ----------------
__device__ float g_Wh3[(size_t)4 * R * 128];     // Wh per layer (0..2) + out-layer (3)
__device__ float g_heads[(size_t)R * 384];
__device__ float g_x[(size_t)R * 128];
__device__ float g_src3[4 * R];
__device__ float g_dst3[4 * R];

__device__ __forceinline__ float lrelu02(float x) { return x > 0.f ? x : 0.2f * x; }
__device__ __forceinline__ float elu1(float x)    { return x > 0.f ? x : expm1f(x); }

// f32x2 packed FMA helpers
__device__ __forceinline__ void fma2(ull& d, ull a, ull b) {
    asm("fma.rn.f32x2 %0, %1, %2, %3;" : "=l"(d) : "l"(a), "l"(b), "l"(d));
}
__device__ __forceinline__ ull pack2(float x) {
    ull r; asm("mov.b64 %0, {%1, %1};" : "=l"(r) : "f"(x)); return r;
}
__device__ __forceinline__ void unpack2(ull v, float& lo, float& hi) {
    asm("mov.b64 {%0, %1}, %2;" : "=f"(lo), "=f"(hi) : "l"(v));
}
union F4U { float4 f; ull u[2]; };

// ============ K1: blocked GEMM  Wh = X @ W,  fused src/dst = Wh @ a1/a2 ============
template<int FIN, int TK>
__global__ __launch_bounds__(256) void k_proj(
    const float* __restrict__ X, int ldx,
    const float* __restrict__ Wbase, const float* __restrict__ abase,
    float* __restrict__ Whout, float* __restrict__ srcout, float* __restrict__ dstout)
{
    __shared__ __align__(16) float WtS[TK][128];
    __shared__ __align__(16) float htT[TK][68];
    __shared__ float aS[256];

    const int l   = blockIdx.z;
    const float* W = Wbase + (size_t)l * FIN * 128;
    const float* a = abase + l * 256;
    float* Wh   = Whout + (size_t)l * R * 128;
    float* srcp = srcout + (size_t)l * R;
    float* dstp = dstout + (size_t)l * R;

    const int r0  = blockIdx.y * 512 + blockIdx.x * 64;
    const int tid = threadIdx.x;
    const int fg  = tid & 31;
    const int ig  = tid >> 5;

    aS[tid] = a[tid];

    ull acc2[4][4];
#pragma unroll
    for (int rp = 0; rp < 4; ++rp)
#pragma unroll
        for (int c = 0; c < 4; ++c) acc2[rp][c] = 0ull;

    for (int k0 = 0; k0 < FIN; k0 += TK) {
        __syncthreads();
        for (int e = tid; e < TK * 32; e += 256) {
            int k = e >> 5, c = e & 31;
            *reinterpret_cast<float4*>(&WtS[k][c * 4]) =
                *reinterpret_cast<const float4*>(&W[(size_t)(k0 + k) * 128 + c * 4]);
        }
        for (int e = tid; e < 64 * TK; e += 256) {
            int ii = e / TK, k = e - ii * TK;
            htT[k][ii] = X[(size_t)(r0 + ii) * ldx + k0 + k];
        }
        __syncthreads();

#pragma unroll 8
        for (int k = 0; k < TK; ++k) {
            float4 w = *reinterpret_cast<const float4*>(&WtS[k][fg * 4]);
            ull w0 = pack2(w.x), w1 = pack2(w.y), w2 = pack2(w.z), w3 = pack2(w.w);
            F4U p0, p1;
            p0.f = *reinterpret_cast<const float4*>(&htT[k][ig * 8]);
            p1.f = *reinterpret_cast<const float4*>(&htT[k][ig * 8 + 4]);
            ull pr[4] = {p0.u[0], p0.u[1], p1.u[0], p1.u[1]};
#pragma unroll
            for (int rp = 0; rp < 4; ++rp) {
                fma2(acc2[rp][0], pr[rp], w0);
                fma2(acc2[rp][1], pr[rp], w1);
                fma2(acc2[rp][2], pr[rp], w2);
                fma2(acc2[rp][3], pr[rp], w3);
            }
        }
    }

    float val[8][4];
#pragma unroll
    for (int rp = 0; rp < 4; ++rp)
#pragma unroll
        for (int c = 0; c < 4; ++c)
            unpack2(acc2[rp][c], val[2 * rp][c], val[2 * rp + 1][c]);

    float a1v[4], a2v[4];
#pragma unroll
    for (int c = 0; c < 4; ++c) { a1v[c] = aS[fg * 4 + c]; a2v[c] = aS[128 + fg * 4 + c]; }

#pragma unroll
    for (int rr = 0; rr < 8; ++rr) {
        int i = r0 + ig * 8 + rr;
        float4 o = make_float4(val[rr][0], val[rr][1], val[rr][2], val[rr][3]);
        *reinterpret_cast<float4*>(&Wh[(size_t)i * 128 + fg * 4]) = o;
        float v1 = val[rr][0] * a1v[0] + val[rr][1] * a1v[1] + val[rr][2] * a1v[2] + val[rr][3] * a1v[3];
        float v2 = val[rr][0] * a2v[0] + val[rr][1] * a2v[1] + val[rr][2] * a2v[2] + val[rr][3] * a2v[3];
#pragma unroll
        for (int o2 = 16; o2; o2 >>= 1) {
            v1 += __shfl_xor_sync(0xffffffffu, v1, o2);
            v2 += __shfl_xor_sync(0xffffffffu, v2, o2);
        }
        if (fg == 0) { srcp[i] = v1; dstp[i] = v2; }
    }
}

// ============ K3: fused softmax-stats + attention-aggregate ============
// One CTA = 64 rows x all 512 cols. Full P panel resident in dynamic smem.
constexpr int TI  = 64;
constexpr int PLD = 68;   // padded i-dim of P panel

// dynamic smem layout (floats):
//   PS   [512][PLD]   34816
//   WhS  [32][128]     4096
//   dstS [512]          512
//   srcS [64]            64
//   mS   [64]            64
//   rZS  [64]            64
//   red  [4][64]        256
//   adjS [64][33] ints  2112 ints
constexpr int SM_PS   = 0;
constexpr int SM_WHS  = SM_PS + 512 * PLD;
constexpr int SM_DST  = SM_WHS + 32 * 128;
constexpr int SM_SRC  = SM_DST + 512;
constexpr int SM_M    = SM_SRC + 64;
constexpr int SM_RZ   = SM_M + 64;
constexpr int SM_RED  = SM_RZ + 64;
constexpr int SM_ADJ  = SM_RED + 256;                 // int region
constexpr int SMEM_AGG_BYTES = SM_ADJ * 4 + 64 * 33 * 4;

__global__ __launch_bounds__(256) void k_agg(
    const int* __restrict__ adj, const float* __restrict__ Whp,
    const float* __restrict__ srcp, const float* __restrict__ dstp,
    float* __restrict__ outp, int ld, int col0base)
{
    extern __shared__ __align__(16) float dyn[];
    float* PS   = dyn + SM_PS;
    float* WhS  = dyn + SM_WHS;
    float* dstS = dyn + SM_DST;
    float* srcS = dyn + SM_SRC;
    float* mS   = dyn + SM_M;
    float* rZS  = dyn + SM_RZ;
    float* red  = dyn + SM_RED;
    int*   adjS = (int*)(dyn + SM_ADJ);

    const int b   = blockIdx.y;
    const int i0  = blockIdx.x * TI;
    const int tid = threadIdx.x;
    const int fg  = tid & 31;
    const int ig  = tid >> 5;
    const int ii  = tid & 63;   // stats-row
    const int jg  = tid >> 6;   // stats j-slice (0..3)

    for (int k = tid; k < 512; k += 256) dstS[k] = dstp[(b << 9) + k];
    if (tid < TI) srcS[tid] = srcp[(b << 9) + i0 + tid];
    __syncthreads();

    const size_t adj_base = ((size_t)(b << 9) + i0) * 512;
    const float si = srcS[ii];

    // ---- pass 1: raw masked scores into PS, track per-slice max ----
    float mloc = -3.4e38f;
    for (int t = 0; t < 16; ++t) {
        const int tj0 = t * 32;
        // stage adj chunk [64][32]
        for (int e = tid; e < 64 * 32; e += 256) {
            int ri = e >> 5, jj = e & 31;
            adjS[ri * 33 + jj] = adj[adj_base + (size_t)ri * 512 + tj0 + jj];
        }
        __syncthreads();
#pragma unroll
        for (int rr = 0; rr < 8; ++rr) {
            int j = jg * 8 + rr;
            float e2 = lrelu02(si + dstS[tj0 + j]);
            float sc = (adjS[ii * 33 + j] > 0) ? e2 : -9e15f;
            PS[(tj0 + j) * PLD + ii] = sc;
            mloc = fmaxf(mloc, sc);
        }
        __syncthreads();
    }
    red[jg * 64 + ii] = mloc;
    __syncthreads();
    if (tid < 64) {
        float m = fmaxf(fmaxf(red[tid], red[64 + tid]),
                        fmaxf(red[128 + tid], red[192 + tid]));
        mS[tid] = m;
    }
    __syncthreads();

    // ---- pass 2: exp in place, reduce Z ----
    {
        const float mi = mS[ii];
        float z = 0.f;
#pragma unroll 4
        for (int it = 0; it < 16; ++it) {
#pragma unroll
            for (int rr = 0; rr < 8; ++rr) {
                int j = it * 32 + jg * 8 + rr;
                float sc = PS[j * PLD + ii];
                float p  = __expf(sc - mi);
                PS[j * PLD + ii] = p;
                z += p;
            }
        }
        red[jg * 64 + ii] = z;
    }
    __syncthreads();
    if (tid < 64)
        rZS[tid] = 1.f / (red[tid] + red[64 + tid] + red[128 + tid] + red[192 + tid]);

    // ---- main loop: acc += P^T-panel x Wh tiles (packed FMA) ----
    ull acc2[4][4];
#pragma unroll
    for (int rp = 0; rp < 4; ++rp)
#pragma unroll
        for (int c = 0; c < 4; ++c) acc2[rp][c] = 0ull;

    const float4* Whg = reinterpret_cast<const float4*>(Whp) + (size_t)(b << 9) * 32;

    for (int t = 0; t < 16; ++t) {
        const int tj0 = t * 32;
        __syncthreads();
        for (int e = tid; e < 32 * 32; e += 256) {
            int jj = e >> 5, c = e & 31;
            reinterpret_cast<float4*>(WhS)[e] = Whg[(size_t)(tj0 + jj) * 32 + c];
        }
        __syncthreads();

#pragma unroll 8
        for (int j = 0; j < 32; ++j) {
            float4 w = *reinterpret_cast<const float4*>(&WhS[j * 128 + fg * 4]);
            ull w0 = pack2(w.x), w1 = pack2(w.y), w2 = pack2(w.z), w3 = pack2(w.w);
            F4U p0, p1;
            p0.f = *reinterpret_cast<const float4*>(&PS[(tj0 + j) * PLD + ig * 8]);
            p1.f = *reinterpret_cast<const float4*>(&PS[(tj0 + j) * PLD + ig * 8 + 4]);
            ull pr[4] = {p0.u[0], p0.u[1], p1.u[0], p1.u[1]};
#pragma unroll
            for (int rp = 0; rp < 4; ++rp) {
                fma2(acc2[rp][0], pr[rp], w0);
                fma2(acc2[rp][1], pr[rp], w1);
                fma2(acc2[rp][2], pr[rp], w2);
                fma2(acc2[rp][3], pr[rp], w3);
            }
        }
    }

    float val[8][4];
#pragma unroll
    for (int rp = 0; rp < 4; ++rp)
#pragma unroll
        for (int c = 0; c < 4; ++c)
            unpack2(acc2[rp][c], val[2 * rp][c], val[2 * rp + 1][c]);

#pragma unroll
    for (int rr = 0; rr < 8; ++rr) {
        int i   = i0 + ig * 8 + rr;
        float s = rZS[ig * 8 + rr];
        float4 o;
        o.x = elu1(val[rr][0] * s);
        o.y = elu1(val[rr][1] * s);
        o.z = elu1(val[rr][2] * s);
        o.w = elu1(val[rr][3] * s);
        *reinterpret_cast<float4*>(&outp[((size_t)(b << 9) + i) * ld + col0base + fg * 4]) = o;
    }
}

// ============ K4: out = lrelu( x @ Wc + bc ), blocked GEMM ============
__global__ __launch_bounds__(256) void k_final(const float* __restrict__ Wc,
                                               const float* __restrict__ bc,
                                               float* __restrict__ out)
{
    __shared__ __align__(16) float WtS[32][128];
    __shared__ __align__(16) float htT[32][68];

    int r0   = blockIdx.y * 512 + blockIdx.x * 64;
    int col0 = blockIdx.z * 128;
    int tid  = threadIdx.x;
    int fg   = tid & 31;
    int ig   = tid >> 5;

    ull acc2[4][4];
#pragma unroll
    for (int rp = 0; rp < 4; ++rp)
#pragma unroll
        for (int c = 0; c < 4; ++c) acc2[rp][c] = 0ull;

    for (int k0 = 0; k0 < 128; k0 += 32) {
        __syncthreads();
        for (int e = tid; e < 32 * 32; e += 256) {
            int k = e >> 5, c = e & 31;
            *reinterpret_cast<float4*>(&WtS[k][c * 4]) =
                *reinterpret_cast<const float4*>(&Wc[(size_t)(k0 + k) * 256 + col0 + c * 4]);
        }
        for (int e = tid; e < 64 * 32; e += 256) {
            int ii = e >> 5, k = e & 31;
            htT[k][ii] = g_x[(size_t)(r0 + ii) * 128 + k0 + k];
        }
        __syncthreads();

#pragma unroll 8
        for (int k = 0; k < 32; ++k) {
            float4 w = *reinterpret_cast<const float4*>(&WtS[k][fg * 4]);
            ull w0 = pack2(w.x), w1 = pack2(w.y), w2 = pack2(w.z), w3 = pack2(w.w);
            F4U p0, p1;
            p0.f = *reinterpret_cast<const float4*>(&htT[k][ig * 8]);
            p1.f = *reinterpret_cast<const float4*>(&htT[k][ig * 8 + 4]);
            ull pr[4] = {p0.u[0], p0.u[1], p1.u[0], p1.u[1]};
#pragma unroll
            for (int rp = 0; rp < 4; ++rp) {
                fma2(acc2[rp][0], pr[rp], w0);
                fma2(acc2[rp][1], pr[rp], w1);
                fma2(acc2[rp][2], pr[rp], w2);
                fma2(acc2[rp][3], pr[rp], w3);
            }
        }
    }

    float val[8][4];
#pragma unroll
    for (int rp = 0; rp < 4; ++rp)
#pragma unroll
        for (int c = 0; c < 4; ++c)
            unpack2(acc2[rp][c], val[2 * rp][c], val[2 * rp + 1][c]);

    float bv[4];
#pragma unroll
    for (int c = 0; c < 4; ++c) bv[c] = bc[col0 + fg * 4 + c];

#pragma unroll
    for (int rr = 0; rr < 8; ++rr) {
        int i = r0 + ig * 8 + rr;
        float4 o;
        o.x = lrelu02(val[rr][0] + bv[0]);
        o.y = lrelu02(val[rr][1] + bv[1]);
        o.z = lrelu02(val[rr][2] + bv[2]);
        o.w = lrelu02(val[rr][3] + bv[3]);
        *reinterpret_cast<float4*>(&out[(size_t)i * 256 + col0 + fg * 4]) = o;
    }
}

// ---------------- launch ----------------
extern "C" void kernel_launch(void* const* d_in, const int* in_sizes, int n_in,
                              void* d_out, int out_size)
{
    (void)in_sizes; (void)n_in; (void)out_size;
    const float* compound = (const float*)d_in[0];   // [64,512,34]
    const int*   adj      = (const int*)d_in[1];     // [64,512,512]
    const float* Wst      = (const float*)d_in[2];   // [3,34,128]
    const float* ast      = (const float*)d_in[3];   // [3,256,1]
    const float* Wout     = (const float*)d_in[4];   // [384,128]
    const float* aout     = (const float*)d_in[5];   // [256,1]
    const float* Wc       = (const float*)d_in[6];   // [128,256]
    const float* bc       = (const float*)d_in[7];   // [256]
    float* out = (float*)d_out;                      // [64,512,256]

    float* g_Wh3_p;   cudaGetSymbolAddress((void**)&g_Wh3_p,  g_Wh3);
    float* g_heads_p; cudaGetSymbolAddress((void**)&g_heads_p, g_heads);
    float* g_x_p;     cudaGetSymbolAddress((void**)&g_x_p,    g_x);
    float* g_src_p;   cudaGetSymbolAddress((void**)&g_src_p,  g_src3);
    float* g_dst_p;   cudaGetSymbolAddress((void**)&g_dst_p,  g_dst3);

    static bool attr_done = false;
    if (!attr_done) {
        cudaFuncSetAttribute(k_agg, cudaFuncAttributeMaxDynamicSharedMemorySize,
                             SMEM_AGG_BYTES);
        attr_done = true;
    }

    dim3 tile_grid(N / 64, B);

    // all 3 input-layer projections in one launch (grid.z = layer)
    k_proj<34, 34><<<dim3(N / 64, B, 3), 256>>>(
        compound, 34, Wst, ast, g_Wh3_p, g_src_p, g_dst_p);

    for (int l = 0; l < 3; ++l) {
        k_agg<<<tile_grid, 256, SMEM_AGG_BYTES>>>(
            adj, g_Wh3_p + (size_t)l * R * 128,
            g_src_p + (size_t)l * R, g_dst_p + (size_t)l * R,
            g_heads_p, 384, l * 128);
    }

    // out-layer projection on concatenated heads
    k_proj<384, 32><<<dim3(N / 64, B, 1), 256>>>(
        g_heads_p, 384, Wout, aout,
        g_Wh3_p + (size_t)3 * R * 128, g_src_p + (size_t)3 * R, g_dst_p + (size_t)3 * R);

    k_agg<<<tile_grid, 256, SMEM_AGG_BYTES>>>(
        adj, g_Wh3_p + (size_t)3 * R * 128,
        g_src_p + (size_t)3 * R, g_dst_p + (size_t)3 * R,
        g_x_p, 128, 0);

    k_final<<<dim3(N / 64, B, 2), 256>>>(Wc, bc, out);
}

// round 4
// speedup vs baseline: 2.0748x; 2.0748x over previous
#include <cuda_runtime.h>

typedef unsigned long long ull;

// ---------------- problem constants ----------------
constexpr int B = 64;
constexpr int N = 512;
constexpr int R = B * N;      // 32768 rows

// ---------------- device scratch ----------------
__device__ float g_Wh3[(size_t)4 * R * 128];     // Wh per layer (0..2) + out-layer (3)
__device__ float g_heads[(size_t)R * 384];
__device__ float g_x[(size_t)R * 128];
__device__ float g_src3[4 * R];
__device__ float g_dst3[4 * R];

__device__ __forceinline__ float lrelu02(float x) { return x > 0.f ? x : 0.2f * x; }
__device__ __forceinline__ float elu1(float x)    { return x > 0.f ? x : expm1f(x); }

__device__ __forceinline__ void fma2(ull& d, ull a, ull b) {
    asm("fma.rn.f32x2 %0, %1, %2, %3;" : "=l"(d) : "l"(a), "l"(b), "l"(d));
}
__device__ __forceinline__ ull pack2(float x) {
    ull r; asm("mov.b64 %0, {%1, %1};" : "=l"(r) : "f"(x)); return r;
}
__device__ __forceinline__ void unpack2(ull v, float& lo, float& hi) {
    asm("mov.b64 {%0, %1}, %2;" : "=f"(lo), "=f"(hi) : "l"(v));
}
union F4U { float4 f; ull u[2]; };

// ============ K1: blocked GEMM  Wh = X @ W,  fused src/dst = Wh @ a1/a2 ============
template<int FIN, int TK>
__global__ __launch_bounds__(256) void k_proj(
    const float* __restrict__ X, int ldx,
    const float* __restrict__ Wbase, const float* __restrict__ abase,
    float* __restrict__ Whout, float* __restrict__ srcout, float* __restrict__ dstout)
{
    __shared__ __align__(16) float WtS[TK][128];
    __shared__ __align__(16) float htT[TK][68];
    __shared__ float aS[256];

    const int l   = blockIdx.z;
    const float* W = Wbase + (size_t)l * FIN * 128;
    const float* a = abase + l * 256;
    float* Wh   = Whout + (size_t)l * R * 128;
    float* srcp = srcout + (size_t)l * R;
    float* dstp = dstout + (size_t)l * R;

    const int r0  = blockIdx.y * 512 + blockIdx.x * 64;
    const int tid = threadIdx.x;
    const int fg  = tid & 31;
    const int ig  = tid >> 5;

    aS[tid] = a[tid];

    ull acc2[4][4];
#pragma unroll
    for (int rp = 0; rp < 4; ++rp)
#pragma unroll
        for (int c = 0; c < 4; ++c) acc2[rp][c] = 0ull;

    for (int k0 = 0; k0 < FIN; k0 += TK) {
        __syncthreads();
        for (int e = tid; e < TK * 32; e += 256) {
            int k = e >> 5, c = e & 31;
            *reinterpret_cast<float4*>(&WtS[k][c * 4]) =
                *reinterpret_cast<const float4*>(&W[(size_t)(k0 + k) * 128 + c * 4]);
        }
        for (int e = tid; e < 64 * TK; e += 256) {
            int ii = e / TK, k = e - ii * TK;
            htT[k][ii] = X[(size_t)(r0 + ii) * ldx + k0 + k];
        }
        __syncthreads();

#pragma unroll 8
        for (int k = 0; k < TK; ++k) {
            float4 w = *reinterpret_cast<const float4*>(&WtS[k][fg * 4]);
            ull w0 = pack2(w.x), w1 = pack2(w.y), w2 = pack2(w.z), w3 = pack2(w.w);
            F4U p0, p1;
            p0.f = *reinterpret_cast<const float4*>(&htT[k][ig * 8]);
            p1.f = *reinterpret_cast<const float4*>(&htT[k][ig * 8 + 4]);
            ull pr[4] = {p0.u[0], p0.u[1], p1.u[0], p1.u[1]};
#pragma unroll
            for (int rp = 0; rp < 4; ++rp) {
                fma2(acc2[rp][0], pr[rp], w0);
                fma2(acc2[rp][1], pr[rp], w1);
                fma2(acc2[rp][2], pr[rp], w2);
                fma2(acc2[rp][3], pr[rp], w3);
            }
        }
    }

    float val[8][4];
#pragma unroll
    for (int rp = 0; rp < 4; ++rp)
#pragma unroll
        for (int c = 0; c < 4; ++c)
            unpack2(acc2[rp][c], val[2 * rp][c], val[2 * rp + 1][c]);

    float a1v[4], a2v[4];
#pragma unroll
    for (int c = 0; c < 4; ++c) { a1v[c] = aS[fg * 4 + c]; a2v[c] = aS[128 + fg * 4 + c]; }

#pragma unroll
    for (int rr = 0; rr < 8; ++rr) {
        int i = r0 + ig * 8 + rr;
        float4 o = make_float4(val[rr][0], val[rr][1], val[rr][2], val[rr][3]);
        *reinterpret_cast<float4*>(&Wh[(size_t)i * 128 + fg * 4]) = o;
        float v1 = val[rr][0] * a1v[0] + val[rr][1] * a1v[1] + val[rr][2] * a1v[2] + val[rr][3] * a1v[3];
        float v2 = val[rr][0] * a2v[0] + val[rr][1] * a2v[1] + val[rr][2] * a2v[2] + val[rr][3] * a2v[3];
#pragma unroll
        for (int o2 = 16; o2; o2 >>= 1) {
            v1 += __shfl_xor_sync(0xffffffffu, v1, o2);
            v2 += __shfl_xor_sync(0xffffffffu, v2, o2);
        }
        if (fg == 0) { srcp[i] = v1; dstp[i] = v2; }
    }
}

// ============ K3: single-pass fused softmax + aggregate ============
// CTA = 64 rows x 128 cols; chunked over j (32 at a time). Safe softmax shift:
// m_i = lrelu(src_i + max_j dst_j)  (monotone lrelu => >= all unmasked scores;
// softmax is shift-invariant, so result is exact).
constexpr int TI = 64, TJ = 32, PLD = 68;

__global__ __launch_bounds__(256) void k_agg(
    const int* __restrict__ adj, const float* __restrict__ Wh0,
    const float* __restrict__ src0, const float* __restrict__ dst0,
    float* __restrict__ outp, int ld)
{
    __shared__ float dstS[512];
    __shared__ float srcS[TI], mS[TI], rZS[TI];
    __shared__ float red[8];
    __shared__ float mdstS;
    __shared__ int   adjS[TI][TJ + 1];
    __shared__ __align__(16) float WhS[TJ][128];
    __shared__ __align__(16) float PS[TJ][PLD];

    const int l   = blockIdx.z;
    const float* Whp  = Wh0 + (size_t)l * R * 128;
    const float* srcp = src0 + (size_t)l * R;
    const float* dstp = dst0 + (size_t)l * R;
    const int col0 = l * 128;

    const int b   = blockIdx.y;
    const int i0  = blockIdx.x * TI;
    const int tid = threadIdx.x;
    const int fg  = tid & 31;
    const int ig  = tid >> 5;
    const int ii  = tid & 63;   // P-phase row
    const int jg  = tid >> 6;   // P-phase j-slice (0..3)

    for (int k = tid; k < 512; k += 256) dstS[k] = dstp[(b << 9) + k];
    if (tid < TI) srcS[tid] = srcp[(b << 9) + i0 + tid];
    __syncthreads();

    // ---- block max of dst ----
    {
        float v = fmaxf(dstS[tid], dstS[tid + 256]);
#pragma unroll
        for (int o = 16; o; o >>= 1) v = fmaxf(v, __shfl_xor_sync(0xffffffffu, v, o));
        if ((tid & 31) == 0) red[tid >> 5] = v;
        __syncthreads();
        if (tid == 0) {
            float m = red[0];
#pragma unroll
            for (int k = 1; k < 8; ++k) m = fmaxf(m, red[k]);
            mdstS = m;
        }
        __syncthreads();
        if (tid < TI) mS[tid] = lrelu02(srcS[tid] + mdstS);
    }

    ull acc2[4][4];
#pragma unroll
    for (int rp = 0; rp < 4; ++rp)
#pragma unroll
        for (int c = 0; c < 4; ++c) acc2[rp][c] = 0ull;

    const size_t adj_base = ((size_t)(b << 9) + i0) * 512;
    const float4* Whg = reinterpret_cast<const float4*>(Whp) + (size_t)(b << 9) * 32;

    const float si = srcS[ii];
    float zloc = 0.f;   // partial Z for row ii over this thread's j-slice
    float mi_p = 0.f;   // filled after first sync in loop (mS valid already)

    for (int t = 0; t < 16; ++t) {
        const int tj0 = t * TJ;
        __syncthreads();   // prev FMA done; safe to overwrite adjS/WhS/PS

        for (int e = tid; e < TI * TJ; e += 256) {
            int ri = e >> 5, jj = e & 31;
            adjS[ri][jj] = adj[adj_base + (size_t)ri * 512 + tj0 + jj];
        }
        for (int e = tid; e < TJ * 32; e += 256) {
            int jj = e >> 5, c = e & 31;
            reinterpret_cast<float4*>(WhS)[e] = Whg[(size_t)(tj0 + jj) * 32 + c];
        }
        __syncthreads();

        // P phase: PS[j][ii] = exp(score - m_ii), accumulate partial Z
        mi_p = mS[ii];
#pragma unroll
        for (int rr = 0; rr < 8; ++rr) {
            int j = jg * 8 + rr;
            float e2 = lrelu02(si + dstS[tj0 + j]);
            float sc = (adjS[ii][j] > 0) ? e2 : -9e15f;
            float p  = __expf(sc - mi_p);
            PS[j][ii] = p;
            zloc += p;
        }
        __syncthreads();

        // FMA phase
#pragma unroll 8
        for (int j = 0; j < TJ; ++j) {
            float4 w = *reinterpret_cast<const float4*>(&WhS[j][fg * 4]);
            ull w0 = pack2(w.x), w1 = pack2(w.y), w2 = pack2(w.z), w3 = pack2(w.w);
            F4U p0, p1;
            p0.f = *reinterpret_cast<const float4*>(&PS[j][ig * 8]);
            p1.f = *reinterpret_cast<const float4*>(&PS[j][ig * 8 + 4]);
            ull pr[4] = {p0.u[0], p0.u[1], p1.u[0], p1.u[1]};
#pragma unroll
            for (int rp = 0; rp < 4; ++rp) {
                fma2(acc2[rp][0], pr[rp], w0);
                fma2(acc2[rp][1], pr[rp], w1);
                fma2(acc2[rp][2], pr[rp], w2);
                fma2(acc2[rp][3], pr[rp], w3);
            }
        }
    }

    // ---- Z reduction: 4 slices per row ----
    __syncthreads();
    {
        // reuse PS as scratch [4][64]
        PS[0][jg * 64 + ii - (jg * 64 & 0)] = 0.f; // no-op placeholder avoided below
    }
    __shared__ float zred[4 * 64];
    zred[jg * 64 + ii] = zloc;
    __syncthreads();
    if (tid < TI)
        rZS[tid] = 1.f / (zred[tid] + zred[64 + tid] + zred[128 + tid] + zred[192 + tid]);
    __syncthreads();

    float val[8][4];
#pragma unroll
    for (int rp = 0; rp < 4; ++rp)
#pragma unroll
        for (int c = 0; c < 4; ++c)
            unpack2(acc2[rp][c], val[2 * rp][c], val[2 * rp + 1][c]);

#pragma unroll
    for (int rr = 0; rr < 8; ++rr) {
        int i   = i0 + ig * 8 + rr;
        float s = rZS[ig * 8 + rr];
        float4 o;
        o.x = elu1(val[rr][0] * s);
        o.y = elu1(val[rr][1] * s);
        o.z = elu1(val[rr][2] * s);
        o.w = elu1(val[rr][3] * s);
        *reinterpret_cast<float4*>(&outp[((size_t)(b << 9) + i) * ld + col0 + fg * 4]) = o;
    }
}

// ============ K4: out = lrelu( x @ Wc + bc ), blocked GEMM ============
__global__ __launch_bounds__(256) void k_final(const float* __restrict__ Wc,
                                               const float* __restrict__ bc,
                                               float* __restrict__ out)
{
    __shared__ __align__(16) float WtS[32][128];
    __shared__ __align__(16) float htT[32][68];

    int r0   = blockIdx.y * 512 + blockIdx.x * 64;
    int col0 = blockIdx.z * 128;
    int tid  = threadIdx.x;
    int fg   = tid & 31;
    int ig   = tid >> 5;

    ull acc2[4][4];
#pragma unroll
    for (int rp = 0; rp < 4; ++rp)
#pragma unroll
        for (int c = 0; c < 4; ++c) acc2[rp][c] = 0ull;

    for (int k0 = 0; k0 < 128; k0 += 32) {
        __syncthreads();
        for (int e = tid; e < 32 * 32; e += 256) {
            int k = e >> 5, c = e & 31;
            *reinterpret_cast<float4*>(&WtS[k][c * 4]) =
                *reinterpret_cast<const float4*>(&Wc[(size_t)(k0 + k) * 256 + col0 + c * 4]);
        }
        for (int e = tid; e < 64 * 32; e += 256) {
            int ii = e >> 5, k = e & 31;
            htT[k][ii] = g_x[(size_t)(r0 + ii) * 128 + k0 + k];
        }
        __syncthreads();

#pragma unroll 8
        for (int k = 0; k < 32; ++k) {
            float4 w = *reinterpret_cast<const float4*>(&WtS[k][fg * 4]);
            ull w0 = pack2(w.x), w1 = pack2(w.y), w2 = pack2(w.z), w3 = pack2(w.w);
            F4U p0, p1;
            p0.f = *reinterpret_cast<const float4*>(&htT[k][ig * 8]);
            p1.f = *reinterpret_cast<const float4*>(&htT[k][ig * 8 + 4]);
            ull pr[4] = {p0.u[0], p0.u[1], p1.u[0], p1.u[1]};
#pragma unroll
            for (int rp = 0; rp < 4; ++rp) {
                fma2(acc2[rp][0], pr[rp], w0);
                fma2(acc2[rp][1], pr[rp], w1);
                fma2(acc2[rp][2], pr[rp], w2);
                fma2(acc2[rp][3], pr[rp], w3);
            }
        }
    }

    float val[8][4];
#pragma unroll
    for (int rp = 0; rp < 4; ++rp)
#pragma unroll
        for (int c = 0; c < 4; ++c)
            unpack2(acc2[rp][c], val[2 * rp][c], val[2 * rp + 1][c]);

    float bv[4];
#pragma unroll
    for (int c = 0; c < 4; ++c) bv[c] = bc[col0 + fg * 4 + c];

#pragma unroll
    for (int rr = 0; rr < 8; ++rr) {
        int i = r0 + ig * 8 + rr;
        float4 o;
        o.x = lrelu02(val[rr][0] + bv[0]);
        o.y = lrelu02(val[rr][1] + bv[1]);
        o.z = lrelu02(val[rr][2] + bv[2]);
        o.w = lrelu02(val[rr][3] + bv[3]);
        *reinterpret_cast<float4*>(&out[(size_t)i * 256 + col0 + fg * 4]) = o;
    }
}

// ---------------- launch ----------------
extern "C" void kernel_launch(void* const* d_in, const int* in_sizes, int n_in,
                              void* d_out, int out_size)
{
    (void)in_sizes; (void)n_in; (void)out_size;
    const float* compound = (const float*)d_in[0];   // [64,512,34]
    const int*   adj      = (const int*)d_in[1];     // [64,512,512]
    const float* Wst      = (const float*)d_in[2];   // [3,34,128]
    const float* ast      = (const float*)d_in[3];   // [3,256,1]
    const float* Wout     = (const float*)d_in[4];   // [384,128]
    const float* aout     = (const float*)d_in[5];   // [256,1]
    const float* Wc       = (const float*)d_in[6];   // [128,256]
    const float* bc       = (const float*)d_in[7];   // [256]
    float* out = (float*)d_out;                      // [64,512,256]

    float* g_Wh3_p;   cudaGetSymbolAddress((void**)&g_Wh3_p,  g_Wh3);
    float* g_heads_p; cudaGetSymbolAddress((void**)&g_heads_p, g_heads);
    float* g_x_p;     cudaGetSymbolAddress((void**)&g_x_p,    g_x);
    float* g_src_p;   cudaGetSymbolAddress((void**)&g_src_p,  g_src3);
    float* g_dst_p;   cudaGetSymbolAddress((void**)&g_dst_p,  g_dst3);

    // all 3 input-layer projections in one launch (grid.z = layer)
    k_proj<34, 34><<<dim3(N / 64, B, 3), 256>>>(
        compound, 34, Wst, ast, g_Wh3_p, g_src_p, g_dst_p);

    // all 3 head aggregations in one launch (independent layers)
    k_agg<<<dim3(N / 64, B, 3), 256>>>(adj, g_Wh3_p, g_src_p, g_dst_p,
                                       g_heads_p, 384);

    // out-layer projection on concatenated heads
    k_proj<384, 32><<<dim3(N / 64, B, 1), 256>>>(
        g_heads_p, 384, Wout, aout,
        g_Wh3_p + (size_t)3 * R * 128, g_src_p + (size_t)3 * R, g_dst_p + (size_t)3 * R);

    // out-layer aggregation (grid.z = 1 -> col0 = 0)
    k_agg<<<dim3(N / 64, B, 1), 256>>>(adj, g_Wh3_p + (size_t)3 * R * 128,
                                       g_src_p + (size_t)3 * R, g_dst_p + (size_t)3 * R,
                                       g_x_p, 128);

    k_final<<<dim3(N / 64, B, 2), 256>>>(Wc, bc, out);
}

// round 5
// speedup vs baseline: 2.1907x; 1.0559x over previous
#include <cuda_runtime.h>

typedef unsigned long long ull;

// ---------------- problem constants ----------------
constexpr int B = 64;
constexpr int N = 512;
constexpr int R = B * N;      // 32768 rows

// ---------------- device scratch ----------------
__device__ float g_Wh3[(size_t)4 * R * 128];     // Wh per layer (0..2) + out-layer (3)
__device__ float g_heads[(size_t)R * 384];
__device__ float g_x[(size_t)R * 128];
__device__ float g_src3[4 * R];
__device__ float g_dst3[4 * R];

__device__ __forceinline__ float lrelu02(float x) { return x > 0.f ? x : 0.2f * x; }
__device__ __forceinline__ float elu1(float x)    { return x > 0.f ? x : expm1f(x); }

__device__ __forceinline__ void fma2(ull& d, ull a, ull b) {
    asm("fma.rn.f32x2 %0, %1, %2, %3;" : "=l"(d) : "l"(a), "l"(b), "l"(d));
}
__device__ __forceinline__ ull pack2(float x) {
    ull r; asm("mov.b64 %0, {%1, %1};" : "=l"(r) : "f"(x)); return r;
}
__device__ __forceinline__ void unpack2(ull v, float& lo, float& hi) {
    asm("mov.b64 {%0, %1}, %2;" : "=f"(lo), "=f"(hi) : "l"(v));
}
union F4U { float4 f; ull u[2]; };

// ============ K1: blocked GEMM  Wh = X @ W,  fused src/dst = Wh @ a1/a2 ============
template<int FIN, int TK>
__global__ __launch_bounds__(256) void k_proj(
    const float* __restrict__ X, int ldx,
    const float* __restrict__ Wbase, const float* __restrict__ abase,
    float* __restrict__ Whout, float* __restrict__ srcout, float* __restrict__ dstout)
{
    __shared__ __align__(16) float WtS[TK][128];
    __shared__ __align__(16) float htT[TK][68];
    __shared__ float aS[256];

    const int l   = blockIdx.z;
    const float* W = Wbase + (size_t)l * FIN * 128;
    const float* a = abase + l * 256;
    float* Wh   = Whout + (size_t)l * R * 128;
    float* srcp = srcout + (size_t)l * R;
    float* dstp = dstout + (size_t)l * R;

    const int r0  = blockIdx.y * 512 + blockIdx.x * 64;
    const int tid = threadIdx.x;
    const int fg  = tid & 31;
    const int ig  = tid >> 5;

    aS[tid] = a[tid];

    ull acc2[4][4];
#pragma unroll
    for (int rp = 0; rp < 4; ++rp)
#pragma unroll
        for (int c = 0; c < 4; ++c) acc2[rp][c] = 0ull;

    for (int k0 = 0; k0 < FIN; k0 += TK) {
        __syncthreads();
        for (int e = tid; e < TK * 32; e += 256) {
            int k = e >> 5, c = e & 31;
            *reinterpret_cast<float4*>(&WtS[k][c * 4]) =
                *reinterpret_cast<const float4*>(&W[(size_t)(k0 + k) * 128 + c * 4]);
        }
        for (int e = tid; e < 64 * TK; e += 256) {
            int ii = e / TK, k = e - ii * TK;
            htT[k][ii] = X[(size_t)(r0 + ii) * ldx + k0 + k];
        }
        __syncthreads();

#pragma unroll 8
        for (int k = 0; k < TK; ++k) {
            float4 w = *reinterpret_cast<const float4*>(&WtS[k][fg * 4]);
            ull w0 = pack2(w.x), w1 = pack2(w.y), w2 = pack2(w.z), w3 = pack2(w.w);
            F4U p0, p1;
            p0.f = *reinterpret_cast<const float4*>(&htT[k][ig * 8]);
            p1.f = *reinterpret_cast<const float4*>(&htT[k][ig * 8 + 4]);
            ull pr[4] = {p0.u[0], p0.u[1], p1.u[0], p1.u[1]};
#pragma unroll
            for (int rp = 0; rp < 4; ++rp) {
                fma2(acc2[rp][0], pr[rp], w0);
                fma2(acc2[rp][1], pr[rp], w1);
                fma2(acc2[rp][2], pr[rp], w2);
                fma2(acc2[rp][3], pr[rp], w3);
            }
        }
    }

    float val[8][4];
#pragma unroll
    for (int rp = 0; rp < 4; ++rp)
#pragma unroll
        for (int c = 0; c < 4; ++c)
            unpack2(acc2[rp][c], val[2 * rp][c], val[2 * rp + 1][c]);

    float a1v[4], a2v[4];
#pragma unroll
    for (int c = 0; c < 4; ++c) { a1v[c] = aS[fg * 4 + c]; a2v[c] = aS[128 + fg * 4 + c]; }

#pragma unroll
    for (int rr = 0; rr < 8; ++rr) {
        int i = r0 + ig * 8 + rr;
        float4 o = make_float4(val[rr][0], val[rr][1], val[rr][2], val[rr][3]);
        *reinterpret_cast<float4*>(&Wh[(size_t)i * 128 + fg * 4]) = o;
        float v1 = val[rr][0] * a1v[0] + val[rr][1] * a1v[1] + val[rr][2] * a1v[2] + val[rr][3] * a1v[3];
        float v2 = val[rr][0] * a2v[0] + val[rr][1] * a2v[1] + val[rr][2] * a2v[2] + val[rr][3] * a2v[3];
#pragma unroll
        for (int o2 = 16; o2; o2 >>= 1) {
            v1 += __shfl_xor_sync(0xffffffffu, v1, o2);
            v2 += __shfl_xor_sync(0xffffffffu, v2, o2);
        }
        if (fg == 0) { srcp[i] = v1; dstp[i] = v2; }
    }
}

// ============ K3: single-pass fused softmax + aggregate, factored exp ============
// P(i,j) = adj ? (s>0 ? E1_i*F1_j : E2_i*F2_j) : 0,  s = src_i + dst_j
//   m_i  = lrelu(src_i + mdst),  mdst = max_j dst_j
//   E1_i = exp(src_i + mdst - m_i)      <= 1
//   E2_i = exp(0.2(src_i + mdst) - m_i) <= 1
//   F1_j = exp(dst_j - mdst)            <= 1
//   F2_j = exp(0.2(dst_j - mdst))       <= 1
// All factors in (0,1] -> overflow-proof; masked entries exactly 0.
constexpr int TI = 64, TJ = 32, PLD = 68;

__global__ __launch_bounds__(256, 3) void k_agg(
    const int* __restrict__ adj, const float* __restrict__ Wh0,
    const float* __restrict__ src0, const float* __restrict__ dst0,
    float* __restrict__ outp, int ld)
{
    __shared__ float dstS[512];
    __shared__ __align__(8) float2 FS[512];     // (F1_j, F2_j)
    __shared__ float srcS[TI], e1S[TI], e2S[TI], rZS[TI];
    __shared__ float red[8];
    __shared__ float mdstS;
    __shared__ __align__(16) float WhS[TJ][128];
    __shared__ __align__(16) float PS[TJ][PLD];
    __shared__ float zred[256];

    const int l   = blockIdx.z;
    const float* Whp  = Wh0 + (size_t)l * R * 128;
    const float* srcp = src0 + (size_t)l * R;
    const float* dstp = dst0 + (size_t)l * R;
    const int col0 = l * 128;

    const int b   = blockIdx.y;
    const int i0  = blockIdx.x * TI;
    const int tid = threadIdx.x;
    const int fg  = tid & 31;
    const int ig  = tid >> 5;
    const int ii  = tid & 63;   // P-phase row
    const int jg  = tid >> 6;   // P-phase j-slice (0..3)

    for (int k = tid; k < 512; k += 256) dstS[k] = dstp[(b << 9) + k];
    if (tid < TI) srcS[tid] = srcp[(b << 9) + i0 + tid];
    __syncthreads();

    // ---- block max of dst ----
    {
        float v = fmaxf(dstS[tid], dstS[tid + 256]);
#pragma unroll
        for (int o = 16; o; o >>= 1) v = fmaxf(v, __shfl_xor_sync(0xffffffffu, v, o));
        if ((tid & 31) == 0) red[tid >> 5] = v;
        __syncthreads();
        if (tid == 0) {
            float m = red[0];
#pragma unroll
            for (int k = 1; k < 8; ++k) m = fmaxf(m, red[k]);
            mdstS = m;
        }
        __syncthreads();
    }
    const float mdst = mdstS;

    // ---- per-column and per-row exp factors (few MUFU ops total) ----
    for (int k = tid; k < 512; k += 256) {
        float d = dstS[k] - mdst;
        FS[k] = make_float2(__expf(d), __expf(0.2f * d));
    }
    if (tid < TI) {
        float t = srcS[tid] + mdst;
        float m = lrelu02(t);
        e1S[tid] = __expf(t - m);
        e2S[tid] = __expf(0.2f * t - m);
    }
    __syncthreads();

    ull acc2[4][4];
#pragma unroll
    for (int rp = 0; rp < 4; ++rp)
#pragma unroll
        for (int c = 0; c < 4; ++c) acc2[rp][c] = 0ull;

    const float4* Whg = reinterpret_cast<const float4*>(Whp) + (size_t)(b << 9) * 32;
    const int* adjrow = adj + ((size_t)(b << 9) + i0 + ii) * 512 + jg * 8;

    const float si = srcS[ii];
    const float e1 = e1S[ii];
    const float e2 = e2S[ii];
    float zloc = 0.f;

    for (int t = 0; t < 16; ++t) {
        const int tj0 = t * TJ;
        __syncthreads();   // prev FMA done; safe to overwrite WhS/PS

        // stage Wh tile [TJ x 128]
        for (int e = tid; e < TJ * 32; e += 256) {
            int jj = e >> 5, c = e & 31;
            reinterpret_cast<float4*>(WhS)[e] = Whg[(size_t)(tj0 + jj) * 32 + c];
        }

        // P phase: direct-global adj (2x int4 per thread, full sector use)
        {
            int4 a0 = *reinterpret_cast<const int4*>(adjrow + tj0);
            int4 a1 = *reinterpret_cast<const int4*>(adjrow + tj0 + 4);
            int av[8] = {a0.x, a0.y, a0.z, a0.w, a1.x, a1.y, a1.z, a1.w};
#pragma unroll
            for (int rr = 0; rr < 8; ++rr) {
                int j = jg * 8 + rr;
                float2 f = FS[tj0 + j];
                float s  = si + dstS[tj0 + j];
                bool pos = s > 0.f;
                float p  = (pos ? e1 : e2) * (pos ? f.x : f.y);
                p = (av[rr] > 0) ? p : 0.f;
                PS[j][ii] = p;
                zloc += p;
            }
        }
        __syncthreads();

        // FMA phase
#pragma unroll 8
        for (int j = 0; j < TJ; ++j) {
            float4 w = *reinterpret_cast<const float4*>(&WhS[j][fg * 4]);
            ull w0 = pack2(w.x), w1 = pack2(w.y), w2 = pack2(w.z), w3 = pack2(w.w);
            F4U p0, p1;
            p0.f = *reinterpret_cast<const float4*>(&PS[j][ig * 8]);
            p1.f = *reinterpret_cast<const float4*>(&PS[j][ig * 8 + 4]);
            ull pr[4] = {p0.u[0], p0.u[1], p1.u[0], p1.u[1]};
#pragma unroll
            for (int rp = 0; rp < 4; ++rp) {
                fma2(acc2[rp][0], pr[rp], w0);
                fma2(acc2[rp][1], pr[rp], w1);
                fma2(acc2[rp][2], pr[rp], w2);
                fma2(acc2[rp][3], pr[rp], w3);
            }
        }
    }

    // ---- Z reduction: 4 j-slices per row ----
    __syncthreads();
    zred[tid] = zloc;
    __syncthreads();
    if (tid < TI)
        rZS[tid] = 1.f / (zred[tid] + zred[64 + tid] + zred[128 + tid] + zred[192 + tid]);
    __syncthreads();

    float val[8][4];
#pragma unroll
    for (int rp = 0; rp < 4; ++rp)
#pragma unroll
        for (int c = 0; c < 4; ++c)
            unpack2(acc2[rp][c], val[2 * rp][c], val[2 * rp + 1][c]);

#pragma unroll
    for (int rr = 0; rr < 8; ++rr) {
        int i   = i0 + ig * 8 + rr;
        float s = rZS[ig * 8 + rr];
        float4 o;
        o.x = elu1(val[rr][0] * s);
        o.y = elu1(val[rr][1] * s);
        o.z = elu1(val[rr][2] * s);
        o.w = elu1(val[rr][3] * s);
        *reinterpret_cast<float4*>(&outp[((size_t)(b << 9) + i) * ld + col0 + fg * 4]) = o;
    }
}

// ============ K4: out = lrelu( x @ Wc + bc ), blocked GEMM ============
__global__ __launch_bounds__(256) void k_final(const float* __restrict__ Wc,
                                               const float* __restrict__ bc,
                                               float* __restrict__ out)
{
    __shared__ __align__(16) float WtS[32][128];
    __shared__ __align__(16) float htT[32][68];

    int r0   = blockIdx.y * 512 + blockIdx.x * 64;
    int col0 = blockIdx.z * 128;
    int tid  = threadIdx.x;
    int fg   = tid & 31;
    int ig   = tid >> 5;

    ull acc2[4][4];
#pragma unroll
    for (int rp = 0; rp < 4; ++rp)
#pragma unroll
        for (int c = 0; c < 4; ++c) acc2[rp][c] = 0ull;

    for (int k0 = 0; k0 < 128; k0 += 32) {
        __syncthreads();
        for (int e = tid; e < 32 * 32; e += 256) {
            int k = e >> 5, c = e & 31;
            *reinterpret_cast<float4*>(&WtS[k][c * 4]) =
                *reinterpret_cast<const float4*>(&Wc[(size_t)(k0 + k) * 256 + col0 + c * 4]);
        }
        for (int e = tid; e < 64 * 32; e += 256) {
            int ii = e >> 5, k = e & 31;
            htT[k][ii] = g_x[(size_t)(r0 + ii) * 128 + k0 + k];
        }
        __syncthreads();

#pragma unroll 8
        for (int k = 0; k < 32; ++k) {
            float4 w = *reinterpret_cast<const float4*>(&WtS[k][fg * 4]);
            ull w0 = pack2(w.x), w1 = pack2(w.y), w2 = pack2(w.z), w3 = pack2(w.w);
            F4U p0, p1;
            p0.f = *reinterpret_cast<const float4*>(&htT[k][ig * 8]);
            p1.f = *reinterpret_cast<const float4*>(&htT[k][ig * 8 + 4]);
            ull pr[4] = {p0.u[0], p0.u[1], p1.u[0], p1.u[1]};
#pragma unroll
            for (int rp = 0; rp < 4; ++rp) {
                fma2(acc2[rp][0], pr[rp], w0);
                fma2(acc2[rp][1], pr[rp], w1);
                fma2(acc2[rp][2], pr[rp], w2);
                fma2(acc2[rp][3], pr[rp], w3);
            }
        }
    }

    float val[8][4];
#pragma unroll
    for (int rp = 0; rp < 4; ++rp)
#pragma unroll
        for (int c = 0; c < 4; ++c)
            unpack2(acc2[rp][c], val[2 * rp][c], val[2 * rp + 1][c]);

    float bv[4];
#pragma unroll
    for (int c = 0; c < 4; ++c) bv[c] = bc[col0 + fg * 4 + c];

#pragma unroll
    for (int rr = 0; rr < 8; ++rr) {
        int i = r0 + ig * 8 + rr;
        float4 o;
        o.x = lrelu02(val[rr][0] + bv[0]);
        o.y = lrelu02(val[rr][1] + bv[1]);
        o.z = lrelu02(val[rr][2] + bv[2]);
        o.w = lrelu02(val[rr][3] + bv[3]);
        *reinterpret_cast<float4*>(&out[(size_t)i * 256 + col0 + fg * 4]) = o;
    }
}

// ---------------- launch ----------------
extern "C" void kernel_launch(void* const* d_in, const int* in_sizes, int n_in,
                              void* d_out, int out_size)
{
    (void)in_sizes; (void)n_in; (void)out_size;
    const float* compound = (const float*)d_in[0];   // [64,512,34]
    const int*   adj      = (const int*)d_in[1];     // [64,512,512]
    const float* Wst      = (const float*)d_in[2];   // [3,34,128]
    const float* ast      = (const float*)d_in[3];   // [3,256,1]
    const float* Wout     = (const float*)d_in[4];   // [384,128]
    const float* aout     = (const float*)d_in[5];   // [256,1]
    const float* Wc       = (const float*)d_in[6];   // [128,256]
    const float* bc       = (const float*)d_in[7];   // [256]
    float* out = (float*)d_out;                      // [64,512,256]

    float* g_Wh3_p;   cudaGetSymbolAddress((void**)&g_Wh3_p,  g_Wh3);
    float* g_heads_p; cudaGetSymbolAddress((void**)&g_heads_p, g_heads);
    float* g_x_p;     cudaGetSymbolAddress((void**)&g_x_p,    g_x);
    float* g_src_p;   cudaGetSymbolAddress((void**)&g_src_p,  g_src3);
    float* g_dst_p;   cudaGetSymbolAddress((void**)&g_dst_p,  g_dst3);

    // all 3 input-layer projections in one launch (grid.z = layer)
    k_proj<34, 34><<<dim3(N / 64, B, 3), 256>>>(
        compound, 34, Wst, ast, g_Wh3_p, g_src_p, g_dst_p);

    // all 3 head aggregations in one launch (independent layers)
    k_agg<<<dim3(N / 64, B, 3), 256>>>(adj, g_Wh3_p, g_src_p, g_dst_p,
                                       g_heads_p, 384);

    // out-layer projection on concatenated heads
    k_proj<384, 32><<<dim3(N / 64, B, 1), 256>>>(
        g_heads_p, 384, Wout, aout,
        g_Wh3_p + (size_t)3 * R * 128, g_src_p + (size_t)3 * R, g_dst_p + (size_t)3 * R);

    // out-layer aggregation (grid.z = 1 -> col0 = 0)
    k_agg<<<dim3(N / 64, B, 1), 256>>>(adj, g_Wh3_p + (size_t)3 * R * 128,
                                       g_src_p + (size_t)3 * R, g_dst_p + (size_t)3 * R,
                                       g_x_p, 128);

    k_final<<<dim3(N / 64, B, 2), 256>>>(Wc, bc, out);
}

// round 6
// speedup vs baseline: 2.3584x; 1.0766x over previous
#include <cuda_runtime.h>

typedef unsigned long long ull;

// ---------------- problem constants ----------------
constexpr int B = 64;
constexpr int N = 512;
constexpr int R = B * N;      // 32768 rows

// ---------------- device scratch ----------------
__device__ float g_Wh3[(size_t)4 * R * 128];     // Wh per layer (0..2) + out-layer (3)
__device__ float g_heads[(size_t)R * 384];
__device__ float g_x[(size_t)R * 128];
__device__ float g_src3[4 * R];
__device__ float g_dst3[4 * R];

__device__ __forceinline__ float lrelu02(float x) { return x > 0.f ? x : 0.2f * x; }
__device__ __forceinline__ float elu1(float x)    { return x > 0.f ? x : expm1f(x); }

__device__ __forceinline__ void fma2(ull& d, ull a, ull b) {
    asm("fma.rn.f32x2 %0, %1, %2, %3;" : "=l"(d) : "l"(a), "l"(b), "l"(d));
}
__device__ __forceinline__ ull pack2(float x) {
    ull r; asm("mov.b64 %0, {%1, %1};" : "=l"(r) : "f"(x)); return r;
}
__device__ __forceinline__ void unpack2(ull v, float& lo, float& hi) {
    asm("mov.b64 {%0, %1}, %2;" : "=f"(lo), "=f"(hi) : "l"(v));
}
union F4U { float4 f; ull u[2]; };

// ============ K1: blocked GEMM  Wh = X @ W,  fused src/dst = Wh @ a1/a2 ============
template<int FIN, int TK>
__global__ __launch_bounds__(256) void k_proj(
    const float* __restrict__ X, int ldx,
    const float* __restrict__ Wbase, const float* __restrict__ abase,
    float* __restrict__ Whout, float* __restrict__ srcout, float* __restrict__ dstout)
{
    __shared__ __align__(16) float WtS[TK][128];
    __shared__ __align__(16) float htT[TK][68];
    __shared__ float aS[256];

    const int l   = blockIdx.z;
    const float* W = Wbase + (size_t)l * FIN * 128;
    const float* a = abase + l * 256;
    float* Wh   = Whout + (size_t)l * R * 128;
    float* srcp = srcout + (size_t)l * R;
    float* dstp = dstout + (size_t)l * R;

    const int r0  = blockIdx.y * 512 + blockIdx.x * 64;
    const int tid = threadIdx.x;
    const int fg  = tid & 31;
    const int ig  = tid >> 5;

    aS[tid] = a[tid];

    ull acc2[4][4];
#pragma unroll
    for (int rp = 0; rp < 4; ++rp)
#pragma unroll
        for (int c = 0; c < 4; ++c) acc2[rp][c] = 0ull;

    for (int k0 = 0; k0 < FIN; k0 += TK) {
        __syncthreads();
        for (int e = tid; e < TK * 32; e += 256) {
            int k = e >> 5, c = e & 31;
            *reinterpret_cast<float4*>(&WtS[k][c * 4]) =
                *reinterpret_cast<const float4*>(&W[(size_t)(k0 + k) * 128 + c * 4]);
        }
        for (int e = tid; e < 64 * TK; e += 256) {
            int ii = e / TK, k = e - ii * TK;
            htT[k][ii] = X[(size_t)(r0 + ii) * ldx + k0 + k];
        }
        __syncthreads();

#pragma unroll 8
        for (int k = 0; k < TK; ++k) {
            float4 w = *reinterpret_cast<const float4*>(&WtS[k][fg * 4]);
            ull w0 = pack2(w.x), w1 = pack2(w.y), w2 = pack2(w.z), w3 = pack2(w.w);
            F4U p0, p1;
            p0.f = *reinterpret_cast<const float4*>(&htT[k][ig * 8]);
            p1.f = *reinterpret_cast<const float4*>(&htT[k][ig * 8 + 4]);
            ull pr[4] = {p0.u[0], p0.u[1], p1.u[0], p1.u[1]};
#pragma unroll
            for (int rp = 0; rp < 4; ++rp) {
                fma2(acc2[rp][0], pr[rp], w0);
                fma2(acc2[rp][1], pr[rp], w1);
                fma2(acc2[rp][2], pr[rp], w2);
                fma2(acc2[rp][3], pr[rp], w3);
            }
        }
    }

    float val[8][4];
#pragma unroll
    for (int rp = 0; rp < 4; ++rp)
#pragma unroll
        for (int c = 0; c < 4; ++c)
            unpack2(acc2[rp][c], val[2 * rp][c], val[2 * rp + 1][c]);

    float a1v[4], a2v[4];
#pragma unroll
    for (int c = 0; c < 4; ++c) { a1v[c] = aS[fg * 4 + c]; a2v[c] = aS[128 + fg * 4 + c]; }

#pragma unroll
    for (int rr = 0; rr < 8; ++rr) {
        int i = r0 + ig * 8 + rr;
        float4 o = make_float4(val[rr][0], val[rr][1], val[rr][2], val[rr][3]);
        *reinterpret_cast<float4*>(&Wh[(size_t)i * 128 + fg * 4]) = o;
        float v1 = val[rr][0] * a1v[0] + val[rr][1] * a1v[1] + val[rr][2] * a1v[2] + val[rr][3] * a1v[3];
        float v2 = val[rr][0] * a2v[0] + val[rr][1] * a2v[1] + val[rr][2] * a2v[2] + val[rr][3] * a2v[3];
#pragma unroll
        for (int o2 = 16; o2; o2 >>= 1) {
            v1 += __shfl_xor_sync(0xffffffffu, v1, o2);
            v2 += __shfl_xor_sync(0xffffffffu, v2, o2);
        }
        if (fg == 0) { srcp[i] = v1; dstp[i] = v2; }
    }
}

// ============ K3: fused softmax+aggregate; factored exp; 2x4 warp tile;
//               double-buffered tiles with global prefetch ============
constexpr int TI = 64, TJ = 32;

__global__ __launch_bounds__(256, 3) void k_agg(
    const int* __restrict__ adj, const float* __restrict__ Wh0,
    const float* __restrict__ src0, const float* __restrict__ dst0,
    float* __restrict__ outp, int ld)
{
    __shared__ float dstS[512];
    __shared__ __align__(8) float2 FS[512];     // (F1_j, F2_j)
    __shared__ float srcS[TI], e1S[TI], e2S[TI], rZS[TI];
    __shared__ float red[8];
    __shared__ float mdstS;
    __shared__ __align__(16) float WhS[2][TJ][128];
    __shared__ __align__(16) float PS[2][TJ][64];
    __shared__ float zred[256];

    const int l   = blockIdx.z;
    const float* Whp  = Wh0 + (size_t)l * R * 128;
    const float* srcp = src0 + (size_t)l * R;
    const float* dstp = dst0 + (size_t)l * R;
    const int col0 = l * 128;

    const int b   = blockIdx.y;
    const int i0  = blockIdx.x * TI;
    const int tid = threadIdx.x;

    // FMA-phase mapping: warp w = (wi = w&1 i-half, wc = w>>1 c-quarter);
    // lane = (ig2 = lane>>3, cg = lane&7) owns i = wi*32+ig2*8..+8, c = wc*32+cg*4..+4
    const int w    = tid >> 5;
    const int lane = tid & 31;
    const int wi   = w & 1;
    const int wc   = w >> 1;
    const int ig2  = lane >> 3;
    const int cg   = lane & 7;
    const int ibase = wi * 32 + ig2 * 8;
    const int cbase = wc * 32 + cg * 4;

    // P-phase mapping
    const int ii = tid & 63;
    const int jg = tid >> 6;

    for (int k = tid; k < 512; k += 256) dstS[k] = dstp[(b << 9) + k];
    if (tid < TI) srcS[tid] = srcp[(b << 9) + i0 + tid];
    __syncthreads();

    // ---- block max of dst ----
    {
        float v = fmaxf(dstS[tid], dstS[tid + 256]);
#pragma unroll
        for (int o = 16; o; o >>= 1) v = fmaxf(v, __shfl_xor_sync(0xffffffffu, v, o));
        if ((tid & 31) == 0) red[tid >> 5] = v;
        __syncthreads();
        if (tid == 0) {
            float m = red[0];
#pragma unroll
            for (int k = 1; k < 8; ++k) m = fmaxf(m, red[k]);
            mdstS = m;
        }
        __syncthreads();
    }
    const float mdst = mdstS;

    // ---- exp factors ----
    for (int k = tid; k < 512; k += 256) {
        float d = dstS[k] - mdst;
        FS[k] = make_float2(__expf(d), __expf(0.2f * d));
    }
    if (tid < TI) {
        float t = srcS[tid] + mdst;
        float m = lrelu02(t);
        e1S[tid] = __expf(t - m);
        e2S[tid] = __expf(0.2f * t - m);
    }
    __syncthreads();

    ull acc2[4][4];
#pragma unroll
    for (int rp = 0; rp < 4; ++rp)
#pragma unroll
        for (int c = 0; c < 4; ++c) acc2[rp][c] = 0ull;

    const float4* Whg = reinterpret_cast<const float4*>(Whp) + (size_t)(b << 9) * 32;
    const int* adjrow = adj + ((size_t)(b << 9) + i0 + ii) * 512 + jg * 8;

    const float si = srcS[ii];
    const float e1 = e1S[ii];
    const float e2 = e2S[ii];
    float zloc = 0.f;

    // Wh staging mapping for this thread: 4 float4 elements
    const int sj0 = tid >> 5;          // jj for q=0 (stride 8 rows per q)
    const int sc  = tid & 31;          // float4 column

    // ---- prologue: produce tile 0 into buffer 0 ----
    {
#pragma unroll
        for (int q = 0; q < 4; ++q) {
            int jj = sj0 + q * 8;
            *reinterpret_cast<float4*>(&WhS[0][jj][sc * 4]) = Whg[(size_t)jj * 32 + sc];
        }
        int4 a0 = *reinterpret_cast<const int4*>(adjrow);
        int4 a1 = *reinterpret_cast<const int4*>(adjrow + 4);
        int av[8] = {a0.x, a0.y, a0.z, a0.w, a1.x, a1.y, a1.z, a1.w};
#pragma unroll
        for (int rr = 0; rr < 8; ++rr) {
            int j = jg * 8 + rr;
            float2 f = FS[j];
            float s  = si + dstS[j];
            bool pos = s > 0.f;
            float p  = (pos ? e1 : e2) * (pos ? f.x : f.y);
            p = (av[rr] > 0) ? p : 0.f;
            PS[0][j][ii] = p;
            zloc += p;
        }
    }
    __syncthreads();

    for (int t = 0; t < 16; ++t) {
        const int cur = t & 1, nxt = cur ^ 1;

        // prefetch next tile's global data (issued before FMA to hide latency)
        float4 whp[4];
        int4 a0, a1;
        if (t < 15) {
            const int tj0n = (t + 1) * TJ;
#pragma unroll
            for (int q = 0; q < 4; ++q) {
                int jj = sj0 + q * 8;
                whp[q] = Whg[(size_t)(tj0n + jj) * 32 + sc];
            }
            a0 = *reinterpret_cast<const int4*>(adjrow + tj0n);
            a1 = *reinterpret_cast<const int4*>(adjrow + tj0n + 4);
        }

        // FMA phase on current buffer
#pragma unroll 8
        for (int j = 0; j < TJ; ++j) {
            float4 wv = *reinterpret_cast<const float4*>(&WhS[cur][j][cbase]);
            ull w0 = pack2(wv.x), w1 = pack2(wv.y), w2 = pack2(wv.z), w3 = pack2(wv.w);
            F4U p0, p1;
            p0.f = *reinterpret_cast<const float4*>(&PS[cur][j][ibase]);
            p1.f = *reinterpret_cast<const float4*>(&PS[cur][j][ibase + 4]);
            ull pr[4] = {p0.u[0], p0.u[1], p1.u[0], p1.u[1]};
#pragma unroll
            for (int rp = 0; rp < 4; ++rp) {
                fma2(acc2[rp][0], pr[rp], w0);
                fma2(acc2[rp][1], pr[rp], w1);
                fma2(acc2[rp][2], pr[rp], w2);
                fma2(acc2[rp][3], pr[rp], w3);
            }
        }

        // store next tile into alternate buffer
        if (t < 15) {
            const int tj0n = (t + 1) * TJ;
#pragma unroll
            for (int q = 0; q < 4; ++q) {
                int jj = sj0 + q * 8;
                *reinterpret_cast<float4*>(&WhS[nxt][jj][sc * 4]) = whp[q];
            }
            int av[8] = {a0.x, a0.y, a0.z, a0.w, a1.x, a1.y, a1.z, a1.w};
#pragma unroll
            for (int rr = 0; rr < 8; ++rr) {
                int j = jg * 8 + rr;
                float2 f = FS[tj0n + j];
                float s  = si + dstS[tj0n + j];
                bool pos = s > 0.f;
                float p  = (pos ? e1 : e2) * (pos ? f.x : f.y);
                p = (av[rr] > 0) ? p : 0.f;
                PS[nxt][j][ii] = p;
                zloc += p;
            }
        }
        __syncthreads();
    }

    // ---- Z reduction: 4 j-slices per row ----
    zred[tid] = zloc;
    __syncthreads();
    if (tid < TI)
        rZS[tid] = 1.f / (zred[tid] + zred[64 + tid] + zred[128 + tid] + zred[192 + tid]);
    __syncthreads();

    float val[8][4];
#pragma unroll
    for (int rp = 0; rp < 4; ++rp)
#pragma unroll
        for (int c = 0; c < 4; ++c)
            unpack2(acc2[rp][c], val[2 * rp][c], val[2 * rp + 1][c]);

#pragma unroll
    for (int rr = 0; rr < 8; ++rr) {
        int il  = ibase + rr;
        float s = rZS[il];
        float4 o;
        o.x = elu1(val[rr][0] * s);
        o.y = elu1(val[rr][1] * s);
        o.z = elu1(val[rr][2] * s);
        o.w = elu1(val[rr][3] * s);
        *reinterpret_cast<float4*>(&outp[((size_t)(b << 9) + i0 + il) * ld + col0 + cbase]) = o;
    }
}

// ============ K4: out = lrelu( x @ Wc + bc ), blocked GEMM ============
__global__ __launch_bounds__(256) void k_final(const float* __restrict__ Wc,
                                               const float* __restrict__ bc,
                                               float* __restrict__ out)
{
    __shared__ __align__(16) float WtS[32][128];
    __shared__ __align__(16) float htT[32][68];

    int r0   = blockIdx.y * 512 + blockIdx.x * 64;
    int col0 = blockIdx.z * 128;
    int tid  = threadIdx.x;
    int fg   = tid & 31;
    int ig   = tid >> 5;

    ull acc2[4][4];
#pragma unroll
    for (int rp = 0; rp < 4; ++rp)
#pragma unroll
        for (int c = 0; c < 4; ++c) acc2[rp][c] = 0ull;

    for (int k0 = 0; k0 < 128; k0 += 32) {
        __syncthreads();
        for (int e = tid; e < 32 * 32; e += 256) {
            int k = e >> 5, c = e & 31;
            *reinterpret_cast<float4*>(&WtS[k][c * 4]) =
                *reinterpret_cast<const float4*>(&Wc[(size_t)(k0 + k) * 256 + col0 + c * 4]);
        }
        for (int e = tid; e < 64 * 32; e += 256) {
            int ii = e >> 5, k = e & 31;
            htT[k][ii] = g_x[(size_t)(r0 + ii) * 128 + k0 + k];
        }
        __syncthreads();

#pragma unroll 8
        for (int k = 0; k < 32; ++k) {
            float4 w = *reinterpret_cast<const float4*>(&WtS[k][fg * 4]);
            ull w0 = pack2(w.x), w1 = pack2(w.y), w2 = pack2(w.z), w3 = pack2(w.w);
            F4U p0, p1;
            p0.f = *reinterpret_cast<const float4*>(&htT[k][ig * 8]);
            p1.f = *reinterpret_cast<const float4*>(&htT[k][ig * 8 + 4]);
            ull pr[4] = {p0.u[0], p0.u[1], p1.u[0], p1.u[1]};
#pragma unroll
            for (int rp = 0; rp < 4; ++rp) {
                fma2(acc2[rp][0], pr[rp], w0);
                fma2(acc2[rp][1], pr[rp], w1);
                fma2(acc2[rp][2], pr[rp], w2);
                fma2(acc2[rp][3], pr[rp], w3);
            }
        }
    }

    float val[8][4];
#pragma unroll
    for (int rp = 0; rp < 4; ++rp)
#pragma unroll
        for (int c = 0; c < 4; ++c)
            unpack2(acc2[rp][c], val[2 * rp][c], val[2 * rp + 1][c]);

    float bv[4];
#pragma unroll
    for (int c = 0; c < 4; ++c) bv[c] = bc[col0 + fg * 4 + c];

#pragma unroll
    for (int rr = 0; rr < 8; ++rr) {
        int i = r0 + ig * 8 + rr;
        float4 o;
        o.x = lrelu02(val[rr][0] + bv[0]);
        o.y = lrelu02(val[rr][1] + bv[1]);
        o.z = lrelu02(val[rr][2] + bv[2]);
        o.w = lrelu02(val[rr][3] + bv[3]);
        *reinterpret_cast<float4*>(&out[(size_t)i * 256 + col0 + fg * 4]) = o;
    }
}

// ---------------- launch ----------------
extern "C" void kernel_launch(void* const* d_in, const int* in_sizes, int n_in,
                              void* d_out, int out_size)
{
    (void)in_sizes; (void)n_in; (void)out_size;
    const float* compound = (const float*)d_in[0];   // [64,512,34]
    const int*   adj      = (const int*)d_in[1];     // [64,512,512]
    const float* Wst      = (const float*)d_in[2];   // [3,34,128]
    const float* ast      = (const float*)d_in[3];   // [3,256,1]
    const float* Wout     = (const float*)d_in[4];   // [384,128]
    const float* aout     = (const float*)d_in[5];   // [256,1]
    const float* Wc       = (const float*)d_in[6];   // [128,256]
    const float* bc       = (const float*)d_in[7];   // [256]
    float* out = (float*)d_out;                      // [64,512,256]

    float* g_Wh3_p;   cudaGetSymbolAddress((void**)&g_Wh3_p,  g_Wh3);
    float* g_heads_p; cudaGetSymbolAddress((void**)&g_heads_p, g_heads);
    float* g_x_p;     cudaGetSymbolAddress((void**)&g_x_p,    g_x);
    float* g_src_p;   cudaGetSymbolAddress((void**)&g_src_p,  g_src3);
    float* g_dst_p;   cudaGetSymbolAddress((void**)&g_dst_p,  g_dst3);

    // all 3 input-layer projections in one launch (grid.z = layer)
    k_proj<34, 34><<<dim3(N / 64, B, 3), 256>>>(
        compound, 34, Wst, ast, g_Wh3_p, g_src_p, g_dst_p);

    // all 3 head aggregations in one launch (independent layers)
    k_agg<<<dim3(N / 64, B, 3), 256>>>(adj, g_Wh3_p, g_src_p, g_dst_p,
                                       g_heads_p, 384);

    // out-layer projection on concatenated heads
    k_proj<384, 32><<<dim3(N / 64, B, 1), 256>>>(
        g_heads_p, 384, Wout, aout,
        g_Wh3_p + (size_t)3 * R * 128, g_src_p + (size_t)3 * R, g_dst_p + (size_t)3 * R);

    // out-layer aggregation (grid.z = 1 -> col0 = 0)
    k_agg<<<dim3(N / 64, B, 1), 256>>>(adj, g_Wh3_p + (size_t)3 * R * 128,
                                       g_src_p + (size_t)3 * R, g_dst_p + (size_t)3 * R,
                                       g_x_p, 128);

    k_final<<<dim3(N / 64, B, 2), 256>>>(Wc, bc, out);
}

// round 9
// speedup vs baseline: 3.2259x; 1.3678x over previous
#include <cuda_runtime.h>
#include <cstdint>

typedef unsigned long long ull;

// ---------------- problem constants ----------------
constexpr int B = 64;
constexpr int N = 512;
constexpr int R = B * N;      // 32768 rows

// ---------------- device scratch ----------------
// WhT: per layer, per batch, TRANSPOSED [f][j], tf32-rounded (mma B operand)
__device__ float g_WhT[(size_t)4 * R * 128];
__device__ float g_heads[(size_t)R * 384];
__device__ float g_x[(size_t)R * 128];
__device__ float g_src3[4 * R];
__device__ float g_dst3[4 * R];

__device__ __forceinline__ float lrelu02(float x) { return x > 0.f ? x : 0.2f * x; }
__device__ __forceinline__ float elu1(float x)    { return x > 0.f ? x : expm1f(x); }

__device__ __forceinline__ void fma2(ull& d, ull a, ull b) {
    asm("fma.rn.f32x2 %0, %1, %2, %3;" : "=l"(d) : "l"(a), "l"(b), "l"(d));
}
__device__ __forceinline__ ull pack2(float x) {
    ull r; asm("mov.b64 %0, {%1, %1};" : "=l"(r) : "f"(x)); return r;
}
__device__ __forceinline__ void unpack2(ull v, float& lo, float& hi) {
    asm("mov.b64 {%0, %1}, %2;" : "=f"(lo), "=f"(hi) : "l"(v));
}
__device__ __forceinline__ float totf32(float x) {
    float r; asm("cvt.rna.tf32.f32 %0, %1;" : "=f"(r) : "f"(x)); return r;
}
union F4U { float4 f; ull u[2]; };

// warp-level tf32 MMA (baseline PTX, sm_80+; lowers to HMMA on sm_103)
__device__ __forceinline__ void mma_tf32(float* d,
    uint32_t a0, uint32_t a1, uint32_t a2, uint32_t a3,
    uint32_t b0, uint32_t b1)
{
    asm volatile(
        "mma.sync.aligned.m16n8k8.row.col.f32.tf32.tf32.f32 "
        "{%0,%1,%2,%3}, {%4,%5,%6,%7}, {%8,%9}, {%0,%1,%2,%3};"
        : "+f"(d[0]), "+f"(d[1]), "+f"(d[2]), "+f"(d[3])
        : "r"(a0), "r"(a1), "r"(a2), "r"(a3), "r"(b0), "r"(b1));
}

// ============ K1: blocked GEMM Wh = X @ W (fused src/dst); stores WhT tf32 ============
template<int FIN, int TK>
__global__ __launch_bounds__(256) void k_proj(
    const float* __restrict__ X, int ldx,
    const float* __restrict__ Wbase, const float* __restrict__ abase,
    float* __restrict__ WhTout, float* __restrict__ srcout, float* __restrict__ dstout)
{
    __shared__ __align__(16) float WtS[TK][128];
    __shared__ __align__(16) float htT[TK][68];
    __shared__ float aS[256];

    const int l   = blockIdx.z;
    const float* W = Wbase + (size_t)l * FIN * 128;
    const float* a = abase + l * 256;
    float* srcp = srcout + (size_t)l * R;
    float* dstp = dstout + (size_t)l * R;

    const int r0  = blockIdx.y * 512 + blockIdx.x * 64;
    const int tid = threadIdx.x;
    const int fg  = tid & 31;
    const int ig  = tid >> 5;

    aS[tid] = a[tid];

    ull acc2[4][4];
#pragma unroll
    for (int rp = 0; rp < 4; ++rp)
#pragma unroll
        for (int c = 0; c < 4; ++c) acc2[rp][c] = 0ull;

    for (int k0 = 0; k0 < FIN; k0 += TK) {
        __syncthreads();
        for (int e = tid; e < TK * 32; e += 256) {
            int k = e >> 5, c = e & 31;
            *reinterpret_cast<float4*>(&WtS[k][c * 4]) =
                *reinterpret_cast<const float4*>(&W[(size_t)(k0 + k) * 128 + c * 4]);
        }
        for (int e = tid; e < 64 * TK; e += 256) {
            int ii = e / TK, k = e - ii * TK;
            htT[k][ii] = X[(size_t)(r0 + ii) * ldx + k0 + k];
        }
        __syncthreads();

#pragma unroll 8
        for (int k = 0; k < TK; ++k) {
            float4 w = *reinterpret_cast<const float4*>(&WtS[k][fg * 4]);
            ull w0 = pack2(w.x), w1 = pack2(w.y), w2 = pack2(w.z), w3 = pack2(w.w);
            F4U p0, p1;
            p0.f = *reinterpret_cast<const float4*>(&htT[k][ig * 8]);
            p1.f = *reinterpret_cast<const float4*>(&htT[k][ig * 8 + 4]);
            ull pr[4] = {p0.u[0], p0.u[1], p1.u[0], p1.u[1]};
#pragma unroll
            for (int rp = 0; rp < 4; ++rp) {
                fma2(acc2[rp][0], pr[rp], w0);
                fma2(acc2[rp][1], pr[rp], w1);
                fma2(acc2[rp][2], pr[rp], w2);
                fma2(acc2[rp][3], pr[rp], w3);
            }
        }
    }

    float val[8][4];
#pragma unroll
    for (int rp = 0; rp < 4; ++rp)
#pragma unroll
        for (int c = 0; c < 4; ++c)
            unpack2(acc2[rp][c], val[2 * rp][c], val[2 * rp + 1][c]);

    // transposed, tf32-rounded WhT store: WhT[b][f][j]
    {
        float* WT = WhTout + (size_t)l * R * 128 + (size_t)blockIdx.y * 128 * 512;
        const int il0 = blockIdx.x * 64 + ig * 8;
#pragma unroll
        for (int c = 0; c < 4; ++c) {
            int f = fg * 4 + c;
            float4 lo = make_float4(totf32(val[0][c]), totf32(val[1][c]),
                                    totf32(val[2][c]), totf32(val[3][c]));
            float4 hi = make_float4(totf32(val[4][c]), totf32(val[5][c]),
                                    totf32(val[6][c]), totf32(val[7][c]));
            *reinterpret_cast<float4*>(&WT[(size_t)f * 512 + il0])     = lo;
            *reinterpret_cast<float4*>(&WT[(size_t)f * 512 + il0 + 4]) = hi;
        }
    }

    float a1v[4], a2v[4];
#pragma unroll
    for (int c = 0; c < 4; ++c) { a1v[c] = aS[fg * 4 + c]; a2v[c] = aS[128 + fg * 4 + c]; }

#pragma unroll
    for (int rr = 0; rr < 8; ++rr) {
        int i = r0 + ig * 8 + rr;
        float v1 = val[rr][0] * a1v[0] + val[rr][1] * a1v[1] + val[rr][2] * a1v[2] + val[rr][3] * a1v[3];
        float v2 = val[rr][0] * a2v[0] + val[rr][1] * a2v[1] + val[rr][2] * a2v[2] + val[rr][3] * a2v[3];
#pragma unroll
        for (int o2 = 16; o2; o2 >>= 1) {
            v1 += __shfl_xor_sync(0xffffffffu, v1, o2);
            v2 += __shfl_xor_sync(0xffffffffu, v2, o2);
        }
        if (fg == 0) { srcp[i] = v1; dstp[i] = v2; }
    }
}

// ============ K3: mma.sync tf32 fused softmax + aggregate ============
// CTA: 128i x 128f, K=512 in 16 tiles of 32. 8 warps, warp tile 32i x 64f.
constexpr int PLD = 36;   // padded row stride for PS/WS (conflict-free frags)

__global__ __launch_bounds__(256, 2) void k_agg_mma(
    const int* __restrict__ adj, const float* __restrict__ WhT0,
    const float* __restrict__ src0, const float* __restrict__ dst0,
    float* __restrict__ outp, int ld)
{
    __shared__ __align__(16) float PS[128 * PLD];   // P tile [i][j]
    __shared__ __align__(16) float WS[128 * PLD];   // Wh tile [f][j]
    __shared__ float dstS[512];
    __shared__ __align__(16) float2 FS[512];
    __shared__ float srcS[128], e1S[128], e2S[128], rZS[128];
    __shared__ float zpartS[1024];
    __shared__ float red[8];
    __shared__ float mdstS;

    const int l    = blockIdx.z;
    const int b    = blockIdx.y;
    const int i0   = blockIdx.x * 128;
    const int tid  = threadIdx.x;
    const int w    = tid >> 5;
    const int lane = tid & 31;
    const int col0 = l * 128;

    const float* WhTl = WhT0 + (size_t)l * R * 128 + (size_t)b * 128 * 512;
    const float* srcp = src0 + (size_t)l * R;
    const float* dstp = dst0 + (size_t)l * R;

    for (int k = tid; k < 512; k += 256) dstS[k] = dstp[(b << 9) + k];
    if (tid < 128) srcS[tid] = srcp[(b << 9) + i0 + tid];
    __syncthreads();

    // ---- block max of dst ----
    {
        float v = fmaxf(dstS[tid], dstS[tid + 256]);
#pragma unroll
        for (int o = 16; o; o >>= 1) v = fmaxf(v, __shfl_xor_sync(0xffffffffu, v, o));
        if (lane == 0) red[w] = v;
        __syncthreads();
        if (tid == 0) {
            float m = red[0];
#pragma unroll
            for (int k = 1; k < 8; ++k) m = fmaxf(m, red[k]);
            mdstS = m;
        }
        __syncthreads();
    }
    const float mdst = mdstS;

    // ---- exp factors (factored softmax; all in (0,1]) ----
    for (int k = tid; k < 512; k += 256) {
        float d = dstS[k] - mdst;
        FS[k] = make_float2(__expf(d), __expf(0.2f * d));
    }
    if (tid < 128) {
        float t2 = srcS[tid] + mdst;
        float m  = lrelu02(t2);
        e1S[tid] = __expf(t2 - m);
        e2S[tid] = __expf(0.2f * t2 - m);
    }
    __syncthreads();

    // frag-phase mapping
    const int wm = w & 3;          // i block (32 rows)
    const int wn = w >> 2;         // f block (64 cols)
    const int g  = lane >> 2;      // 0..7
    const int q  = lane & 3;       // 0..3

    // P-phase mapping
    const int srow = tid >> 3;     // rows srow, +32, +64, +96
    const int jq   = tid & 7;      // 4-j group

    const int* adjb = adj + ((size_t)(b << 9) + i0) * 512;
    const uint32_t* PSu = reinterpret_cast<const uint32_t*>(PS);
    const uint32_t* WSu = reinterpret_cast<const uint32_t*>(WS);

    float dacc[2][8][4];
#pragma unroll
    for (int mf = 0; mf < 2; ++mf)
#pragma unroll
        for (int nf = 0; nf < 8; ++nf)
#pragma unroll
            for (int c = 0; c < 4; ++c) dacc[mf][nf][c] = 0.f;

    float zl[4] = {0.f, 0.f, 0.f, 0.f};

#pragma unroll 1
    for (int t = 0; t < 16; ++t) {
        const int tj0 = t * 32;
        __syncthreads();   // prev frag loads done; safe to overwrite PS/WS

        // stage Wh tile [128 f][32 j] (already tf32)
#pragma unroll
        for (int k = 0; k < 4; ++k) {
            int e = tid + k * 256;
            int f = e >> 3, c4 = e & 7;
            float4 v = *reinterpret_cast<const float4*>(&WhTl[(size_t)f * 512 + tj0 + c4 * 4]);
            *reinterpret_cast<float4*>(&WS[f * PLD + c4 * 4]) = v;
        }

        // P phase: PS[r][j] = exp(score - m_r) via factored exp, tf32-rounded
#pragma unroll
        for (int qq = 0; qq < 4; ++qq) {
            const int r_ = srow + qq * 32;
            int4  av = *reinterpret_cast<const int4*>(&adjb[(size_t)r_ * 512 + tj0 + jq * 4]);
            float4 d4 = *reinterpret_cast<const float4*>(&dstS[tj0 + jq * 4]);
            const float4* fsp = reinterpret_cast<const float4*>(&FS[tj0 + jq * 4]);
            float4 f01 = fsp[0];
            float4 f23 = fsp[1];
            float sv = srcS[r_], E1 = e1S[r_], E2 = e2S[r_];
            float p0, p1, p2, p3;
            { float s = sv + d4.x; bool gg = s > 0.f; p0 = (gg ? E1 : E2) * (gg ? f01.x : f01.y); p0 = (av.x > 0) ? p0 : 0.f; }
            { float s = sv + d4.y; bool gg = s > 0.f; p1 = (gg ? E1 : E2) * (gg ? f01.z : f01.w); p1 = (av.y > 0) ? p1 : 0.f; }
            { float s = sv + d4.z; bool gg = s > 0.f; p2 = (gg ? E1 : E2) * (gg ? f23.x : f23.y); p2 = (av.z > 0) ? p2 : 0.f; }
            { float s = sv + d4.w; bool gg = s > 0.f; p3 = (gg ? E1 : E2) * (gg ? f23.z : f23.w); p3 = (av.w > 0) ? p3 : 0.f; }
            zl[qq] += (p0 + p1) + (p2 + p3);
            float4 pv = make_float4(totf32(p0), totf32(p1), totf32(p2), totf32(p3));
            *reinterpret_cast<float4*>(&PS[r_ * PLD + jq * 4]) = pv;
        }
        __syncthreads();

        // frag + mma phase
#pragma unroll
        for (int kk = 0; kk < 32; kk += 8) {
            uint32_t bf0[8], bf1[8];
#pragma unroll
            for (int nf = 0; nf < 8; ++nf) {
                int f = wn * 64 + nf * 8 + g;
                bf0[nf] = WSu[f * PLD + kk + q];
                bf1[nf] = WSu[f * PLD + kk + q + 4];
            }
#pragma unroll
            for (int mf = 0; mf < 2; ++mf) {
                int r_ = wm * 32 + mf * 16 + g;
                uint32_t a0 = PSu[r_ * PLD + kk + q];
                uint32_t a1 = PSu[(r_ + 8) * PLD + kk + q];
                uint32_t a2 = PSu[r_ * PLD + kk + q + 4];
                uint32_t a3 = PSu[(r_ + 8) * PLD + kk + q + 4];
#pragma unroll
                for (int nf = 0; nf < 8; ++nf)
                    mma_tf32(dacc[mf][nf], a0, a1, a2, a3, bf0[nf], bf1[nf]);
            }
        }
    }

    // ---- Z reduction ----
    __syncthreads();
#pragma unroll
    for (int qq = 0; qq < 4; ++qq) zpartS[(srow + qq * 32) * 8 + jq] = zl[qq];
    __syncthreads();
    if (tid < 128) {
        float z = 0.f;
#pragma unroll
        for (int k = 0; k < 8; ++k) z += zpartS[tid * 8 + k];
        rZS[tid] = 1.f / z;
    }
    __syncthreads();

    // ---- epilogue: normalize, elu, store ----
#pragma unroll
    for (int mf = 0; mf < 2; ++mf) {
#pragma unroll
        for (int h = 0; h < 2; ++h) {
            int rl = wm * 32 + mf * 16 + g + h * 8;
            float rz = rZS[rl];
            float* orow = outp + ((size_t)(b << 9) + i0 + rl) * ld + col0 + wn * 64;
#pragma unroll
            for (int nf = 0; nf < 8; ++nf) {
                float2 v;
                v.x = elu1(dacc[mf][nf][2 * h]     * rz);
                v.y = elu1(dacc[mf][nf][2 * h + 1] * rz);
                *reinterpret_cast<float2*>(&orow[nf * 8 + 2 * q]) = v;
            }
        }
    }
}

// ============ K4: out = lrelu( x @ Wc + bc ), blocked GEMM ============
__global__ __launch_bounds__(256) void k_final(const float* __restrict__ Wc,
                                               const float* __restrict__ bc,
                                               float* __restrict__ out)
{
    __shared__ __align__(16) float WtS[32][128];
    __shared__ __align__(16) float htT[32][68];

    int r0   = blockIdx.y * 512 + blockIdx.x * 64;
    int col0 = blockIdx.z * 128;
    int tid  = threadIdx.x;
    int fg   = tid & 31;
    int ig   = tid >> 5;

    ull acc2[4][4];
#pragma unroll
    for (int rp = 0; rp < 4; ++rp)
#pragma unroll
        for (int c = 0; c < 4; ++c) acc2[rp][c] = 0ull;

    for (int k0 = 0; k0 < 128; k0 += 32) {
        __syncthreads();
        for (int e = tid; e < 32 * 32; e += 256) {
            int k = e >> 5, c = e & 31;
            *reinterpret_cast<float4*>(&WtS[k][c * 4]) =
                *reinterpret_cast<const float4*>(&Wc[(size_t)(k0 + k) * 256 + col0 + c * 4]);
        }
        for (int e = tid; e < 64 * 32; e += 256) {
            int ii = e >> 5, k = e & 31;
            htT[k][ii] = g_x[(size_t)(r0 + ii) * 128 + k0 + k];
        }
        __syncthreads();

#pragma unroll 8
        for (int k = 0; k < 32; ++k) {
            float4 w = *reinterpret_cast<const float4*>(&WtS[k][fg * 4]);
            ull w0 = pack2(w.x), w1 = pack2(w.y), w2 = pack2(w.z), w3 = pack2(w.w);
            F4U p0, p1;
            p0.f = *reinterpret_cast<const float4*>(&htT[k][ig * 8]);
            p1.f = *reinterpret_cast<const float4*>(&htT[k][ig * 8 + 4]);
            ull pr[4] = {p0.u[0], p0.u[1], p1.u[0], p1.u[1]};
#pragma unroll
            for (int rp = 0; rp < 4; ++rp) {
                fma2(acc2[rp][0], pr[rp], w0);
                fma2(acc2[rp][1], pr[rp], w1);
                fma2(acc2[rp][2], pr[rp], w2);
                fma2(acc2[rp][3], pr[rp], w3);
            }
        }
    }

    float val[8][4];
#pragma unroll
    for (int rp = 0; rp < 4; ++rp)
#pragma unroll
        for (int c = 0; c < 4; ++c)
            unpack2(acc2[rp][c], val[2 * rp][c], val[2 * rp + 1][c]);

    float bv[4];
#pragma unroll
    for (int c = 0; c < 4; ++c) bv[c] = bc[col0 + fg * 4 + c];

#pragma unroll
    for (int rr = 0; rr < 8; ++rr) {
        int i = r0 + ig * 8 + rr;
        float4 o;
        o.x = lrelu02(val[rr][0] + bv[0]);
        o.y = lrelu02(val[rr][1] + bv[1]);
        o.z = lrelu02(val[rr][2] + bv[2]);
        o.w = lrelu02(val[rr][3] + bv[3]);
        *reinterpret_cast<float4*>(&out[(size_t)i * 256 + col0 + fg * 4]) = o;
    }
}

// ---------------- launch ----------------
extern "C" void kernel_launch(void* const* d_in, const int* in_sizes, int n_in,
                              void* d_out, int out_size)
{
    (void)in_sizes; (void)n_in; (void)out_size;
    const float* compound = (const float*)d_in[0];   // [64,512,34]
    const int*   adj      = (const int*)d_in[1];     // [64,512,512]
    const float* Wst      = (const float*)d_in[2];   // [3,34,128]
    const float* ast      = (const float*)d_in[3];   // [3,256,1]
    const float* Wout     = (const float*)d_in[4];   // [384,128]
    const float* aout     = (const float*)d_in[5];   // [256,1]
    const float* Wc       = (const float*)d_in[6];   // [128,256]
    const float* bc       = (const float*)d_in[7];   // [256]
    float* out = (float*)d_out;                      // [64,512,256]

    float* g_WhT_p;   cudaGetSymbolAddress((void**)&g_WhT_p,  g_WhT);
    float* g_heads_p; cudaGetSymbolAddress((void**)&g_heads_p, g_heads);
    float* g_x_p;     cudaGetSymbolAddress((void**)&g_x_p,    g_x);
    float* g_src_p;   cudaGetSymbolAddress((void**)&g_src_p,  g_src3);
    float* g_dst_p;   cudaGetSymbolAddress((void**)&g_dst_p,  g_dst3);

    // all 3 input-layer projections in one launch (grid.z = layer)
    k_proj<34, 34><<<dim3(N / 64, B, 3), 256>>>(
        compound, 34, Wst, ast, g_WhT_p, g_src_p, g_dst_p);

    // all 3 head aggregations, tensor-core (mma.sync tf32) path
    k_agg_mma<<<dim3(N / 128, B, 3), 256>>>(adj, g_WhT_p, g_src_p, g_dst_p,
                                            g_heads_p, 384);

    // out-layer projection on concatenated heads
    k_proj<384, 32><<<dim3(N / 64, B, 1), 256>>>(
        g_heads_p, 384, Wout, aout,
        g_WhT_p + (size_t)3 * R * 128, g_src_p + (size_t)3 * R, g_dst_p + (size_t)3 * R);

    // out-layer aggregation
    k_agg_mma<<<dim3(N / 128, B, 1), 256>>>(adj, g_WhT_p + (size_t)3 * R * 128,
                                            g_src_p + (size_t)3 * R, g_dst_p + (size_t)3 * R,
                                            g_x_p, 128);

    k_final<<<dim3(N / 64, B, 2), 256>>>(Wc, bc, out);
}

// round 10
// speedup vs baseline: 3.9450x; 1.2229x over previous
#include <cuda_runtime.h>
#include <cstdint>

typedef unsigned long long ull;

// ---------------- problem constants ----------------
constexpr int B = 64;
constexpr int N = 512;
constexpr int R = B * N;      // 32768 rows

// ---------------- device scratch ----------------
__device__ float g_WhT[(size_t)4 * R * 128];   // per layer, per batch, [f][j], tf32
__device__ float g_heads[(size_t)R * 384];
__device__ float g_x[(size_t)R * 128];
__device__ float g_src3[4 * R];
__device__ float g_dst3[4 * R];
__device__ uint32_t g_adjbits[(size_t)R * 16]; // adj>0 bitmask, word w covers j=32w..32w+31

__device__ __forceinline__ float lrelu02(float x) { return x > 0.f ? x : 0.2f * x; }
__device__ __forceinline__ float elu1(float x)    { return x > 0.f ? x : expm1f(x); }

__device__ __forceinline__ void fma2(ull& d, ull a, ull b) {
    asm("fma.rn.f32x2 %0, %1, %2, %3;" : "=l"(d) : "l"(a), "l"(b), "l"(d));
}
__device__ __forceinline__ ull pack2(float x) {
    ull r; asm("mov.b64 %0, {%1, %1};" : "=l"(r) : "f"(x)); return r;
}
__device__ __forceinline__ void unpack2(ull v, float& lo, float& hi) {
    asm("mov.b64 {%0, %1}, %2;" : "=f"(lo), "=f"(hi) : "l"(v));
}
__device__ __forceinline__ float totf32(float x) {
    float r; asm("cvt.rna.tf32.f32 %0, %1;" : "=f"(r) : "f"(x)); return r;
}
__device__ __forceinline__ float trunc_tf32(float x) {
    return __uint_as_float(__float_as_uint(x) & 0xffffe000u);
}
__device__ __forceinline__ uint32_t smem_u32(const void* p) {
    uint32_t a;
    asm("{ .reg .u64 t; cvta.to.shared.u64 t, %1; cvt.u32.u64 %0, t; }" : "=r"(a) : "l"(p));
    return a;
}
__device__ __forceinline__ void cp16(uint32_t dst, const void* src) {
    asm volatile("cp.async.cg.shared.global [%0], [%1], 16;" :: "r"(dst), "l"(src));
}
#define CP_COMMIT() asm volatile("cp.async.commit_group;" ::: "memory")
#define CP_WAIT0()  asm volatile("cp.async.wait_group 0;" ::: "memory")

union F4U { float4 f; ull u[2]; };

// warp-level tf32 MMA (baseline PTX, sm_80+)
__device__ __forceinline__ void mma_tf32(float* d,
    uint32_t a0, uint32_t a1, uint32_t a2, uint32_t a3,
    uint32_t b0, uint32_t b1)
{
    asm volatile(
        "mma.sync.aligned.m16n8k8.row.col.f32.tf32.tf32.f32 "
        "{%0,%1,%2,%3}, {%4,%5,%6,%7}, {%8,%9}, {%0,%1,%2,%3};"
        : "+f"(d[0]), "+f"(d[1]), "+f"(d[2]), "+f"(d[3])
        : "r"(a0), "r"(a1), "r"(a2), "r"(a3), "r"(b0), "r"(b1));
}

// ============ K0: pack adj into bitmask ============
__global__ __launch_bounds__(256) void k_pack(const int* __restrict__ adj,
                                              uint32_t* __restrict__ bits)
{
    int gid = blockIdx.x * 256 + threadIdx.x;   // one 32-bit word
    const int4* p = reinterpret_cast<const int4*>(adj) + (size_t)gid * 8;
    uint32_t m = 0;
#pragma unroll
    for (int k = 0; k < 8; ++k) {
        int4 v = p[k];
        m |= (v.x > 0 ? 1u : 0u) << (k * 4 + 0);
        m |= (v.y > 0 ? 1u : 0u) << (k * 4 + 1);
        m |= (v.z > 0 ? 1u : 0u) << (k * 4 + 2);
        m |= (v.w > 0 ? 1u : 0u) << (k * 4 + 3);
    }
    bits[gid] = m;
}

// ============ K1: blocked GEMM Wh = X @ W (fused src/dst); stores WhT tf32 ============
template<int FIN, int TK>
__global__ __launch_bounds__(256) void k_proj(
    const float* __restrict__ X, int ldx,
    const float* __restrict__ Wbase, const float* __restrict__ abase,
    float* __restrict__ WhTout, float* __restrict__ srcout, float* __restrict__ dstout)
{
    __shared__ __align__(16) float WtS[TK][128];
    __shared__ __align__(16) float htT[TK][68];
    __shared__ float aS[256];

    const int l   = blockIdx.z;
    const float* W = Wbase + (size_t)l * FIN * 128;
    const float* a = abase + l * 256;
    float* srcp = srcout + (size_t)l * R;
    float* dstp = dstout + (size_t)l * R;

    const int r0  = blockIdx.y * 512 + blockIdx.x * 64;
    const int tid = threadIdx.x;
    const int fg  = tid & 31;
    const int ig  = tid >> 5;

    aS[tid] = a[tid];

    ull acc2[4][4];
#pragma unroll
    for (int rp = 0; rp < 4; ++rp)
#pragma unroll
        for (int c = 0; c < 4; ++c) acc2[rp][c] = 0ull;

    for (int k0 = 0; k0 < FIN; k0 += TK) {
        __syncthreads();
        for (int e = tid; e < TK * 32; e += 256) {
            int k = e >> 5, c = e & 31;
            *reinterpret_cast<float4*>(&WtS[k][c * 4]) =
                *reinterpret_cast<const float4*>(&W[(size_t)(k0 + k) * 128 + c * 4]);
        }
        for (int e = tid; e < 64 * TK; e += 256) {
            int ii = e / TK, k = e - ii * TK;
            htT[k][ii] = X[(size_t)(r0 + ii) * ldx + k0 + k];
        }
        __syncthreads();

#pragma unroll 8
        for (int k = 0; k < TK; ++k) {
            float4 w = *reinterpret_cast<const float4*>(&WtS[k][fg * 4]);
            ull w0 = pack2(w.x), w1 = pack2(w.y), w2 = pack2(w.z), w3 = pack2(w.w);
            F4U p0, p1;
            p0.f = *reinterpret_cast<const float4*>(&htT[k][ig * 8]);
            p1.f = *reinterpret_cast<const float4*>(&htT[k][ig * 8 + 4]);
            ull pr[4] = {p0.u[0], p0.u[1], p1.u[0], p1.u[1]};
#pragma unroll
            for (int rp = 0; rp < 4; ++rp) {
                fma2(acc2[rp][0], pr[rp], w0);
                fma2(acc2[rp][1], pr[rp], w1);
                fma2(acc2[rp][2], pr[rp], w2);
                fma2(acc2[rp][3], pr[rp], w3);
            }
        }
    }

    float val[8][4];
#pragma unroll
    for (int rp = 0; rp < 4; ++rp)
#pragma unroll
        for (int c = 0; c < 4; ++c)
            unpack2(acc2[rp][c], val[2 * rp][c], val[2 * rp + 1][c]);

    // transposed, tf32-rounded WhT store: WhT[b][f][j]
    {
        float* WT = WhTout + (size_t)l * R * 128 + (size_t)blockIdx.y * 128 * 512;
        const int il0 = blockIdx.x * 64 + ig * 8;
#pragma unroll
        for (int c = 0; c < 4; ++c) {
            int f = fg * 4 + c;
            float4 lo = make_float4(totf32(val[0][c]), totf32(val[1][c]),
                                    totf32(val[2][c]), totf32(val[3][c]));
            float4 hi = make_float4(totf32(val[4][c]), totf32(val[5][c]),
                                    totf32(val[6][c]), totf32(val[7][c]));
            *reinterpret_cast<float4*>(&WT[(size_t)f * 512 + il0])     = lo;
            *reinterpret_cast<float4*>(&WT[(size_t)f * 512 + il0 + 4]) = hi;
        }
    }

    float a1v[4], a2v[4];
#pragma unroll
    for (int c = 0; c < 4; ++c) { a1v[c] = aS[fg * 4 + c]; a2v[c] = aS[128 + fg * 4 + c]; }

#pragma unroll
    for (int rr = 0; rr < 8; ++rr) {
        int i = r0 + ig * 8 + rr;
        float v1 = val[rr][0] * a1v[0] + val[rr][1] * a1v[1] + val[rr][2] * a1v[2] + val[rr][3] * a1v[3];
        float v2 = val[rr][0] * a2v[0] + val[rr][1] * a2v[1] + val[rr][2] * a2v[2] + val[rr][3] * a2v[3];
#pragma unroll
        for (int o2 = 16; o2; o2 >>= 1) {
            v1 += __shfl_xor_sync(0xffffffffu, v1, o2);
            v2 += __shfl_xor_sync(0xffffffffu, v2, o2);
        }
        if (fg == 0) { srcp[i] = v1; dstp[i] = v2; }
    }
}

// ============ K3: pipelined mma.sync tf32 fused softmax + aggregate ============
constexpr int PLD = 36;
// dynamic smem layout (float offsets)
constexpr int WS_OFF  = 0;                       // 2 x 128 x PLD
constexpr int PS_OFF  = WS_OFF + 2 * 128 * PLD;  // 9216
constexpr int DST_OFF = PS_OFF + 2 * 128 * PLD;  // 18432
constexpr int FS_OFF  = DST_OFF + 512;           // float2[512] -> 1024 floats
constexpr int SRC_OFF = FS_OFF + 1024;
constexpr int E1_OFF  = SRC_OFF + 128;
constexpr int E2_OFF  = E1_OFF + 128;
constexpr int RZ_OFF  = E2_OFF + 128;
constexpr int ZP_OFF  = RZ_OFF + 128;            // 1024
constexpr int RED_OFF = ZP_OFF + 1024;           // 8
constexpr int MD_OFF  = RED_OFF + 8;
constexpr int AGG_SMEM_BYTES = (MD_OFF + 4) * 4;

__global__ __launch_bounds__(256, 2) void k_agg_mma(
    const uint32_t* __restrict__ bits, const float* __restrict__ WhT0,
    const float* __restrict__ src0, const float* __restrict__ dst0,
    float* __restrict__ outp, int ld)
{
    extern __shared__ __align__(16) float dyn[];
    float* WSf  = dyn + WS_OFF;
    float* PSf  = dyn + PS_OFF;
    float* dstS = dyn + DST_OFF;
    float2* FS2 = reinterpret_cast<float2*>(dyn + FS_OFF);
    float* srcS = dyn + SRC_OFF;
    float* e1S  = dyn + E1_OFF;
    float* e2S  = dyn + E2_OFF;
    float* rZS  = dyn + RZ_OFF;
    float* zpartS = dyn + ZP_OFF;
    float* red  = dyn + RED_OFF;
    float* mdstS = dyn + MD_OFF;

    const uint32_t ws_base = smem_u32(WSf);

    const int l    = blockIdx.z;
    const int b    = blockIdx.y;
    const int i0   = blockIdx.x * 128;
    const int tid  = threadIdx.x;
    const int w    = tid >> 5;
    const int lane = tid & 31;
    const int col0 = l * 128;

    const float* WhTl = WhT0 + (size_t)l * R * 128 + (size_t)b * 128 * 512;
    const float* srcp = src0 + (size_t)l * R;
    const float* dstp = dst0 + (size_t)l * R;
    const uint32_t* bitsb = bits + ((size_t)(b << 9) + i0) * 16;

    for (int k = tid; k < 512; k += 256) dstS[k] = dstp[(b << 9) + k];
    if (tid < 128) srcS[tid] = srcp[(b << 9) + i0 + tid];
    __syncthreads();

    // ---- block max of dst ----
    {
        float v = fmaxf(dstS[tid], dstS[tid + 256]);
#pragma unroll
        for (int o = 16; o; o >>= 1) v = fmaxf(v, __shfl_xor_sync(0xffffffffu, v, o));
        if (lane == 0) red[w] = v;
        __syncthreads();
        if (tid == 0) {
            float m = red[0];
#pragma unroll
            for (int k = 1; k < 8; ++k) m = fmaxf(m, red[k]);
            mdstS[0] = m;
        }
        __syncthreads();
    }
    const float mdst = mdstS[0];

    // ---- exp factors ----
    for (int k = tid; k < 512; k += 256) {
        float d = dstS[k] - mdst;
        FS2[k] = make_float2(__expf(d), __expf(0.2f * d));
    }
    if (tid < 128) {
        float t2 = srcS[tid] + mdst;
        float m  = lrelu02(t2);
        e1S[tid] = __expf(t2 - m);
        e2S[tid] = __expf(0.2f * t2 - m);
    }
    __syncthreads();

    // frag-phase mapping
    const int wm = w & 3;
    const int wn = w >> 2;
    const int g  = lane >> 2;
    const int q  = lane & 3;

    // P/staging mapping
    const int srow = tid >> 3;     // rows srow, +32, +64, +96
    const int jq   = tid & 7;      // 4-j group

    float dacc[2][8][4];
#pragma unroll
    for (int mf = 0; mf < 2; ++mf)
#pragma unroll
        for (int nf = 0; nf < 8; ++nf)
#pragma unroll
            for (int c = 0; c < 4; ++c) dacc[mf][nf][c] = 0.f;

    float zl[4] = {0.f, 0.f, 0.f, 0.f};

    // staging indices for WS cp.async (4 float4 per thread)
    const int sf[4]  = { (tid + 0) >> 3, (tid + 256) >> 3, (tid + 512) >> 3, (tid + 768) >> 3 };
    const int sc4    = jq;   // (e & 7) == tid & 7 for all k since 256 % 8 == 0

    // ---- prologue: stage WS[0] (tile 0) async; compute PS[0] (tile 0) ----
#pragma unroll
    for (int k = 0; k < 4; ++k)
        cp16(ws_base + (uint32_t)(sf[k] * PLD + sc4 * 4) * 4,
             WhTl + (size_t)sf[k] * 512 + sc4 * 4);
    CP_COMMIT();
    {
        float4 d4 = *reinterpret_cast<const float4*>(&dstS[jq * 4]);
        const float4* fsp = reinterpret_cast<const float4*>(&FS2[jq * 4]);
        float4 f01 = fsp[0], f23 = fsp[1];
#pragma unroll
        for (int qq = 0; qq < 4; ++qq) {
            int r_ = srow + qq * 32;
            uint32_t m = bitsb[r_ * 16 + 0];
            float sv = srcS[r_], E1 = e1S[r_], E2 = e2S[r_];
            float p0, p1, p2, p3;
            { float s = sv + d4.x; bool gg = s > 0.f; p0 = (gg ? E1 : E2) * (gg ? f01.x : f01.y); }
            { float s = sv + d4.y; bool gg = s > 0.f; p1 = (gg ? E1 : E2) * (gg ? f01.z : f01.w); }
            { float s = sv + d4.z; bool gg = s > 0.f; p2 = (gg ? E1 : E2) * (gg ? f23.x : f23.y); }
            { float s = sv + d4.w; bool gg = s > 0.f; p3 = (gg ? E1 : E2) * (gg ? f23.z : f23.w); }
            p0 = ((m >> (jq * 4 + 0)) & 1u) ? trunc_tf32(p0) : 0.f;
            p1 = ((m >> (jq * 4 + 1)) & 1u) ? trunc_tf32(p1) : 0.f;
            p2 = ((m >> (jq * 4 + 2)) & 1u) ? trunc_tf32(p2) : 0.f;
            p3 = ((m >> (jq * 4 + 3)) & 1u) ? trunc_tf32(p3) : 0.f;
            zl[qq] += (p0 + p1) + (p2 + p3);
            *reinterpret_cast<float4*>(&PSf[r_ * PLD + jq * 4]) =
                make_float4(p0, p1, p2, p3);
        }
    }
    CP_WAIT0();
    __syncthreads();

    // ---- pipelined main loop ----
#pragma unroll 1
    for (int t = 0; t < 16; ++t) {
        const int cur = t & 1, nxt = cur ^ 1;

        if (t < 15) {
            const int tj1 = (t + 1) * 32;
            // async stage WS[nxt] = Wh tile t+1
#pragma unroll
            for (int k = 0; k < 4; ++k)
                cp16(ws_base + (uint32_t)(nxt * 4608 + sf[k] * PLD + sc4 * 4) * 4,
                     WhTl + (size_t)sf[k] * 512 + tj1 + sc4 * 4);
            CP_COMMIT();

            // P compute tile t+1 into PS[nxt]
            float4 d4 = *reinterpret_cast<const float4*>(&dstS[tj1 + jq * 4]);
            const float4* fsp = reinterpret_cast<const float4*>(&FS2[tj1 + jq * 4]);
            float4 f01 = fsp[0], f23 = fsp[1];
            float* PSb = PSf + nxt * 4608;
#pragma unroll
            for (int qq = 0; qq < 4; ++qq) {
                int r_ = srow + qq * 32;
                uint32_t m = bitsb[r_ * 16 + (t + 1)];
                float sv = srcS[r_], E1 = e1S[r_], E2 = e2S[r_];
                float p0, p1, p2, p3;
                { float s = sv + d4.x; bool gg = s > 0.f; p0 = (gg ? E1 : E2) * (gg ? f01.x : f01.y); }
                { float s = sv + d4.y; bool gg = s > 0.f; p1 = (gg ? E1 : E2) * (gg ? f01.z : f01.w); }
                { float s = sv + d4.z; bool gg = s > 0.f; p2 = (gg ? E1 : E2) * (gg ? f23.x : f23.y); }
                { float s = sv + d4.w; bool gg = s > 0.f; p3 = (gg ? E1 : E2) * (gg ? f23.z : f23.w); }
                p0 = ((m >> (jq * 4 + 0)) & 1u) ? trunc_tf32(p0) : 0.f;
                p1 = ((m >> (jq * 4 + 1)) & 1u) ? trunc_tf32(p1) : 0.f;
                p2 = ((m >> (jq * 4 + 2)) & 1u) ? trunc_tf32(p2) : 0.f;
                p3 = ((m >> (jq * 4 + 3)) & 1u) ? trunc_tf32(p3) : 0.f;
                zl[qq] += (p0 + p1) + (p2 + p3);
                *reinterpret_cast<float4*>(&PSb[r_ * PLD + jq * 4]) =
                    make_float4(p0, p1, p2, p3);
            }
        }

        // mma on current buffers
        const uint32_t* PSu = reinterpret_cast<const uint32_t*>(PSf + cur * 4608);
        const uint32_t* WSu = reinterpret_cast<const uint32_t*>(WSf + cur * 4608);
#pragma unroll
        for (int kk = 0; kk < 32; kk += 8) {
            uint32_t bf0[8], bf1[8];
#pragma unroll
            for (int nf = 0; nf < 8; ++nf) {
                int f = wn * 64 + nf * 8 + g;
                bf0[nf] = WSu[f * PLD + kk + q];
                bf1[nf] = WSu[f * PLD + kk + q + 4];
            }
#pragma unroll
            for (int mf = 0; mf < 2; ++mf) {
                int r_ = wm * 32 + mf * 16 + g;
                uint32_t a0 = PSu[r_ * PLD + kk + q];
                uint32_t a1 = PSu[(r_ + 8) * PLD + kk + q];
                uint32_t a2 = PSu[r_ * PLD + kk + q + 4];
                uint32_t a3 = PSu[(r_ + 8) * PLD + kk + q + 4];
#pragma unroll
                for (int nf = 0; nf < 8; ++nf)
                    mma_tf32(dacc[mf][nf], a0, a1, a2, a3, bf0[nf], bf1[nf]);
            }
        }

        if (t < 15) CP_WAIT0();
        __syncthreads();
    }

    // ---- Z reduction ----
#pragma unroll
    for (int qq = 0; qq < 4; ++qq) zpartS[(srow + qq * 32) * 8 + jq] = zl[qq];
    __syncthreads();
    if (tid < 128) {
        float z = 0.f;
#pragma unroll
        for (int k = 0; k < 8; ++k) z += zpartS[tid * 8 + k];
        rZS[tid] = 1.f / z;
    }
    __syncthreads();

    // ---- epilogue: normalize, elu, store ----
#pragma unroll
    for (int mf = 0; mf < 2; ++mf) {
#pragma unroll
        for (int h = 0; h < 2; ++h) {
            int rl = wm * 32 + mf * 16 + g + h * 8;
            float rz = rZS[rl];
            float* orow = outp + ((size_t)(b << 9) + i0 + rl) * ld + col0 + wn * 64;
#pragma unroll
            for (int nf = 0; nf < 8; ++nf) {
                float2 v;
                v.x = elu1(dacc[mf][nf][2 * h]     * rz);
                v.y = elu1(dacc[mf][nf][2 * h + 1] * rz);
                *reinterpret_cast<float2*>(&orow[nf * 8 + 2 * q]) = v;
            }
        }
    }
}

// ============ K4: out = lrelu( x @ Wc + bc ), blocked GEMM ============
__global__ __launch_bounds__(256) void k_final(const float* __restrict__ Wc,
                                               const float* __restrict__ bc,
                                               float* __restrict__ out)
{
    __shared__ __align__(16) float WtS[32][128];
    __shared__ __align__(16) float htT[32][68];

    int r0   = blockIdx.y * 512 + blockIdx.x * 64;
    int col0 = blockIdx.z * 128;
    int tid  = threadIdx.x;
    int fg   = tid & 31;
    int ig   = tid >> 5;

    ull acc2[4][4];
#pragma unroll
    for (int rp = 0; rp < 4; ++rp)
#pragma unroll
        for (int c = 0; c < 4; ++c) acc2[rp][c] = 0ull;

    for (int k0 = 0; k0 < 128; k0 += 32) {
        __syncthreads();
        for (int e = tid; e < 32 * 32; e += 256) {
            int k = e >> 5, c = e & 31;
            *reinterpret_cast<float4*>(&WtS[k][c * 4]) =
                *reinterpret_cast<const float4*>(&Wc[(size_t)(k0 + k) * 256 + col0 + c * 4]);
        }
        for (int e = tid; e < 64 * 32; e += 256) {
            int ii = e >> 5, k = e & 31;
            htT[k][ii] = g_x[(size_t)(r0 + ii) * 128 + k0 + k];
        }
        __syncthreads();

#pragma unroll 8
        for (int k = 0; k < 32; ++k) {
            float4 w = *reinterpret_cast<const float4*>(&WtS[k][fg * 4]);
            ull w0 = pack2(w.x), w1 = pack2(w.y), w2 = pack2(w.z), w3 = pack2(w.w);
            F4U p0, p1;
            p0.f = *reinterpret_cast<const float4*>(&htT[k][ig * 8]);
            p1.f = *reinterpret_cast<const float4*>(&htT[k][ig * 8 + 4]);
            ull pr[4] = {p0.u[0], p0.u[1], p1.u[0], p1.u[1]};
#pragma unroll
            for (int rp = 0; rp < 4; ++rp) {
                fma2(acc2[rp][0], pr[rp], w0);
                fma2(acc2[rp][1], pr[rp], w1);
                fma2(acc2[rp][2], pr[rp], w2);
                fma2(acc2[rp][3], pr[rp], w3);
            }
        }
    }

    float val[8][4];
#pragma unroll
    for (int rp = 0; rp < 4; ++rp)
#pragma unroll
        for (int c = 0; c < 4; ++c)
            unpack2(acc2[rp][c], val[2 * rp][c], val[2 * rp + 1][c]);

    float bv[4];
#pragma unroll
    for (int c = 0; c < 4; ++c) bv[c] = bc[col0 + fg * 4 + c];

#pragma unroll
    for (int rr = 0; rr < 8; ++rr) {
        int i = r0 + ig * 8 + rr;
        float4 o;
        o.x = lrelu02(val[rr][0] + bv[0]);
        o.y = lrelu02(val[rr][1] + bv[1]);
        o.z = lrelu02(val[rr][2] + bv[2]);
        o.w = lrelu02(val[rr][3] + bv[3]);
        *reinterpret_cast<float4*>(&out[(size_t)i * 256 + col0 + fg * 4]) = o;
    }
}

// ---------------- launch ----------------
extern "C" void kernel_launch(void* const* d_in, const int* in_sizes, int n_in,
                              void* d_out, int out_size)
{
    (void)in_sizes; (void)n_in; (void)out_size;
    const float* compound = (const float*)d_in[0];   // [64,512,34]
    const int*   adj      = (const int*)d_in[1];     // [64,512,512]
    const float* Wst      = (const float*)d_in[2];   // [3,34,128]
    const float* ast      = (const float*)d_in[3];   // [3,256,1]
    const float* Wout     = (const float*)d_in[4];   // [384,128]
    const float* aout     = (const float*)d_in[5];   // [256,1]
    const float* Wc       = (const float*)d_in[6];   // [128,256]
    const float* bc       = (const float*)d_in[7];   // [256]
    float* out = (float*)d_out;                      // [64,512,256]

    float* g_WhT_p;   cudaGetSymbolAddress((void**)&g_WhT_p,  g_WhT);
    float* g_heads_p; cudaGetSymbolAddress((void**)&g_heads_p, g_heads);
    float* g_x_p;     cudaGetSymbolAddress((void**)&g_x_p,    g_x);
    float* g_src_p;   cudaGetSymbolAddress((void**)&g_src_p,  g_src3);
    float* g_dst_p;   cudaGetSymbolAddress((void**)&g_dst_p,  g_dst3);
    uint32_t* g_bits_p; cudaGetSymbolAddress((void**)&g_bits_p, g_adjbits);

    cudaFuncSetAttribute(k_agg_mma, cudaFuncAttributeMaxDynamicSharedMemorySize,
                         AGG_SMEM_BYTES);

    // pack adjacency bits (reused by all 4 agg launches)
    k_pack<<<(R * 16) / 256, 256>>>(adj, g_bits_p);

    // all 3 input-layer projections in one launch
    k_proj<34, 34><<<dim3(N / 64, B, 3), 256>>>(
        compound, 34, Wst, ast, g_WhT_p, g_src_p, g_dst_p);

    // all 3 head aggregations (pipelined mma.sync tf32)
    k_agg_mma<<<dim3(N / 128, B, 3), 256, AGG_SMEM_BYTES>>>(
        g_bits_p, g_WhT_p, g_src_p, g_dst_p, g_heads_p, 384);

    // out-layer projection on concatenated heads
    k_proj<384, 32><<<dim3(N / 64, B, 1), 256>>>(
        g_heads_p, 384, Wout, aout,
        g_WhT_p + (size_t)3 * R * 128, g_src_p + (size_t)3 * R, g_dst_p + (size_t)3 * R);

    // out-layer aggregation
    k_agg_mma<<<dim3(N / 128, B, 1), 256, AGG_SMEM_BYTES>>>(
        g_bits_p, g_WhT_p + (size_t)3 * R * 128,
        g_src_p + (size_t)3 * R, g_dst_p + (size_t)3 * R, g_x_p, 128);

    k_final<<<dim3(N / 64, B, 2), 256>>>(Wc, bc, out);
}

// round 11
// speedup vs baseline: 5.0892x; 1.2900x over previous
#include <cuda_runtime.h>
#include <cstdint>

typedef unsigned long long ull;

// ---------------- problem constants ----------------
constexpr int B = 64;
constexpr int N = 512;
constexpr int R = B * N;      // 32768 rows

// ---------------- device scratch ----------------
__device__ float g_WhT[(size_t)4 * R * 128];   // per layer, per batch, [f][j], tf32
__device__ float g_heads[(size_t)R * 384];     // tf32-rounded values (elu out)
__device__ float g_x[(size_t)R * 128];         // tf32-rounded values
__device__ float g_src3[4 * R];
__device__ float g_dst3[4 * R];
__device__ uint32_t g_adjbits[(size_t)R * 16];
__device__ float g_WoutT[128 * 384];           // tf32-rounded, [f][k]
__device__ float g_WcT[256 * 128];             // tf32-rounded, [c][k]

__device__ __forceinline__ float lrelu02(float x) { return x > 0.f ? x : 0.2f * x; }
__device__ __forceinline__ float elu1(float x)    { return x > 0.f ? x : expm1f(x); }

__device__ __forceinline__ void fma2(ull& d, ull a, ull b) {
    asm("fma.rn.f32x2 %0, %1, %2, %3;" : "=l"(d) : "l"(a), "l"(b), "l"(d));
}
__device__ __forceinline__ ull pack2(float x) {
    ull r; asm("mov.b64 %0, {%1, %1};" : "=l"(r) : "f"(x)); return r;
}
__device__ __forceinline__ void unpack2(ull v, float& lo, float& hi) {
    asm("mov.b64 {%0, %1}, %2;" : "=f"(lo), "=f"(hi) : "l"(v));
}
__device__ __forceinline__ float totf32(float x) {
    float r; asm("cvt.rna.tf32.f32 %0, %1;" : "=f"(r) : "f"(x)); return r;
}
__device__ __forceinline__ float trunc_tf32(float x) {
    return __uint_as_float(__float_as_uint(x) & 0xffffe000u);
}
__device__ __forceinline__ uint32_t smem_u32(const void* p) {
    uint32_t a;
    asm("{ .reg .u64 t; cvta.to.shared.u64 t, %1; cvt.u32.u64 %0, t; }" : "=r"(a) : "l"(p));
    return a;
}
__device__ __forceinline__ void cp16(uint32_t dst, const void* src) {
    asm volatile("cp.async.cg.shared.global [%0], [%1], 16;" :: "r"(dst), "l"(src));
}
#define CP_COMMIT() asm volatile("cp.async.commit_group;" ::: "memory")
#define CP_WAIT0()  asm volatile("cp.async.wait_group 0;" ::: "memory")

union F4U { float4 f; ull u[2]; };

__device__ __forceinline__ void mma_tf32(float* d,
    uint32_t a0, uint32_t a1, uint32_t a2, uint32_t a3,
    uint32_t b0, uint32_t b1)
{
    asm volatile(
        "mma.sync.aligned.m16n8k8.row.col.f32.tf32.tf32.f32 "
        "{%0,%1,%2,%3}, {%4,%5,%6,%7}, {%8,%9}, {%0,%1,%2,%3};"
        : "+f"(d[0]), "+f"(d[1]), "+f"(d[2]), "+f"(d[3])
        : "r"(a0), "r"(a1), "r"(a2), "r"(a3), "r"(b0), "r"(b1));
}

// ============ K0a: pack adj into bitmask ============
__global__ __launch_bounds__(256) void k_pack(const int* __restrict__ adj,
                                              uint32_t* __restrict__ bits)
{
    int gid = blockIdx.x * 256 + threadIdx.x;
    const int4* p = reinterpret_cast<const int4*>(adj) + (size_t)gid * 8;
    uint32_t m = 0;
#pragma unroll
    for (int k = 0; k < 8; ++k) {
        int4 v = p[k];
        m |= (v.x > 0 ? 1u : 0u) << (k * 4 + 0);
        m |= (v.y > 0 ? 1u : 0u) << (k * 4 + 1);
        m |= (v.z > 0 ? 1u : 0u) << (k * 4 + 2);
        m |= (v.w > 0 ? 1u : 0u) << (k * 4 + 3);
    }
    bits[gid] = m;
}

// ============ K0b: transpose+round weights for mma B operands ============
__global__ __launch_bounds__(256) void k_prepT(const float* __restrict__ Wout,
                                               const float* __restrict__ Wc,
                                               float* __restrict__ WoutT,
                                               float* __restrict__ WcT)
{
    int idx = blockIdx.x * 256 + threadIdx.x;
    if (idx < 128 * 384) {
        int f = idx / 384, k = idx % 384;
        WoutT[idx] = totf32(Wout[(size_t)k * 128 + f]);
    } else {
        int j = idx - 128 * 384;
        if (j < 256 * 128) {
            int c = j / 128, k = j % 128;
            WcT[j] = totf32(Wc[(size_t)k * 256 + c]);
        }
    }
}

// ============ K1: blocked GEMM Wh = X @ W (fused src/dst); stores WhT tf32 ============
template<int FIN, int TK>
__global__ __launch_bounds__(256) void k_proj(
    const float* __restrict__ X, int ldx,
    const float* __restrict__ Wbase, const float* __restrict__ abase,
    float* __restrict__ WhTout, float* __restrict__ srcout, float* __restrict__ dstout)
{
    __shared__ __align__(16) float WtS[TK][128];
    __shared__ __align__(16) float htT[TK][68];
    __shared__ float aS[256];

    const int l   = blockIdx.z;
    const float* W = Wbase + (size_t)l * FIN * 128;
    const float* a = abase + l * 256;
    float* srcp = srcout + (size_t)l * R;
    float* dstp = dstout + (size_t)l * R;

    const int r0  = blockIdx.y * 512 + blockIdx.x * 64;
    const int tid = threadIdx.x;
    const int fg  = tid & 31;
    const int ig  = tid >> 5;

    aS[tid] = a[tid];

    ull acc2[4][4];
#pragma unroll
    for (int rp = 0; rp < 4; ++rp)
#pragma unroll
        for (int c = 0; c < 4; ++c) acc2[rp][c] = 0ull;

    for (int k0 = 0; k0 < FIN; k0 += TK) {
        __syncthreads();
        for (int e = tid; e < TK * 32; e += 256) {
            int k = e >> 5, c = e & 31;
            *reinterpret_cast<float4*>(&WtS[k][c * 4]) =
                *reinterpret_cast<const float4*>(&W[(size_t)(k0 + k) * 128 + c * 4]);
        }
        for (int e = tid; e < 64 * TK; e += 256) {
            int ii = e / TK, k = e - ii * TK;
            htT[k][ii] = X[(size_t)(r0 + ii) * ldx + k0 + k];
        }
        __syncthreads();

#pragma unroll 8
        for (int k = 0; k < TK; ++k) {
            float4 w = *reinterpret_cast<const float4*>(&WtS[k][fg * 4]);
            ull w0 = pack2(w.x), w1 = pack2(w.y), w2 = pack2(w.z), w3 = pack2(w.w);
            F4U p0, p1;
            p0.f = *reinterpret_cast<const float4*>(&htT[k][ig * 8]);
            p1.f = *reinterpret_cast<const float4*>(&htT[k][ig * 8 + 4]);
            ull pr[4] = {p0.u[0], p0.u[1], p1.u[0], p1.u[1]};
#pragma unroll
            for (int rp = 0; rp < 4; ++rp) {
                fma2(acc2[rp][0], pr[rp], w0);
                fma2(acc2[rp][1], pr[rp], w1);
                fma2(acc2[rp][2], pr[rp], w2);
                fma2(acc2[rp][3], pr[rp], w3);
            }
        }
    }

    float val[8][4];
#pragma unroll
    for (int rp = 0; rp < 4; ++rp)
#pragma unroll
        for (int c = 0; c < 4; ++c)
            unpack2(acc2[rp][c], val[2 * rp][c], val[2 * rp + 1][c]);

    {
        float* WT = WhTout + (size_t)l * R * 128 + (size_t)blockIdx.y * 128 * 512;
        const int il0 = blockIdx.x * 64 + ig * 8;
#pragma unroll
        for (int c = 0; c < 4; ++c) {
            int f = fg * 4 + c;
            float4 lo = make_float4(totf32(val[0][c]), totf32(val[1][c]),
                                    totf32(val[2][c]), totf32(val[3][c]));
            float4 hi = make_float4(totf32(val[4][c]), totf32(val[5][c]),
                                    totf32(val[6][c]), totf32(val[7][c]));
            *reinterpret_cast<float4*>(&WT[(size_t)f * 512 + il0])     = lo;
            *reinterpret_cast<float4*>(&WT[(size_t)f * 512 + il0 + 4]) = hi;
        }
    }

    float a1v[4], a2v[4];
#pragma unroll
    for (int c = 0; c < 4; ++c) { a1v[c] = aS[fg * 4 + c]; a2v[c] = aS[128 + fg * 4 + c]; }

#pragma unroll
    for (int rr = 0; rr < 8; ++rr) {
        int i = r0 + ig * 8 + rr;
        float v1 = val[rr][0] * a1v[0] + val[rr][1] * a1v[1] + val[rr][2] * a1v[2] + val[rr][3] * a1v[3];
        float v2 = val[rr][0] * a2v[0] + val[rr][1] * a2v[1] + val[rr][2] * a2v[2] + val[rr][3] * a2v[3];
#pragma unroll
        for (int o2 = 16; o2; o2 >>= 1) {
            v1 += __shfl_xor_sync(0xffffffffu, v1, o2);
            v2 += __shfl_xor_sync(0xffffffffu, v2, o2);
        }
        if (fg == 0) { srcp[i] = v1; dstp[i] = v2; }
    }
}

// ============ K2: generic pipelined mma.sync tf32 GEMM (128 rows x 128 cols) ============
// EPI 0: proj-out epilogue (fused src/dst, transposed WhT store)
// EPI 1: final epilogue (bias + lrelu -> out)
constexpr int PLD = 36;
constexpr int TILE_F = 128 * PLD;                 // 4608 floats per buffer
constexpr int GEMM_SMEM_BYTES = 4 * TILE_F * 4;   // XS[2] + WS[2] = 73728 B

template<int K, int LDX, int EPI>
__global__ __launch_bounds__(256, 2) void k_mma(
    const float* __restrict__ X, const float* __restrict__ WT,
    const float* __restrict__ vec,
    float* __restrict__ O,
    float* __restrict__ srcp, float* __restrict__ dstp)
{
    extern __shared__ __align__(16) float dyn[];
    float* XS = dyn;                 // [2][128][PLD]
    float* WS = dyn + 2 * TILE_F;    // [2][128][PLD]
    __shared__ float vS[256];
    __shared__ float2 sred[128][2];

    const uint32_t xs_base = smem_u32(XS);
    const uint32_t ws_base = smem_u32(WS);

    const int r0   = blockIdx.x * 128;
    const int col0 = blockIdx.y * 128;
    const int tid  = threadIdx.x;
    const int w    = tid >> 5;
    const int lane = tid & 31;

    const float* WTb = WT + (size_t)col0 * K;

    if (EPI == 0) vS[tid] = vec[tid];
    else if (tid < 128) vS[tid] = vec[col0 + tid];

    const int wm = w & 3;
    const int wn = w >> 2;
    const int g  = lane >> 2;
    const int q  = lane & 3;

    const int sr = tid >> 3, c4 = tid & 7;

    float dacc[2][8][4];
#pragma unroll
    for (int mf = 0; mf < 2; ++mf)
#pragma unroll
        for (int nf = 0; nf < 8; ++nf)
#pragma unroll
            for (int c = 0; c < 4; ++c) dacc[mf][nf][c] = 0.f;

    // prologue: stage tile 0
#pragma unroll
    for (int k = 0; k < 4; ++k) {
        int row = sr + k * 32;
        cp16(xs_base + (uint32_t)(row * PLD + c4 * 4) * 4,
             X + (size_t)(r0 + row) * LDX + c4 * 4);
        cp16(ws_base + (uint32_t)(row * PLD + c4 * 4) * 4,
             WTb + (size_t)row * K + c4 * 4);
    }
    CP_COMMIT();
    CP_WAIT0();
    __syncthreads();

    constexpr int NT = K / 32;
#pragma unroll 1
    for (int t = 0; t < NT; ++t) {
        const int cur = t & 1, nxt = cur ^ 1;
        if (t < NT - 1) {
            const int tj1 = (t + 1) * 32;
#pragma unroll
            for (int k = 0; k < 4; ++k) {
                int row = sr + k * 32;
                cp16(xs_base + (uint32_t)(nxt * TILE_F + row * PLD + c4 * 4) * 4,
                     X + (size_t)(r0 + row) * LDX + tj1 + c4 * 4);
                cp16(ws_base + (uint32_t)(nxt * TILE_F + row * PLD + c4 * 4) * 4,
                     WTb + (size_t)row * K + tj1 + c4 * 4);
            }
            CP_COMMIT();
        }

        const uint32_t* XSu = reinterpret_cast<const uint32_t*>(XS + cur * TILE_F);
        const uint32_t* WSu = reinterpret_cast<const uint32_t*>(WS + cur * TILE_F);
#pragma unroll
        for (int kk = 0; kk < 32; kk += 8) {
            uint32_t bf0[8], bf1[8];
#pragma unroll
            for (int nf = 0; nf < 8; ++nf) {
                int f = wn * 64 + nf * 8 + g;
                bf0[nf] = WSu[f * PLD + kk + q];
                bf1[nf] = WSu[f * PLD + kk + q + 4];
            }
#pragma unroll
            for (int mf = 0; mf < 2; ++mf) {
                int r_ = wm * 32 + mf * 16 + g;
                uint32_t a0 = XSu[r_ * PLD + kk + q];
                uint32_t a1 = XSu[(r_ + 8) * PLD + kk + q];
                uint32_t a2 = XSu[r_ * PLD + kk + q + 4];
                uint32_t a3 = XSu[(r_ + 8) * PLD + kk + q + 4];
#pragma unroll
                for (int nf = 0; nf < 8; ++nf)
                    mma_tf32(dacc[mf][nf], a0, a1, a2, a3, bf0[nf], bf1[nf]);
            }
        }

        if (t < NT - 1) CP_WAIT0();
        __syncthreads();
    }

    if (EPI == 1) {
        // bias + lrelu -> out [R][256]
#pragma unroll
        for (int mf = 0; mf < 2; ++mf) {
#pragma unroll
            for (int h = 0; h < 2; ++h) {
                int rl = wm * 32 + mf * 16 + g + h * 8;
                float* orow = O + (size_t)(r0 + rl) * 256 + col0 + wn * 64;
#pragma unroll
                for (int nf = 0; nf < 8; ++nf) {
                    int c0 = nf * 8 + 2 * q;
                    float2 v;
                    v.x = lrelu02(dacc[mf][nf][2 * h]     + vS[wn * 64 + c0]);
                    v.y = lrelu02(dacc[mf][nf][2 * h + 1] + vS[wn * 64 + c0 + 1]);
                    *reinterpret_cast<float2*>(&orow[c0]) = v;
                }
            }
        }
        return;
    }

    // ---- EPI 0: fused src/dst reduction ----
#pragma unroll
    for (int mf = 0; mf < 2; ++mf) {
#pragma unroll
        for (int h = 0; h < 2; ++h) {
            int rl = wm * 32 + mf * 16 + g + h * 8;
            float s1 = 0.f, s2 = 0.f;
#pragma unroll
            for (int nf = 0; nf < 8; ++nf) {
                int c0 = wn * 64 + nf * 8 + 2 * q;
                float v0 = dacc[mf][nf][2 * h], v1 = dacc[mf][nf][2 * h + 1];
                s1 += v0 * vS[c0] + v1 * vS[c0 + 1];
                s2 += v0 * vS[128 + c0] + v1 * vS[128 + c0 + 1];
            }
            s1 += __shfl_xor_sync(0xffffffffu, s1, 1);
            s1 += __shfl_xor_sync(0xffffffffu, s1, 2);
            s2 += __shfl_xor_sync(0xffffffffu, s2, 1);
            s2 += __shfl_xor_sync(0xffffffffu, s2, 2);
            if (q == 0) sred[rl][wn] = make_float2(s1, s2);
        }
    }
    __syncthreads();
    if (tid < 128) {
        float2 u = sred[tid][0], v = sred[tid][1];
        srcp[r0 + tid] = u.x + v.x;
        dstp[r0 + tid] = u.y + v.y;
    }

    // ---- dump fragments to smem, then transposed tf32 store to WhT ----
    float* WhS = dyn;   // reuse: 128 x 132 = 67584 B < 73728 B
#pragma unroll
    for (int mf = 0; mf < 2; ++mf) {
#pragma unroll
        for (int h = 0; h < 2; ++h) {
            int rl = wm * 32 + mf * 16 + g + h * 8;
#pragma unroll
            for (int nf = 0; nf < 8; ++nf) {
                int c0 = wn * 64 + nf * 8 + 2 * q;
                *reinterpret_cast<float2*>(&WhS[rl * 132 + c0]) =
                    make_float2(dacc[mf][nf][2 * h], dacc[mf][nf][2 * h + 1]);
            }
        }
    }
    __syncthreads();
    {
        const int f = tid >> 1, ih = tid & 1;
        float* WTo = O + (size_t)(r0 >> 9) * (128 * 512)
                       + (size_t)f * 512 + (r0 & 511) + ih * 64;
#pragma unroll
        for (int v = 0; v < 16; ++v) {
            int i = ih * 64 + v * 4;
            float4 o = make_float4(totf32(WhS[(i + 0) * 132 + f]),
                                   totf32(WhS[(i + 1) * 132 + f]),
                                   totf32(WhS[(i + 2) * 132 + f]),
                                   totf32(WhS[(i + 3) * 132 + f]));
            *reinterpret_cast<float4*>(&WTo[v * 4]) = o;
        }
    }
}

// ============ K3: pipelined mma.sync tf32 fused softmax + aggregate ============
constexpr int WS_OFF  = 0;
constexpr int PS_OFF  = WS_OFF + 2 * 128 * PLD;
constexpr int DST_OFF = PS_OFF + 2 * 128 * PLD;
constexpr int FS_OFF  = DST_OFF + 512;
constexpr int SRC_OFF = FS_OFF + 1024;
constexpr int E1_OFF  = SRC_OFF + 128;
constexpr int E2_OFF  = E1_OFF + 128;
constexpr int RZ_OFF  = E2_OFF + 128;
constexpr int ZP_OFF  = RZ_OFF + 128;
constexpr int RED_OFF = ZP_OFF + 1024;
constexpr int MD_OFF  = RED_OFF + 8;
constexpr int AGG_SMEM_BYTES = (MD_OFF + 4) * 4;

__global__ __launch_bounds__(256, 2) void k_agg_mma(
    const uint32_t* __restrict__ bits, const float* __restrict__ WhT0,
    const float* __restrict__ src0, const float* __restrict__ dst0,
    float* __restrict__ outp, int ld)
{
    extern __shared__ __align__(16) float dyn[];
    float* WSf  = dyn + WS_OFF;
    float* PSf  = dyn + PS_OFF;
    float* dstS = dyn + DST_OFF;
    float2* FS2 = reinterpret_cast<float2*>(dyn + FS_OFF);
    float* srcS = dyn + SRC_OFF;
    float* e1S  = dyn + E1_OFF;
    float* e2S  = dyn + E2_OFF;
    float* rZS  = dyn + RZ_OFF;
    float* zpartS = dyn + ZP_OFF;
    float* red  = dyn + RED_OFF;
    float* mdstS = dyn + MD_OFF;

    const uint32_t ws_base = smem_u32(WSf);

    const int l    = blockIdx.z;
    const int b    = blockIdx.y;
    const int i0   = blockIdx.x * 128;
    const int tid  = threadIdx.x;
    const int w    = tid >> 5;
    const int lane = tid & 31;
    const int col0 = l * 128;

    const float* WhTl = WhT0 + (size_t)l * R * 128 + (size_t)b * 128 * 512;
    const float* srcp = src0 + (size_t)l * R;
    const float* dstp = dst0 + (size_t)l * R;
    const uint32_t* bitsb = bits + ((size_t)(b << 9) + i0) * 16;

    for (int k = tid; k < 512; k += 256) dstS[k] = dstp[(b << 9) + k];
    if (tid < 128) srcS[tid] = srcp[(b << 9) + i0 + tid];
    __syncthreads();

    {
        float v = fmaxf(dstS[tid], dstS[tid + 256]);
#pragma unroll
        for (int o = 16; o; o >>= 1) v = fmaxf(v, __shfl_xor_sync(0xffffffffu, v, o));
        if (lane == 0) red[w] = v;
        __syncthreads();
        if (tid == 0) {
            float m = red[0];
#pragma unroll
            for (int k = 1; k < 8; ++k) m = fmaxf(m, red[k]);
            mdstS[0] = m;
        }
        __syncthreads();
    }
    const float mdst = mdstS[0];

    for (int k = tid; k < 512; k += 256) {
        float d = dstS[k] - mdst;
        FS2[k] = make_float2(__expf(d), __expf(0.2f * d));
    }
    if (tid < 128) {
        float t2 = srcS[tid] + mdst;
        float m  = lrelu02(t2);
        e1S[tid] = __expf(t2 - m);
        e2S[tid] = __expf(0.2f * t2 - m);
    }
    __syncthreads();

    const int wm = w & 3;
    const int wn = w >> 2;
    const int g  = lane >> 2;
    const int q  = lane & 3;

    const int srow = tid >> 3;
    const int jq   = tid & 7;

    float dacc[2][8][4];
#pragma unroll
    for (int mf = 0; mf < 2; ++mf)
#pragma unroll
        for (int nf = 0; nf < 8; ++nf)
#pragma unroll
            for (int c = 0; c < 4; ++c) dacc[mf][nf][c] = 0.f;

    float zl[4] = {0.f, 0.f, 0.f, 0.f};

    const int sf[4] = { (tid + 0) >> 3, (tid + 256) >> 3, (tid + 512) >> 3, (tid + 768) >> 3 };
    const int sc4   = jq;

#pragma unroll
    for (int k = 0; k < 4; ++k)
        cp16(ws_base + (uint32_t)(sf[k] * PLD + sc4 * 4) * 4,
             WhTl + (size_t)sf[k] * 512 + sc4 * 4);
    CP_COMMIT();
    {
        float4 d4 = *reinterpret_cast<const float4*>(&dstS[jq * 4]);
        const float4* fsp = reinterpret_cast<const float4*>(&FS2[jq * 4]);
        float4 f01 = fsp[0], f23 = fsp[1];
#pragma unroll
        for (int qq = 0; qq < 4; ++qq) {
            int r_ = srow + qq * 32;
            uint32_t m = bitsb[r_ * 16 + 0];
            float sv = srcS[r_], E1 = e1S[r_], E2 = e2S[r_];
            float p0, p1, p2, p3;
            { float s = sv + d4.x; bool gg = s > 0.f; p0 = (gg ? E1 : E2) * (gg ? f01.x : f01.y); }
            { float s = sv + d4.y; bool gg = s > 0.f; p1 = (gg ? E1 : E2) * (gg ? f01.z : f01.w); }
            { float s = sv + d4.z; bool gg = s > 0.f; p2 = (gg ? E1 : E2) * (gg ? f23.x : f23.y); }
            { float s = sv + d4.w; bool gg = s > 0.f; p3 = (gg ? E1 : E2) * (gg ? f23.z : f23.w); }
            p0 = ((m >> (jq * 4 + 0)) & 1u) ? trunc_tf32(p0) : 0.f;
            p1 = ((m >> (jq * 4 + 1)) & 1u) ? trunc_tf32(p1) : 0.f;
            p2 = ((m >> (jq * 4 + 2)) & 1u) ? trunc_tf32(p2) : 0.f;
            p3 = ((m >> (jq * 4 + 3)) & 1u) ? trunc_tf32(p3) : 0.f;
            zl[qq] += (p0 + p1) + (p2 + p3);
            *reinterpret_cast<float4*>(&PSf[r_ * PLD + jq * 4]) =
                make_float4(p0, p1, p2, p3);
        }
    }
    CP_WAIT0();
    __syncthreads();

#pragma unroll 1
    for (int t = 0; t < 16; ++t) {
        const int cur = t & 1, nxt = cur ^ 1;

        if (t < 15) {
            const int tj1 = (t + 1) * 32;
#pragma unroll
            for (int k = 0; k < 4; ++k)
                cp16(ws_base + (uint32_t)(nxt * TILE_F + sf[k] * PLD + sc4 * 4) * 4,
                     WhTl + (size_t)sf[k] * 512 + tj1 + sc4 * 4);
            CP_COMMIT();

            float4 d4 = *reinterpret_cast<const float4*>(&dstS[tj1 + jq * 4]);
            const float4* fsp = reinterpret_cast<const float4*>(&FS2[tj1 + jq * 4]);
            float4 f01 = fsp[0], f23 = fsp[1];
            float* PSb = PSf + nxt * TILE_F;
#pragma unroll
            for (int qq = 0; qq < 4; ++qq) {
                int r_ = srow + qq * 32;
                uint32_t m = bitsb[r_ * 16 + (t + 1)];
                float sv = srcS[r_], E1 = e1S[r_], E2 = e2S[r_];
                float p0, p1, p2, p3;
                { float s = sv + d4.x; bool gg = s > 0.f; p0 = (gg ? E1 : E2) * (gg ? f01.x : f01.y); }
                { float s = sv + d4.y; bool gg = s > 0.f; p1 = (gg ? E1 : E2) * (gg ? f01.z : f01.w); }
                { float s = sv + d4.z; bool gg = s > 0.f; p2 = (gg ? E1 : E2) * (gg ? f23.x : f23.y); }
                { float s = sv + d4.w; bool gg = s > 0.f; p3 = (gg ? E1 : E2) * (gg ? f23.z : f23.w); }
                p0 = ((m >> (jq * 4 + 0)) & 1u) ? trunc_tf32(p0) : 0.f;
                p1 = ((m >> (jq * 4 + 1)) & 1u) ? trunc_tf32(p1) : 0.f;
                p2 = ((m >> (jq * 4 + 2)) & 1u) ? trunc_tf32(p2) : 0.f;
                p3 = ((m >> (jq * 4 + 3)) & 1u) ? trunc_tf32(p3) : 0.f;
                zl[qq] += (p0 + p1) + (p2 + p3);
                *reinterpret_cast<float4*>(&PSb[r_ * PLD + jq * 4]) =
                    make_float4(p0, p1, p2, p3);
            }
        }

        const uint32_t* PSu = reinterpret_cast<const uint32_t*>(PSf + cur * TILE_F);
        const uint32_t* WSu = reinterpret_cast<const uint32_t*>(WSf + cur * TILE_F);
#pragma unroll
        for (int kk = 0; kk < 32; kk += 8) {
            uint32_t bf0[8], bf1[8];
#pragma unroll
            for (int nf = 0; nf < 8; ++nf) {
                int f = wn * 64 + nf * 8 + g;
                bf0[nf] = WSu[f * PLD + kk + q];
                bf1[nf] = WSu[f * PLD + kk + q + 4];
            }
#pragma unroll
            for (int mf = 0; mf < 2; ++mf) {
                int r_ = wm * 32 + mf * 16 + g;
                uint32_t a0 = PSu[r_ * PLD + kk + q];
                uint32_t a1 = PSu[(r_ + 8) * PLD + kk + q];
                uint32_t a2 = PSu[r_ * PLD + kk + q + 4];
                uint32_t a3 = PSu[(r_ + 8) * PLD + kk + q + 4];
#pragma unroll
                for (int nf = 0; nf < 8; ++nf)
                    mma_tf32(dacc[mf][nf], a0, a1, a2, a3, bf0[nf], bf1[nf]);
            }
        }

        if (t < 15) CP_WAIT0();
        __syncthreads();
    }

#pragma unroll
    for (int qq = 0; qq < 4; ++qq) zpartS[(srow + qq * 32) * 8 + jq] = zl[qq];
    __syncthreads();
    if (tid < 128) {
        float z = 0.f;
#pragma unroll
        for (int k = 0; k < 8; ++k) z += zpartS[tid * 8 + k];
        rZS[tid] = 1.f / z;
    }
    __syncthreads();

    // epilogue: normalize, elu, tf32-round (so downstream cp.async A-operand is exact)
#pragma unroll
    for (int mf = 0; mf < 2; ++mf) {
#pragma unroll
        for (int h = 0; h < 2; ++h) {
            int rl = wm * 32 + mf * 16 + g + h * 8;
            float rz = rZS[rl];
            float* orow = outp + ((size_t)(b << 9) + i0 + rl) * ld + col0 + wn * 64;
#pragma unroll
            for (int nf = 0; nf < 8; ++nf) {
                float2 v;
                v.x = totf32(elu1(dacc[mf][nf][2 * h]     * rz));
                v.y = totf32(elu1(dacc[mf][nf][2 * h + 1] * rz));
                *reinterpret_cast<float2*>(&orow[nf * 8 + 2 * q]) = v;
            }
        }
    }
}

// ---------------- launch ----------------
extern "C" void kernel_launch(void* const* d_in, const int* in_sizes, int n_in,
                              void* d_out, int out_size)
{
    (void)in_sizes; (void)n_in; (void)out_size;
    const float* compound = (const float*)d_in[0];   // [64,512,34]
    const int*   adj      = (const int*)d_in[1];     // [64,512,512]
    const float* Wst      = (const float*)d_in[2];   // [3,34,128]
    const float* ast      = (const float*)d_in[3];   // [3,256,1]
    const float* Wout     = (const float*)d_in[4];   // [384,128]
    const float* aout     = (const float*)d_in[5];   // [256,1]
    const float* Wc       = (const float*)d_in[6];   // [128,256]
    const float* bc       = (const float*)d_in[7];   // [256]
    float* out = (float*)d_out;                      // [64,512,256]

    float* g_WhT_p;   cudaGetSymbolAddress((void**)&g_WhT_p,  g_WhT);
    float* g_heads_p; cudaGetSymbolAddress((void**)&g_heads_p, g_heads);
    float* g_x_p;     cudaGetSymbolAddress((void**)&g_x_p,    g_x);
    float* g_src_p;   cudaGetSymbolAddress((void**)&g_src_p,  g_src3);
    float* g_dst_p;   cudaGetSymbolAddress((void**)&g_dst_p,  g_dst3);
    uint32_t* g_bits_p; cudaGetSymbolAddress((void**)&g_bits_p, g_adjbits);
    float* g_WoutT_p; cudaGetSymbolAddress((void**)&g_WoutT_p, g_WoutT);
    float* g_WcT_p;   cudaGetSymbolAddress((void**)&g_WcT_p,   g_WcT);

    cudaFuncSetAttribute(k_agg_mma, cudaFuncAttributeMaxDynamicSharedMemorySize,
                         AGG_SMEM_BYTES);
    cudaFuncSetAttribute(k_mma<384, 384, 0>,
                         cudaFuncAttributeMaxDynamicSharedMemorySize, GEMM_SMEM_BYTES);
    cudaFuncSetAttribute(k_mma<128, 128, 1>,
                         cudaFuncAttributeMaxDynamicSharedMemorySize, GEMM_SMEM_BYTES);

    k_pack<<<(R * 16) / 256, 256>>>(adj, g_bits_p);
    k_prepT<<<(128 * 384 + 256 * 128 + 255) / 256, 256>>>(Wout, Wc, g_WoutT_p, g_WcT_p);

    // 3 input-layer projections (CUDA-core path, small K)
    k_proj<34, 34><<<dim3(N / 64, B, 3), 256>>>(
        compound, 34, Wst, ast, g_WhT_p, g_src_p, g_dst_p);

    // 3 head aggregations
    k_agg_mma<<<dim3(N / 128, B, 3), 256, AGG_SMEM_BYTES>>>(
        g_bits_p, g_WhT_p, g_src_p, g_dst_p, g_heads_p, 384);

    // out-layer projection: mma GEMM with fused src/dst + transposed WhT store
    k_mma<384, 384, 0><<<dim3(R / 128, 1), 256, GEMM_SMEM_BYTES>>>(
        g_heads_p, g_WoutT_p, aout,
        g_WhT_p + (size_t)3 * R * 128, g_src_p + (size_t)3 * R, g_dst_p + (size_t)3 * R);

    // out-layer aggregation
    k_agg_mma<<<dim3(N / 128, B, 1), 256, AGG_SMEM_BYTES>>>(
        g_bits_p, g_WhT_p + (size_t)3 * R * 128,
        g_src_p + (size_t)3 * R, g_dst_p + (size_t)3 * R, g_x_p, 128);

    // final dense layer: mma GEMM, bias + lrelu
    k_mma<128, 128, 1><<<dim3(R / 128, 2), 256, GEMM_SMEM_BYTES>>>(
        g_x_p, g_WcT_p, bc, out, nullptr, nullptr);
}

// round 12
// speedup vs baseline: 5.1267x; 1.0074x over previous
#include <cuda_runtime.h>
#include <cstdint>

typedef unsigned long long ull;

// ---------------- problem constants ----------------
constexpr int B = 64;
constexpr int N = 512;
constexpr int R = B * N;      // 32768 rows

// ---------------- device scratch ----------------
__device__ float g_WhT[(size_t)4 * R * 128];   // per layer, per batch, [f][j], tf32
__device__ float g_heads[(size_t)R * 384];     // tf32-rounded values (elu out)
__device__ float g_x[(size_t)R * 128];         // tf32-rounded values
__device__ float g_src3[4 * R];
__device__ float g_dst3[4 * R];
__device__ uint32_t g_adjbits[(size_t)R * 16];
__device__ float g_WoutT[128 * 384];           // tf32-rounded, [f][k]
__device__ float g_WcT[256 * 128];             // tf32-rounded, [c][k]

__device__ __forceinline__ float lrelu02(float x) { return x > 0.f ? x : 0.2f * x; }
__device__ __forceinline__ float elu1(float x)    { return x > 0.f ? x : expm1f(x); }

__device__ __forceinline__ void fma2(ull& d, ull a, ull b) {
    asm("fma.rn.f32x2 %0, %1, %2, %3;" : "=l"(d) : "l"(a), "l"(b), "l"(d));
}
__device__ __forceinline__ ull pack2(float x) {
    ull r; asm("mov.b64 %0, {%1, %1};" : "=l"(r) : "f"(x)); return r;
}
__device__ __forceinline__ void unpack2(ull v, float& lo, float& hi) {
    asm("mov.b64 {%0, %1}, %2;" : "=f"(lo), "=f"(hi) : "l"(v));
}
__device__ __forceinline__ float totf32(float x) {
    float r; asm("cvt.rna.tf32.f32 %0, %1;" : "=f"(r) : "f"(x)); return r;
}
__device__ __forceinline__ float trunc_tf32(float x) {
    return __uint_as_float(__float_as_uint(x) & 0xffffe000u);
}
__device__ __forceinline__ uint32_t smem_u32(const void* p) {
    uint32_t a;
    asm("{ .reg .u64 t; cvta.to.shared.u64 t, %1; cvt.u32.u64 %0, t; }" : "=r"(a) : "l"(p));
    return a;
}
__device__ __forceinline__ void cp16(uint32_t dst, const void* src) {
    asm volatile("cp.async.cg.shared.global [%0], [%1], 16;" :: "r"(dst), "l"(src));
}
#define CP_COMMIT() asm volatile("cp.async.commit_group;" ::: "memory")
#define CP_WAIT0()  asm volatile("cp.async.wait_group 0;" ::: "memory")

// XOR swizzle: element (row, col) of a [128][32] tile lives at
// row*32 + ((col>>2 ^ (row&7))<<2 | (col&3)).  swz4 gives float4-group offset.
__device__ __forceinline__ int swz4(int row, int c4) {
    return ((c4 ^ (row & 7)) << 2);
}

union F4U { float4 f; ull u[2]; };

__device__ __forceinline__ void mma_tf32(float* d,
    uint32_t a0, uint32_t a1, uint32_t a2, uint32_t a3,
    uint32_t b0, uint32_t b1)
{
    asm volatile(
        "mma.sync.aligned.m16n8k8.row.col.f32.tf32.tf32.f32 "
        "{%0,%1,%2,%3}, {%4,%5,%6,%7}, {%8,%9}, {%0,%1,%2,%3};"
        : "+f"(d[0]), "+f"(d[1]), "+f"(d[2]), "+f"(d[3])
        : "r"(a0), "r"(a1), "r"(a2), "r"(a3), "r"(b0), "r"(b1));
}

// ============ K0a: pack adj into bitmask ============
__global__ __launch_bounds__(256) void k_pack(const int* __restrict__ adj,
                                              uint32_t* __restrict__ bits)
{
    int gid = blockIdx.x * 256 + threadIdx.x;
    const int4* p = reinterpret_cast<const int4*>(adj) + (size_t)gid * 8;
    uint32_t m = 0;
#pragma unroll
    for (int k = 0; k < 8; ++k) {
        int4 v = p[k];
        m |= (v.x > 0 ? 1u : 0u) << (k * 4 + 0);
        m |= (v.y > 0 ? 1u : 0u) << (k * 4 + 1);
        m |= (v.z > 0 ? 1u : 0u) << (k * 4 + 2);
        m |= (v.w > 0 ? 1u : 0u) << (k * 4 + 3);
    }
    bits[gid] = m;
}

// ============ K0b: transpose+round weights ============
__global__ __launch_bounds__(256) void k_prepT(const float* __restrict__ Wout,
                                               const float* __restrict__ Wc,
                                               float* __restrict__ WoutT,
                                               float* __restrict__ WcT)
{
    int idx = blockIdx.x * 256 + threadIdx.x;
    if (idx < 128 * 384) {
        int f = idx / 384, k = idx % 384;
        WoutT[idx] = totf32(Wout[(size_t)k * 128 + f]);
    } else {
        int j = idx - 128 * 384;
        if (j < 256 * 128) {
            int c = j / 128, k = j % 128;
            WcT[j] = totf32(Wc[(size_t)k * 256 + c]);
        }
    }
}

// ============ K1: blocked GEMM Wh = X @ W (fused src/dst); stores WhT tf32 ============
template<int FIN, int TK>
__global__ __launch_bounds__(256) void k_proj(
    const float* __restrict__ X, int ldx,
    const float* __restrict__ Wbase, const float* __restrict__ abase,
    float* __restrict__ WhTout, float* __restrict__ srcout, float* __restrict__ dstout)
{
    __shared__ __align__(16) float WtS[TK][128];
    __shared__ __align__(16) float htT[TK][68];
    __shared__ float aS[256];

    const int l   = blockIdx.z;
    const float* W = Wbase + (size_t)l * FIN * 128;
    const float* a = abase + l * 256;
    float* srcp = srcout + (size_t)l * R;
    float* dstp = dstout + (size_t)l * R;

    const int r0  = blockIdx.y * 512 + blockIdx.x * 64;
    const int tid = threadIdx.x;
    const int fg  = tid & 31;
    const int ig  = tid >> 5;

    aS[tid] = a[tid];

    ull acc2[4][4];
#pragma unroll
    for (int rp = 0; rp < 4; ++rp)
#pragma unroll
        for (int c = 0; c < 4; ++c) acc2[rp][c] = 0ull;

    for (int k0 = 0; k0 < FIN; k0 += TK) {
        __syncthreads();
        for (int e = tid; e < TK * 32; e += 256) {
            int k = e >> 5, c = e & 31;
            *reinterpret_cast<float4*>(&WtS[k][c * 4]) =
                *reinterpret_cast<const float4*>(&W[(size_t)(k0 + k) * 128 + c * 4]);
        }
        for (int e = tid; e < 64 * TK; e += 256) {
            int ii = e / TK, k = e - ii * TK;
            htT[k][ii] = X[(size_t)(r0 + ii) * ldx + k0 + k];
        }
        __syncthreads();

#pragma unroll 8
        for (int k = 0; k < TK; ++k) {
            float4 w = *reinterpret_cast<const float4*>(&WtS[k][fg * 4]);
            ull w0 = pack2(w.x), w1 = pack2(w.y), w2 = pack2(w.z), w3 = pack2(w.w);
            F4U p0, p1;
            p0.f = *reinterpret_cast<const float4*>(&htT[k][ig * 8]);
            p1.f = *reinterpret_cast<const float4*>(&htT[k][ig * 8 + 4]);
            ull pr[4] = {p0.u[0], p0.u[1], p1.u[0], p1.u[1]};
#pragma unroll
            for (int rp = 0; rp < 4; ++rp) {
                fma2(acc2[rp][0], pr[rp], w0);
                fma2(acc2[rp][1], pr[rp], w1);
                fma2(acc2[rp][2], pr[rp], w2);
                fma2(acc2[rp][3], pr[rp], w3);
            }
        }
    }

    float val[8][4];
#pragma unroll
    for (int rp = 0; rp < 4; ++rp)
#pragma unroll
        for (int c = 0; c < 4; ++c)
            unpack2(acc2[rp][c], val[2 * rp][c], val[2 * rp + 1][c]);

    {
        float* WT = WhTout + (size_t)l * R * 128 + (size_t)blockIdx.y * 128 * 512;
        const int il0 = blockIdx.x * 64 + ig * 8;
#pragma unroll
        for (int c = 0; c < 4; ++c) {
            int f = fg * 4 + c;
            float4 lo = make_float4(totf32(val[0][c]), totf32(val[1][c]),
                                    totf32(val[2][c]), totf32(val[3][c]));
            float4 hi = make_float4(totf32(val[4][c]), totf32(val[5][c]),
                                    totf32(val[6][c]), totf32(val[7][c]));
            *reinterpret_cast<float4*>(&WT[(size_t)f * 512 + il0])     = lo;
            *reinterpret_cast<float4*>(&WT[(size_t)f * 512 + il0 + 4]) = hi;
        }
    }

    float a1v[4], a2v[4];
#pragma unroll
    for (int c = 0; c < 4; ++c) { a1v[c] = aS[fg * 4 + c]; a2v[c] = aS[128 + fg * 4 + c]; }

#pragma unroll
    for (int rr = 0; rr < 8; ++rr) {
        int i = r0 + ig * 8 + rr;
        float v1 = val[rr][0] * a1v[0] + val[rr][1] * a1v[1] + val[rr][2] * a1v[2] + val[rr][3] * a1v[3];
        float v2 = val[rr][0] * a2v[0] + val[rr][1] * a2v[1] + val[rr][2] * a2v[2] + val[rr][3] * a2v[3];
#pragma unroll
        for (int o2 = 16; o2; o2 >>= 1) {
            v1 += __shfl_xor_sync(0xffffffffu, v1, o2);
            v2 += __shfl_xor_sync(0xffffffffu, v2, o2);
        }
        if (fg == 0) { srcp[i] = v1; dstp[i] = v2; }
    }
}

// ============ K2: generic pipelined mma.sync tf32 GEMM (swizzled tiles) ============
constexpr int TILE_F = 128 * 32;                   // 4096 floats per buffer
constexpr int GEMM_SMEM_BYTES = 128 * 132 * 4;     // 67584 >= 4*TILE_F*4 = 65536

template<int K, int LDX, int EPI>
__global__ __launch_bounds__(256, 2) void k_mma(
    const float* __restrict__ X, const float* __restrict__ WT,
    const float* __restrict__ vec,
    float* __restrict__ O,
    float* __restrict__ srcp, float* __restrict__ dstp)
{
    extern __shared__ __align__(16) float dyn[];
    float* XS = dyn;                 // [2][128][32] swizzled
    float* WS = dyn + 2 * TILE_F;
    __shared__ float vS[256];
    __shared__ float2 sred[128][2];

    const uint32_t xs_base = smem_u32(XS);
    const uint32_t ws_base = smem_u32(WS);

    const int r0   = blockIdx.x * 128;
    const int col0 = blockIdx.y * 128;
    const int tid  = threadIdx.x;
    const int w    = tid >> 5;
    const int lane = tid & 31;

    const float* WTb = WT + (size_t)col0 * K;

    if (EPI == 0) vS[tid] = vec[tid];
    else if (tid < 128) vS[tid] = vec[col0 + tid];

    const int wm = w & 3;
    const int wn = w >> 2;
    const int g  = lane >> 2;
    const int q  = lane & 3;

    const int sr = tid >> 3, c4 = tid & 7;

    float dacc[2][8][4];
#pragma unroll
    for (int mf = 0; mf < 2; ++mf)
#pragma unroll
        for (int nf = 0; nf < 8; ++nf)
#pragma unroll
            for (int c = 0; c < 4; ++c) dacc[mf][nf][c] = 0.f;

#pragma unroll
    for (int k = 0; k < 4; ++k) {
        int row = sr + k * 32;
        int so = row * 32 + swz4(row, c4);
        cp16(xs_base + (uint32_t)so * 4, X + (size_t)(r0 + row) * LDX + c4 * 4);
        cp16(ws_base + (uint32_t)so * 4, WTb + (size_t)row * K + c4 * 4);
    }
    CP_COMMIT();
    CP_WAIT0();
    __syncthreads();

    constexpr int NT = K / 32;
#pragma unroll 1
    for (int t = 0; t < NT; ++t) {
        const int cur = t & 1, nxt = cur ^ 1;
        if (t < NT - 1) {
            const int tj1 = (t + 1) * 32;
#pragma unroll
            for (int k = 0; k < 4; ++k) {
                int row = sr + k * 32;
                int so = row * 32 + swz4(row, c4);
                cp16(xs_base + (uint32_t)(nxt * TILE_F + so) * 4,
                     X + (size_t)(r0 + row) * LDX + tj1 + c4 * 4);
                cp16(ws_base + (uint32_t)(nxt * TILE_F + so) * 4,
                     WTb + (size_t)row * K + tj1 + c4 * 4);
            }
            CP_COMMIT();
        }

        const uint32_t* XSu = reinterpret_cast<const uint32_t*>(XS + cur * TILE_F);
        const uint32_t* WSu = reinterpret_cast<const uint32_t*>(WS + cur * TILE_F);
#pragma unroll
        for (int kk = 0; kk < 32; kk += 8) {
            const int k4a = kk >> 2, k4b = (kk >> 2) + 1;
            uint32_t bf0[8], bf1[8];
#pragma unroll
            for (int nf = 0; nf < 8; ++nf) {
                int f = wn * 64 + nf * 8 + g;
                bf0[nf] = WSu[f * 32 + ((k4a ^ g) << 2) + q];
                bf1[nf] = WSu[f * 32 + ((k4b ^ g) << 2) + q];
            }
#pragma unroll
            for (int mf = 0; mf < 2; ++mf) {
                int r_ = wm * 32 + mf * 16 + g;
                uint32_t a0 = XSu[r_ * 32 + ((k4a ^ g) << 2) + q];
                uint32_t a1 = XSu[(r_ + 8) * 32 + ((k4a ^ g) << 2) + q];
                uint32_t a2 = XSu[r_ * 32 + ((k4b ^ g) << 2) + q];
                uint32_t a3 = XSu[(r_ + 8) * 32 + ((k4b ^ g) << 2) + q];
#pragma unroll
                for (int nf = 0; nf < 8; ++nf)
                    mma_tf32(dacc[mf][nf], a0, a1, a2, a3, bf0[nf], bf1[nf]);
            }
        }

        if (t < NT - 1) CP_WAIT0();
        __syncthreads();
    }

    if (EPI == 1) {
#pragma unroll
        for (int mf = 0; mf < 2; ++mf) {
#pragma unroll
            for (int h = 0; h < 2; ++h) {
                int rl = wm * 32 + mf * 16 + g + h * 8;
                float* orow = O + (size_t)(r0 + rl) * 256 + col0 + wn * 64;
#pragma unroll
                for (int nf = 0; nf < 8; ++nf) {
                    int c0 = nf * 8 + 2 * q;
                    float2 v;
                    v.x = lrelu02(dacc[mf][nf][2 * h]     + vS[wn * 64 + c0]);
                    v.y = lrelu02(dacc[mf][nf][2 * h + 1] + vS[wn * 64 + c0 + 1]);
                    *reinterpret_cast<float2*>(&orow[c0]) = v;
                }
            }
        }
        return;
    }

    // EPI 0: fused src/dst
#pragma unroll
    for (int mf = 0; mf < 2; ++mf) {
#pragma unroll
        for (int h = 0; h < 2; ++h) {
            int rl = wm * 32 + mf * 16 + g + h * 8;
            float s1 = 0.f, s2 = 0.f;
#pragma unroll
            for (int nf = 0; nf < 8; ++nf) {
                int c0 = wn * 64 + nf * 8 + 2 * q;
                float v0 = dacc[mf][nf][2 * h], v1 = dacc[mf][nf][2 * h + 1];
                s1 += v0 * vS[c0] + v1 * vS[c0 + 1];
                s2 += v0 * vS[128 + c0] + v1 * vS[128 + c0 + 1];
            }
            s1 += __shfl_xor_sync(0xffffffffu, s1, 1);
            s1 += __shfl_xor_sync(0xffffffffu, s1, 2);
            s2 += __shfl_xor_sync(0xffffffffu, s2, 1);
            s2 += __shfl_xor_sync(0xffffffffu, s2, 2);
            if (q == 0) sred[rl][wn] = make_float2(s1, s2);
        }
    }
    __syncthreads();
    if (tid < 128) {
        float2 u = sred[tid][0], v = sred[tid][1];
        srcp[r0 + tid] = u.x + v.x;
        dstp[r0 + tid] = u.y + v.y;
    }

    // dump fragments, transposed tf32 store to WhT
    float* WhS = dyn;   // 128 x 132
#pragma unroll
    for (int mf = 0; mf < 2; ++mf) {
#pragma unroll
        for (int h = 0; h < 2; ++h) {
            int rl = wm * 32 + mf * 16 + g + h * 8;
#pragma unroll
            for (int nf = 0; nf < 8; ++nf) {
                int c0 = wn * 64 + nf * 8 + 2 * q;
                *reinterpret_cast<float2*>(&WhS[rl * 132 + c0]) =
                    make_float2(dacc[mf][nf][2 * h], dacc[mf][nf][2 * h + 1]);
            }
        }
    }
    __syncthreads();
    {
        const int f = tid >> 1, ih = tid & 1;
        float* WTo = O + (size_t)(r0 >> 9) * (128 * 512)
                       + (size_t)f * 512 + (r0 & 511) + ih * 64;
#pragma unroll
        for (int v = 0; v < 16; ++v) {
            int i = ih * 64 + v * 4;
            float4 o = make_float4(totf32(WhS[(i + 0) * 132 + f]),
                                   totf32(WhS[(i + 1) * 132 + f]),
                                   totf32(WhS[(i + 2) * 132 + f]),
                                   totf32(WhS[(i + 3) * 132 + f]));
            *reinterpret_cast<float4*>(&WTo[v * 4]) = o;
        }
    }
}

// ============ K3: pipelined mma.sync tf32 fused softmax + aggregate (swizzled) ============
constexpr int WS_OFF  = 0;
constexpr int PS_OFF  = WS_OFF + 2 * TILE_F;
constexpr int DST_OFF = PS_OFF + 2 * TILE_F;
constexpr int FS_OFF  = DST_OFF + 512;
constexpr int SRC_OFF = FS_OFF + 1024;
constexpr int E1_OFF  = SRC_OFF + 128;
constexpr int E2_OFF  = E1_OFF + 128;
constexpr int RZ_OFF  = E2_OFF + 128;
constexpr int ZP_OFF  = RZ_OFF + 128;
constexpr int RED_OFF = ZP_OFF + 1024;
constexpr int MD_OFF  = RED_OFF + 8;
constexpr int AGG_SMEM_BYTES = (MD_OFF + 4) * 4;

__global__ __launch_bounds__(256, 2) void k_agg_mma(
    const uint32_t* __restrict__ bits, const float* __restrict__ WhT0,
    const float* __restrict__ src0, const float* __restrict__ dst0,
    float* __restrict__ outp, int ld)
{
    extern __shared__ __align__(16) float dyn[];
    float* WSf  = dyn + WS_OFF;
    float* PSf  = dyn + PS_OFF;
    float* dstS = dyn + DST_OFF;
    float2* FS2 = reinterpret_cast<float2*>(dyn + FS_OFF);
    float* srcS = dyn + SRC_OFF;
    float* e1S  = dyn + E1_OFF;
    float* e2S  = dyn + E2_OFF;
    float* rZS  = dyn + RZ_OFF;
    float* zpartS = dyn + ZP_OFF;
    float* red  = dyn + RED_OFF;
    float* mdstS = dyn + MD_OFF;

    const uint32_t ws_base = smem_u32(WSf);

    const int l    = blockIdx.z;
    const int b    = blockIdx.y;
    const int i0   = blockIdx.x * 128;
    const int tid  = threadIdx.x;
    const int w    = tid >> 5;
    const int lane = tid & 31;
    const int col0 = l * 128;

    const float* WhTl = WhT0 + (size_t)l * R * 128 + (size_t)b * 128 * 512;
    const float* srcp = src0 + (size_t)l * R;
    const float* dstp = dst0 + (size_t)l * R;
    const uint32_t* bitsb = bits + ((size_t)(b << 9) + i0) * 16;

    for (int k = tid; k < 512; k += 256) dstS[k] = dstp[(b << 9) + k];
    if (tid < 128) srcS[tid] = srcp[(b << 9) + i0 + tid];
    __syncthreads();

    {
        float v = fmaxf(dstS[tid], dstS[tid + 256]);
#pragma unroll
        for (int o = 16; o; o >>= 1) v = fmaxf(v, __shfl_xor_sync(0xffffffffu, v, o));
        if (lane == 0) red[w] = v;
        __syncthreads();
        if (tid == 0) {
            float m = red[0];
#pragma unroll
            for (int k = 1; k < 8; ++k) m = fmaxf(m, red[k]);
            mdstS[0] = m;
        }
        __syncthreads();
    }
    const float mdst = mdstS[0];

    for (int k = tid; k < 512; k += 256) {
        float d = dstS[k] - mdst;
        FS2[k] = make_float2(__expf(d), __expf(0.2f * d));
    }
    if (tid < 128) {
        float t2 = srcS[tid] + mdst;
        float m  = lrelu02(t2);
        e1S[tid] = __expf(t2 - m);
        e2S[tid] = __expf(0.2f * t2 - m);
    }
    __syncthreads();

    const int wm = w & 3;
    const int wn = w >> 2;
    const int g  = lane >> 2;
    const int q  = lane & 3;

    const int srow = tid >> 3;
    const int jq   = tid & 7;

    float dacc[2][8][4];
#pragma unroll
    for (int mf = 0; mf < 2; ++mf)
#pragma unroll
        for (int nf = 0; nf < 8; ++nf)
#pragma unroll
            for (int c = 0; c < 4; ++c) dacc[mf][nf][c] = 0.f;

    float zl[4] = {0.f, 0.f, 0.f, 0.f};

    const int sf[4] = { (tid + 0) >> 3, (tid + 256) >> 3, (tid + 512) >> 3, (tid + 768) >> 3 };

#pragma unroll
    for (int k = 0; k < 4; ++k) {
        int so = sf[k] * 32 + swz4(sf[k], jq);
        cp16(ws_base + (uint32_t)so * 4, WhTl + (size_t)sf[k] * 512 + jq * 4);
    }
    CP_COMMIT();
    {
        float4 d4 = *reinterpret_cast<const float4*>(&dstS[jq * 4]);
        const float4* fsp = reinterpret_cast<const float4*>(&FS2[jq * 4]);
        float4 f01 = fsp[0], f23 = fsp[1];
#pragma unroll
        for (int qq = 0; qq < 4; ++qq) {
            int r_ = srow + qq * 32;
            uint32_t m = bitsb[r_ * 16 + 0];
            float sv = srcS[r_], E1 = e1S[r_], E2 = e2S[r_];
            float p0, p1, p2, p3;
            { float s = sv + d4.x; bool gg = s > 0.f; p0 = (gg ? E1 : E2) * (gg ? f01.x : f01.y); }
            { float s = sv + d4.y; bool gg = s > 0.f; p1 = (gg ? E1 : E2) * (gg ? f01.z : f01.w); }
            { float s = sv + d4.z; bool gg = s > 0.f; p2 = (gg ? E1 : E2) * (gg ? f23.x : f23.y); }
            { float s = sv + d4.w; bool gg = s > 0.f; p3 = (gg ? E1 : E2) * (gg ? f23.z : f23.w); }
            p0 = ((m >> (jq * 4 + 0)) & 1u) ? trunc_tf32(p0) : 0.f;
            p1 = ((m >> (jq * 4 + 1)) & 1u) ? trunc_tf32(p1) : 0.f;
            p2 = ((m >> (jq * 4 + 2)) & 1u) ? trunc_tf32(p2) : 0.f;
            p3 = ((m >> (jq * 4 + 3)) & 1u) ? trunc_tf32(p3) : 0.f;
            zl[qq] += (p0 + p1) + (p2 + p3);
            *reinterpret_cast<float4*>(&PSf[r_ * 32 + swz4(r_, jq)]) =
                make_float4(p0, p1, p2, p3);
        }
    }
    CP_WAIT0();
    __syncthreads();

#pragma unroll 1
    for (int t = 0; t < 16; ++t) {
        const int cur = t & 1, nxt = cur ^ 1;

        if (t < 15) {
            const int tj1 = (t + 1) * 32;
#pragma unroll
            for (int k = 0; k < 4; ++k) {
                int so = sf[k] * 32 + swz4(sf[k], jq);
                cp16(ws_base + (uint32_t)(nxt * TILE_F + so) * 4,
                     WhTl + (size_t)sf[k] * 512 + tj1 + jq * 4);
            }
            CP_COMMIT();

            float4 d4 = *reinterpret_cast<const float4*>(&dstS[tj1 + jq * 4]);
            const float4* fsp = reinterpret_cast<const float4*>(&FS2[tj1 + jq * 4]);
            float4 f01 = fsp[0], f23 = fsp[1];
            float* PSb = PSf + nxt * TILE_F;
#pragma unroll
            for (int qq = 0; qq < 4; ++qq) {
                int r_ = srow + qq * 32;
                uint32_t m = bitsb[r_ * 16 + (t + 1)];
                float sv = srcS[r_], E1 = e1S[r_], E2 = e2S[r_];
                float p0, p1, p2, p3;
                { float s = sv + d4.x; bool gg = s > 0.f; p0 = (gg ? E1 : E2) * (gg ? f01.x : f01.y); }
                { float s = sv + d4.y; bool gg = s > 0.f; p1 = (gg ? E1 : E2) * (gg ? f01.z : f01.w); }
                { float s = sv + d4.z; bool gg = s > 0.f; p2 = (gg ? E1 : E2) * (gg ? f23.x : f23.y); }
                { float s = sv + d4.w; bool gg = s > 0.f; p3 = (gg ? E1 : E2) * (gg ? f23.z : f23.w); }
                p0 = ((m >> (jq * 4 + 0)) & 1u) ? trunc_tf32(p0) : 0.f;
                p1 = ((m >> (jq * 4 + 1)) & 1u) ? trunc_tf32(p1) : 0.f;
                p2 = ((m >> (jq * 4 + 2)) & 1u) ? trunc_tf32(p2) : 0.f;
                p3 = ((m >> (jq * 4 + 3)) & 1u) ? trunc_tf32(p3) : 0.f;
                zl[qq] += (p0 + p1) + (p2 + p3);
                *reinterpret_cast<float4*>(&PSb[r_ * 32 + swz4(r_, jq)]) =
                    make_float4(p0, p1, p2, p3);
            }
        }

        const uint32_t* PSu = reinterpret_cast<const uint32_t*>(PSf + cur * TILE_F);
        const uint32_t* WSu = reinterpret_cast<const uint32_t*>(WSf + cur * TILE_F);
#pragma unroll
        for (int kk = 0; kk < 32; kk += 8) {
            const int k4a = kk >> 2, k4b = (kk >> 2) + 1;
            uint32_t bf0[8], bf1[8];
#pragma unroll
            for (int nf = 0; nf < 8; ++nf) {
                int f = wn * 64 + nf * 8 + g;
                bf0[nf] = WSu[f * 32 + ((k4a ^ g) << 2) + q];
                bf1[nf] = WSu[f * 32 + ((k4b ^ g) << 2) + q];
            }
#pragma unroll
            for (int mf = 0; mf < 2; ++mf) {
                int r_ = wm * 32 + mf * 16 + g;
                uint32_t a0 = PSu[r_ * 32 + ((k4a ^ g) << 2) + q];
                uint32_t a1 = PSu[(r_ + 8) * 32 + ((k4a ^ g) << 2) + q];
                uint32_t a2 = PSu[r_ * 32 + ((k4b ^ g) << 2) + q];
                uint32_t a3 = PSu[(r_ + 8) * 32 + ((k4b ^ g) << 2) + q];
#pragma unroll
                for (int nf = 0; nf < 8; ++nf)
                    mma_tf32(dacc[mf][nf], a0, a1, a2, a3, bf0[nf], bf1[nf]);
            }
        }

        if (t < 15) CP_WAIT0();
        __syncthreads();
    }

#pragma unroll
    for (int qq = 0; qq < 4; ++qq) zpartS[(srow + qq * 32) * 8 + jq] = zl[qq];
    __syncthreads();
    if (tid < 128) {
        float z = 0.f;
#pragma unroll
        for (int k = 0; k < 8; ++k) z += zpartS[tid * 8 + k];
        rZS[tid] = 1.f / z;
    }
    __syncthreads();

#pragma unroll
    for (int mf = 0; mf < 2; ++mf) {
#pragma unroll
        for (int h = 0; h < 2; ++h) {
            int rl = wm * 32 + mf * 16 + g + h * 8;
            float rz = rZS[rl];
            float* orow = outp + ((size_t)(b << 9) + i0 + rl) * ld + col0 + wn * 64;
#pragma unroll
            for (int nf = 0; nf < 8; ++nf) {
                float2 v;
                v.x = totf32(elu1(dacc[mf][nf][2 * h]     * rz));
                v.y = totf32(elu1(dacc[mf][nf][2 * h + 1] * rz));
                *reinterpret_cast<float2*>(&orow[nf * 8 + 2 * q]) = v;
            }
        }
    }
}

// ---------------- launch ----------------
extern "C" void kernel_launch(void* const* d_in, const int* in_sizes, int n_in,
                              void* d_out, int out_size)
{
    (void)in_sizes; (void)n_in; (void)out_size;
    const float* compound = (const float*)d_in[0];   // [64,512,34]
    const int*   adj      = (const int*)d_in[1];     // [64,512,512]
    const float* Wst      = (const float*)d_in[2];   // [3,34,128]
    const float* ast      = (const float*)d_in[3];   // [3,256,1]
    const float* Wout     = (const float*)d_in[4];   // [384,128]
    const float* aout     = (const float*)d_in[5];   // [256,1]
    const float* Wc       = (const float*)d_in[6];   // [128,256]
    const float* bc       = (const float*)d_in[7];   // [256]
    float* out = (float*)d_out;                      // [64,512,256]

    float* g_WhT_p;   cudaGetSymbolAddress((void**)&g_WhT_p,  g_WhT);
    float* g_heads_p; cudaGetSymbolAddress((void**)&g_heads_p, g_heads);
    float* g_x_p;     cudaGetSymbolAddress((void**)&g_x_p,    g_x);
    float* g_src_p;   cudaGetSymbolAddress((void**)&g_src_p,  g_src3);
    float* g_dst_p;   cudaGetSymbolAddress((void**)&g_dst_p,  g_dst3);
    uint32_t* g_bits_p; cudaGetSymbolAddress((void**)&g_bits_p, g_adjbits);
    float* g_WoutT_p; cudaGetSymbolAddress((void**)&g_WoutT_p, g_WoutT);
    float* g_WcT_p;   cudaGetSymbolAddress((void**)&g_WcT_p,   g_WcT);

    cudaFuncSetAttribute(k_agg_mma, cudaFuncAttributeMaxDynamicSharedMemorySize,
                         AGG_SMEM_BYTES);
    cudaFuncSetAttribute(k_mma<384, 384, 0>,
                         cudaFuncAttributeMaxDynamicSharedMemorySize, GEMM_SMEM_BYTES);
    cudaFuncSetAttribute(k_mma<128, 128, 1>,
                         cudaFuncAttributeMaxDynamicSharedMemorySize, GEMM_SMEM_BYTES);

    k_pack<<<(R * 16) / 256, 256>>>(adj, g_bits_p);
    k_prepT<<<(128 * 384 + 256 * 128 + 255) / 256, 256>>>(Wout, Wc, g_WoutT_p, g_WcT_p);

    // 3 input-layer projections
    k_proj<34, 34><<<dim3(N / 64, B, 3), 256>>>(
        compound, 34, Wst, ast, g_WhT_p, g_src_p, g_dst_p);

    // 3 head aggregations
    k_agg_mma<<<dim3(N / 128, B, 3), 256, AGG_SMEM_BYTES>>>(
        g_bits_p, g_WhT_p, g_src_p, g_dst_p, g_heads_p, 384);

    // out-layer projection (mma GEMM, fused src/dst + transposed WhT store)
    k_mma<384, 384, 0><<<dim3(R / 128, 1), 256, GEMM_SMEM_BYTES>>>(
        g_heads_p, g_WoutT_p, aout,
        g_WhT_p + (size_t)3 * R * 128, g_src_p + (size_t)3 * R, g_dst_p + (size_t)3 * R);

    // out-layer aggregation
    k_agg_mma<<<dim3(N / 128, B, 1), 256, AGG_SMEM_BYTES>>>(
        g_bits_p, g_WhT_p + (size_t)3 * R * 128,
        g_src_p + (size_t)3 * R, g_dst_p + (size_t)3 * R, g_x_p, 128);

    // final dense layer
    k_mma<128, 128, 1><<<dim3(R / 128, 2), 256, GEMM_SMEM_BYTES>>>(
        g_x_p, g_WcT_p, bc, out, nullptr, nullptr);
}

// round 13
// speedup vs baseline: 5.2273x; 1.0196x over previous
#include <cuda_runtime.h>
#include <cstdint>

typedef unsigned long long ull;

// ---------------- problem constants ----------------
constexpr int B = 64;
constexpr int N = 512;
constexpr int R = B * N;      // 32768 rows

// ---------------- device scratch ----------------
__device__ float g_WhT[(size_t)4 * R * 128];   // per layer, per batch, [f][j], tf32
__device__ float g_heads[(size_t)R * 384];     // tf32-rounded values (elu out)
__device__ float g_x[(size_t)R * 128];         // tf32-rounded values
__device__ float g_src3[4 * R];
__device__ float g_dst3[4 * R];
__device__ uint32_t g_adjmask[(size_t)R * 128]; // per-element byte masks (0xFF / 0x00), 4 j per word
__device__ float g_WoutT[128 * 384];           // tf32-rounded, [f][k]
__device__ float g_WcT[256 * 128];             // tf32-rounded, [c][k]

__device__ __forceinline__ float lrelu02(float x) { return x > 0.f ? x : 0.2f * x; }
__device__ __forceinline__ float elu1(float x)    { return x > 0.f ? x : expm1f(x); }

__device__ __forceinline__ void fma2(ull& d, ull a, ull b) {
    asm("fma.rn.f32x2 %0, %1, %2, %3;" : "=l"(d) : "l"(a), "l"(b), "l"(d));
}
__device__ __forceinline__ ull pack2(float x) {
    ull r; asm("mov.b64 %0, {%1, %1};" : "=l"(r) : "f"(x)); return r;
}
__device__ __forceinline__ void unpack2(ull v, float& lo, float& hi) {
    asm("mov.b64 {%0, %1}, %2;" : "=f"(lo), "=f"(hi) : "l"(v));
}
__device__ __forceinline__ float totf32(float x) {
    float r; asm("cvt.rna.tf32.f32 %0, %1;" : "=f"(r) : "f"(x)); return r;
}
__device__ __forceinline__ uint32_t smem_u32(const void* p) {
    uint32_t a;
    asm("{ .reg .u64 t; cvta.to.shared.u64 t, %1; cvt.u32.u64 %0, t; }" : "=r"(a) : "l"(p));
    return a;
}
__device__ __forceinline__ void cp16(uint32_t dst, const void* src) {
    asm volatile("cp.async.cg.shared.global [%0], [%1], 16;" :: "r"(dst), "l"(src));
}
#define CP_COMMIT() asm volatile("cp.async.commit_group;" ::: "memory")
#define CP_WAIT0()  asm volatile("cp.async.wait_group 0;" ::: "memory")

// masked tf32-truncate: bits(p) & bytemask & 0xffffe000  (single LOP3)
__device__ __forceinline__ float mask_trunc(float p, uint32_t u) {
    return __uint_as_float(__float_as_uint(p) & u & 0xffffe000u);
}

// XOR swizzle float4-group offset within a [128][32] tile row
__device__ __forceinline__ int swz4(int row, int c4) {
    return ((c4 ^ (row & 7)) << 2);
}

union F4U { float4 f; ull u[2]; };

__device__ __forceinline__ void mma_tf32(float* d,
    uint32_t a0, uint32_t a1, uint32_t a2, uint32_t a3,
    uint32_t b0, uint32_t b1)
{
    asm volatile(
        "mma.sync.aligned.m16n8k8.row.col.f32.tf32.tf32.f32 "
        "{%0,%1,%2,%3}, {%4,%5,%6,%7}, {%8,%9}, {%0,%1,%2,%3};"
        : "+f"(d[0]), "+f"(d[1]), "+f"(d[2]), "+f"(d[3])
        : "r"(a0), "r"(a1), "r"(a2), "r"(a3), "r"(b0), "r"(b1));
}

// ============ K0a: pack adj into byte masks (0xFF / 0x00 per element) ============
__global__ __launch_bounds__(256) void k_pack(const int* __restrict__ adj,
                                              uint32_t* __restrict__ mask)
{
    int gid = blockIdx.x * 256 + threadIdx.x;   // one word = 4 adjacent j
    int4 v = reinterpret_cast<const int4*>(adj)[gid];
    uint32_t m = (v.x > 0 ? 0x000000FFu : 0u)
               | (v.y > 0 ? 0x0000FF00u : 0u)
               | (v.z > 0 ? 0x00FF0000u : 0u)
               | (v.w > 0 ? 0xFF000000u : 0u);
    mask[gid] = m;
}

// ============ K0b: transpose+round weights ============
__global__ __launch_bounds__(256) void k_prepT(const float* __restrict__ Wout,
                                               const float* __restrict__ Wc,
                                               float* __restrict__ WoutT,
                                               float* __restrict__ WcT)
{
    int idx = blockIdx.x * 256 + threadIdx.x;
    if (idx < 128 * 384) {
        int f = idx / 384, k = idx % 384;
        WoutT[idx] = totf32(Wout[(size_t)k * 128 + f]);
    } else {
        int j = idx - 128 * 384;
        if (j < 256 * 128) {
            int c = j / 128, k = j % 128;
            WcT[j] = totf32(Wc[(size_t)k * 256 + c]);
        }
    }
}

// ============ K1: blocked GEMM Wh = X @ W (fused src/dst); stores WhT tf32 ============
template<int FIN, int TK>
__global__ __launch_bounds__(256) void k_proj(
    const float* __restrict__ X, int ldx,
    const float* __restrict__ Wbase, const float* __restrict__ abase,
    float* __restrict__ WhTout, float* __restrict__ srcout, float* __restrict__ dstout)
{
    __shared__ __align__(16) float WtS[TK][128];
    __shared__ __align__(16) float htT[TK][68];
    __shared__ float aS[256];

    const int l   = blockIdx.z;
    const float* W = Wbase + (size_t)l * FIN * 128;
    const float* a = abase + l * 256;
    float* srcp = srcout + (size_t)l * R;
    float* dstp = dstout + (size_t)l * R;

    const int r0  = blockIdx.y * 512 + blockIdx.x * 64;
    const int tid = threadIdx.x;
    const int fg  = tid & 31;
    const int ig  = tid >> 5;

    aS[tid] = a[tid];

    ull acc2[4][4];
#pragma unroll
    for (int rp = 0; rp < 4; ++rp)
#pragma unroll
        for (int c = 0; c < 4; ++c) acc2[rp][c] = 0ull;

    for (int k0 = 0; k0 < FIN; k0 += TK) {
        __syncthreads();
        for (int e = tid; e < TK * 32; e += 256) {
            int k = e >> 5, c = e & 31;
            *reinterpret_cast<float4*>(&WtS[k][c * 4]) =
                *reinterpret_cast<const float4*>(&W[(size_t)(k0 + k) * 128 + c * 4]);
        }
        for (int e = tid; e < 64 * TK; e += 256) {
            int ii = e / TK, k = e - ii * TK;
            htT[k][ii] = X[(size_t)(r0 + ii) * ldx + k0 + k];
        }
        __syncthreads();

#pragma unroll 8
        for (int k = 0; k < TK; ++k) {
            float4 w = *reinterpret_cast<const float4*>(&WtS[k][fg * 4]);
            ull w0 = pack2(w.x), w1 = pack2(w.y), w2 = pack2(w.z), w3 = pack2(w.w);
            F4U p0, p1;
            p0.f = *reinterpret_cast<const float4*>(&htT[k][ig * 8]);
            p1.f = *reinterpret_cast<const float4*>(&htT[k][ig * 8 + 4]);
            ull pr[4] = {p0.u[0], p0.u[1], p1.u[0], p1.u[1]};
#pragma unroll
            for (int rp = 0; rp < 4; ++rp) {
                fma2(acc2[rp][0], pr[rp], w0);
                fma2(acc2[rp][1], pr[rp], w1);
                fma2(acc2[rp][2], pr[rp], w2);
                fma2(acc2[rp][3], pr[rp], w3);
            }
        }
    }

    float val[8][4];
#pragma unroll
    for (int rp = 0; rp < 4; ++rp)
#pragma unroll
        for (int c = 0; c < 4; ++c)
            unpack2(acc2[rp][c], val[2 * rp][c], val[2 * rp + 1][c]);

    {
        float* WT = WhTout + (size_t)l * R * 128 + (size_t)blockIdx.y * 128 * 512;
        const int il0 = blockIdx.x * 64 + ig * 8;
#pragma unroll
        for (int c = 0; c < 4; ++c) {
            int f = fg * 4 + c;
            float4 lo = make_float4(totf32(val[0][c]), totf32(val[1][c]),
                                    totf32(val[2][c]), totf32(val[3][c]));
            float4 hi = make_float4(totf32(val[4][c]), totf32(val[5][c]),
                                    totf32(val[6][c]), totf32(val[7][c]));
            *reinterpret_cast<float4*>(&WT[(size_t)f * 512 + il0])     = lo;
            *reinterpret_cast<float4*>(&WT[(size_t)f * 512 + il0 + 4]) = hi;
        }
    }

    float a1v[4], a2v[4];
#pragma unroll
    for (int c = 0; c < 4; ++c) { a1v[c] = aS[fg * 4 + c]; a2v[c] = aS[128 + fg * 4 + c]; }

#pragma unroll
    for (int rr = 0; rr < 8; ++rr) {
        int i = r0 + ig * 8 + rr;
        float v1 = val[rr][0] * a1v[0] + val[rr][1] * a1v[1] + val[rr][2] * a1v[2] + val[rr][3] * a1v[3];
        float v2 = val[rr][0] * a2v[0] + val[rr][1] * a2v[1] + val[rr][2] * a2v[2] + val[rr][3] * a2v[3];
#pragma unroll
        for (int o2 = 16; o2; o2 >>= 1) {
            v1 += __shfl_xor_sync(0xffffffffu, v1, o2);
            v2 += __shfl_xor_sync(0xffffffffu, v2, o2);
        }
        if (fg == 0) { srcp[i] = v1; dstp[i] = v2; }
    }
}

// ============ K2: generic pipelined mma.sync tf32 GEMM (swizzled tiles) ============
constexpr int TILE_F = 128 * 32;
constexpr int GEMM_SMEM_BYTES = 128 * 132 * 4;

template<int K, int LDX, int EPI>
__global__ __launch_bounds__(256, 2) void k_mma(
    const float* __restrict__ X, const float* __restrict__ WT,
    const float* __restrict__ vec,
    float* __restrict__ O,
    float* __restrict__ srcp, float* __restrict__ dstp)
{
    extern __shared__ __align__(16) float dyn[];
    float* XS = dyn;
    float* WS = dyn + 2 * TILE_F;
    __shared__ float vS[256];
    __shared__ float2 sred[128][2];

    const uint32_t xs_base = smem_u32(XS);
    const uint32_t ws_base = smem_u32(WS);

    const int r0   = blockIdx.x * 128;
    const int col0 = blockIdx.y * 128;
    const int tid  = threadIdx.x;
    const int w    = tid >> 5;
    const int lane = tid & 31;

    const float* WTb = WT + (size_t)col0 * K;

    if (EPI == 0) vS[tid] = vec[tid];
    else if (tid < 128) vS[tid] = vec[col0 + tid];

    const int wm = w & 3;
    const int wn = w >> 2;
    const int g  = lane >> 2;
    const int q  = lane & 3;

    const int sr = tid >> 3, c4 = tid & 7;

    float dacc[2][8][4];
#pragma unroll
    for (int mf = 0; mf < 2; ++mf)
#pragma unroll
        for (int nf = 0; nf < 8; ++nf)
#pragma unroll
            for (int c = 0; c < 4; ++c) dacc[mf][nf][c] = 0.f;

#pragma unroll
    for (int k = 0; k < 4; ++k) {
        int row = sr + k * 32;
        int so = row * 32 + swz4(row, c4);
        cp16(xs_base + (uint32_t)so * 4, X + (size_t)(r0 + row) * LDX + c4 * 4);
        cp16(ws_base + (uint32_t)so * 4, WTb + (size_t)row * K + c4 * 4);
    }
    CP_COMMIT();
    CP_WAIT0();
    __syncthreads();

    constexpr int NT = K / 32;
#pragma unroll 1
    for (int t = 0; t < NT; ++t) {
        const int cur = t & 1, nxt = cur ^ 1;
        if (t < NT - 1) {
            const int tj1 = (t + 1) * 32;
#pragma unroll
            for (int k = 0; k < 4; ++k) {
                int row = sr + k * 32;
                int so = row * 32 + swz4(row, c4);
                cp16(xs_base + (uint32_t)(nxt * TILE_F + so) * 4,
                     X + (size_t)(r0 + row) * LDX + tj1 + c4 * 4);
                cp16(ws_base + (uint32_t)(nxt * TILE_F + so) * 4,
                     WTb + (size_t)row * K + tj1 + c4 * 4);
            }
            CP_COMMIT();
        }

        const uint32_t* XSu = reinterpret_cast<const uint32_t*>(XS + cur * TILE_F);
        const uint32_t* WSu = reinterpret_cast<const uint32_t*>(WS + cur * TILE_F);
#pragma unroll
        for (int kk = 0; kk < 32; kk += 8) {
            const int k4a = kk >> 2, k4b = (kk >> 2) + 1;
            uint32_t bf0[8], bf1[8];
#pragma unroll
            for (int nf = 0; nf < 8; ++nf) {
                int f = wn * 64 + nf * 8 + g;
                bf0[nf] = WSu[f * 32 + ((k4a ^ g) << 2) + q];
                bf1[nf] = WSu[f * 32 + ((k4b ^ g) << 2) + q];
            }
#pragma unroll
            for (int mf = 0; mf < 2; ++mf) {
                int r_ = wm * 32 + mf * 16 + g;
                uint32_t a0 = XSu[r_ * 32 + ((k4a ^ g) << 2) + q];
                uint32_t a1 = XSu[(r_ + 8) * 32 + ((k4a ^ g) << 2) + q];
                uint32_t a2 = XSu[r_ * 32 + ((k4b ^ g) << 2) + q];
                uint32_t a3 = XSu[(r_ + 8) * 32 + ((k4b ^ g) << 2) + q];
#pragma unroll
                for (int nf = 0; nf < 8; ++nf)
                    mma_tf32(dacc[mf][nf], a0, a1, a2, a3, bf0[nf], bf1[nf]);
            }
        }

        if (t < NT - 1) CP_WAIT0();
        __syncthreads();
    }

    if (EPI == 1) {
#pragma unroll
        for (int mf = 0; mf < 2; ++mf) {
#pragma unroll
            for (int h = 0; h < 2; ++h) {
                int rl = wm * 32 + mf * 16 + g + h * 8;
                float* orow = O + (size_t)(r0 + rl) * 256 + col0 + wn * 64;
#pragma unroll
                for (int nf = 0; nf < 8; ++nf) {
                    int c0 = nf * 8 + 2 * q;
                    float2 v;
                    v.x = lrelu02(dacc[mf][nf][2 * h]     + vS[wn * 64 + c0]);
                    v.y = lrelu02(dacc[mf][nf][2 * h + 1] + vS[wn * 64 + c0 + 1]);
                    *reinterpret_cast<float2*>(&orow[c0]) = v;
                }
            }
        }
        return;
    }

    // EPI 0: fused src/dst
#pragma unroll
    for (int mf = 0; mf < 2; ++mf) {
#pragma unroll
        for (int h = 0; h < 2; ++h) {
            int rl = wm * 32 + mf * 16 + g + h * 8;
            float s1 = 0.f, s2 = 0.f;
#pragma unroll
            for (int nf = 0; nf < 8; ++nf) {
                int c0 = wn * 64 + nf * 8 + 2 * q;
                float v0 = dacc[mf][nf][2 * h], v1 = dacc[mf][nf][2 * h + 1];
                s1 += v0 * vS[c0] + v1 * vS[c0 + 1];
                s2 += v0 * vS[128 + c0] + v1 * vS[128 + c0 + 1];
            }
            s1 += __shfl_xor_sync(0xffffffffu, s1, 1);
            s1 += __shfl_xor_sync(0xffffffffu, s1, 2);
            s2 += __shfl_xor_sync(0xffffffffu, s2, 1);
            s2 += __shfl_xor_sync(0xffffffffu, s2, 2);
            if (q == 0) sred[rl][wn] = make_float2(s1, s2);
        }
    }
    __syncthreads();
    if (tid < 128) {
        float2 u = sred[tid][0], v = sred[tid][1];
        srcp[r0 + tid] = u.x + v.x;
        dstp[r0 + tid] = u.y + v.y;
    }

    float* WhS = dyn;   // 128 x 132
#pragma unroll
    for (int mf = 0; mf < 2; ++mf) {
#pragma unroll
        for (int h = 0; h < 2; ++h) {
            int rl = wm * 32 + mf * 16 + g + h * 8;
#pragma unroll
            for (int nf = 0; nf < 8; ++nf) {
                int c0 = wn * 64 + nf * 8 + 2 * q;
                *reinterpret_cast<float2*>(&WhS[rl * 132 + c0]) =
                    make_float2(dacc[mf][nf][2 * h], dacc[mf][nf][2 * h + 1]);
            }
        }
    }
    __syncthreads();
    {
        const int f = tid >> 1, ih = tid & 1;
        float* WTo = O + (size_t)(r0 >> 9) * (128 * 512)
                       + (size_t)f * 512 + (r0 & 511) + ih * 64;
#pragma unroll
        for (int v = 0; v < 16; ++v) {
            int i = ih * 64 + v * 4;
            float4 o = make_float4(totf32(WhS[(i + 0) * 132 + f]),
                                   totf32(WhS[(i + 1) * 132 + f]),
                                   totf32(WhS[(i + 2) * 132 + f]),
                                   totf32(WhS[(i + 3) * 132 + f]));
            *reinterpret_cast<float4*>(&WTo[v * 4]) = o;
        }
    }
}

// ============ K3: pipelined mma.sync tf32 fused softmax + aggregate ============
// P = max(E1_i*F1_j, E2_i*F2_j) masked&truncated via one LOP3 per element.
constexpr int WS_OFF  = 0;
constexpr int PS_OFF  = WS_OFF + 2 * TILE_F;
constexpr int DST_OFF = PS_OFF + 2 * TILE_F;
constexpr int FS_OFF  = DST_OFF + 512;
constexpr int SRC_OFF = FS_OFF + 1024;
constexpr int E1_OFF  = SRC_OFF + 128;
constexpr int E2_OFF  = E1_OFF + 128;
constexpr int RZ_OFF  = E2_OFF + 128;
constexpr int ZP_OFF  = RZ_OFF + 128;
constexpr int RED_OFF = ZP_OFF + 1024;
constexpr int MD_OFF  = RED_OFF + 8;
constexpr int AGG_SMEM_BYTES = (MD_OFF + 4) * 4;

__global__ __launch_bounds__(256, 2) void k_agg_mma(
    const uint32_t* __restrict__ amask, const float* __restrict__ WhT0,
    const float* __restrict__ src0, const float* __restrict__ dst0,
    float* __restrict__ outp, int ld)
{
    extern __shared__ __align__(16) float dyn[];
    float* WSf  = dyn + WS_OFF;
    float* PSf  = dyn + PS_OFF;
    float* dstS = dyn + DST_OFF;
    float2* FS2 = reinterpret_cast<float2*>(dyn + FS_OFF);
    float* srcS = dyn + SRC_OFF;
    float* e1S  = dyn + E1_OFF;
    float* e2S  = dyn + E2_OFF;
    float* rZS  = dyn + RZ_OFF;
    float* zpartS = dyn + ZP_OFF;
    float* red  = dyn + RED_OFF;
    float* mdstS = dyn + MD_OFF;

    const uint32_t ws_base = smem_u32(WSf);

    const int l    = blockIdx.z;
    const int b    = blockIdx.y;
    const int i0   = blockIdx.x * 128;
    const int tid  = threadIdx.x;
    const int w    = tid >> 5;
    const int lane = tid & 31;
    const int col0 = l * 128;

    const float* WhTl = WhT0 + (size_t)l * R * 128 + (size_t)b * 128 * 512;
    const float* srcp = src0 + (size_t)l * R;
    const float* dstp = dst0 + (size_t)l * R;
    const uint32_t* maskb = amask + ((size_t)(b << 9) + i0) * 128;

    for (int k = tid; k < 512; k += 256) dstS[k] = dstp[(b << 9) + k];
    if (tid < 128) srcS[tid] = srcp[(b << 9) + i0 + tid];
    __syncthreads();

    {
        float v = fmaxf(dstS[tid], dstS[tid + 256]);
#pragma unroll
        for (int o = 16; o; o >>= 1) v = fmaxf(v, __shfl_xor_sync(0xffffffffu, v, o));
        if (lane == 0) red[w] = v;
        __syncthreads();
        if (tid == 0) {
            float m = red[0];
#pragma unroll
            for (int k = 1; k < 8; ++k) m = fmaxf(m, red[k]);
            mdstS[0] = m;
        }
        __syncthreads();
    }
    const float mdst = mdstS[0];

    for (int k = tid; k < 512; k += 256) {
        float d = dstS[k] - mdst;
        FS2[k] = make_float2(__expf(d), __expf(0.2f * d));
    }
    if (tid < 128) {
        float t2 = srcS[tid] + mdst;
        float m  = fmaxf(t2, 0.2f * t2);
        e1S[tid] = __expf(t2 - m);
        e2S[tid] = __expf(0.2f * t2 - m);
    }
    __syncthreads();

    const int wm = w & 3;
    const int wn = w >> 2;
    const int g  = lane >> 2;
    const int q  = lane & 3;

    const int srow = tid >> 3;
    const int jq   = tid & 7;

    // loop-invariant row factors for P phase (rows srow + 32*qq)
    float E1r[4], E2r[4];
#pragma unroll
    for (int qq = 0; qq < 4; ++qq) {
        E1r[qq] = e1S[srow + qq * 32];
        E2r[qq] = e2S[srow + qq * 32];
    }

    float dacc[2][8][4];
#pragma unroll
    for (int mf = 0; mf < 2; ++mf)
#pragma unroll
        for (int nf = 0; nf < 8; ++nf)
#pragma unroll
            for (int c = 0; c < 4; ++c) dacc[mf][nf][c] = 0.f;

    float zl[4] = {0.f, 0.f, 0.f, 0.f};

    const int sf[4] = { (tid + 0) >> 3, (tid + 256) >> 3, (tid + 512) >> 3, (tid + 768) >> 3 };

#pragma unroll
    for (int k = 0; k < 4; ++k) {
        int so = sf[k] * 32 + swz4(sf[k], jq);
        cp16(ws_base + (uint32_t)so * 4, WhTl + (size_t)sf[k] * 512 + jq * 4);
    }
    CP_COMMIT();
    {
        const float4* fsp = reinterpret_cast<const float4*>(&FS2[jq * 4]);
        float4 f01 = fsp[0], f23 = fsp[1];
#pragma unroll
        for (int qq = 0; qq < 4; ++qq) {
            int r_ = srow + qq * 32;
            uint32_t mw = maskb[r_ * 128 + jq];
            float E1 = E1r[qq], E2 = E2r[qq];
            float p0 = mask_trunc(fmaxf(E1 * f01.x, E2 * f01.y), __byte_perm(mw, 0, 0x0000));
            float p1 = mask_trunc(fmaxf(E1 * f01.z, E2 * f01.w), __byte_perm(mw, 0, 0x1111));
            float p2 = mask_trunc(fmaxf(E1 * f23.x, E2 * f23.y), __byte_perm(mw, 0, 0x2222));
            float p3 = mask_trunc(fmaxf(E1 * f23.z, E2 * f23.w), __byte_perm(mw, 0, 0x3333));
            zl[qq] += (p0 + p1) + (p2 + p3);
            *reinterpret_cast<float4*>(&PSf[r_ * 32 + swz4(r_, jq)]) =
                make_float4(p0, p1, p2, p3);
        }
    }
    CP_WAIT0();
    __syncthreads();

#pragma unroll 1
    for (int t = 0; t < 16; ++t) {
        const int cur = t & 1, nxt = cur ^ 1;

        if (t < 15) {
            const int tj1 = (t + 1) * 32;
#pragma unroll
            for (int k = 0; k < 4; ++k) {
                int so = sf[k] * 32 + swz4(sf[k], jq);
                cp16(ws_base + (uint32_t)(nxt * TILE_F + so) * 4,
                     WhTl + (size_t)sf[k] * 512 + tj1 + jq * 4);
            }
            CP_COMMIT();

            const float4* fsp = reinterpret_cast<const float4*>(&FS2[tj1 + jq * 4]);
            float4 f01 = fsp[0], f23 = fsp[1];
            float* PSb = PSf + nxt * TILE_F;
            const int wofs = (t + 1) * 8 + jq;
#pragma unroll
            for (int qq = 0; qq < 4; ++qq) {
                int r_ = srow + qq * 32;
                uint32_t mw = maskb[r_ * 128 + wofs];
                float E1 = E1r[qq], E2 = E2r[qq];
                float p0 = mask_trunc(fmaxf(E1 * f01.x, E2 * f01.y), __byte_perm(mw, 0, 0x0000));
                float p1 = mask_trunc(fmaxf(E1 * f01.z, E2 * f01.w), __byte_perm(mw, 0, 0x1111));
                float p2 = mask_trunc(fmaxf(E1 * f23.x, E2 * f23.y), __byte_perm(mw, 0, 0x2222));
                float p3 = mask_trunc(fmaxf(E1 * f23.z, E2 * f23.w), __byte_perm(mw, 0, 0x3333));
                zl[qq] += (p0 + p1) + (p2 + p3);
                *reinterpret_cast<float4*>(&PSb[r_ * 32 + swz4(r_, jq)]) =
                    make_float4(p0, p1, p2, p3);
            }
        }

        const uint32_t* PSu = reinterpret_cast<const uint32_t*>(PSf + cur * TILE_F);
        const uint32_t* WSu = reinterpret_cast<const uint32_t*>(WSf + cur * TILE_F);
#pragma unroll
        for (int kk = 0; kk < 32; kk += 8) {
            const int k4a = kk >> 2, k4b = (kk >> 2) + 1;
            uint32_t bf0[8], bf1[8];
#pragma unroll
            for (int nf = 0; nf < 8; ++nf) {
                int f = wn * 64 + nf * 8 + g;
                bf0[nf] = WSu[f * 32 + ((k4a ^ g) << 2) + q];
                bf1[nf] = WSu[f * 32 + ((k4b ^ g) << 2) + q];
            }
#pragma unroll
            for (int mf = 0; mf < 2; ++mf) {
                int r_ = wm * 32 + mf * 16 + g;
                uint32_t a0 = PSu[r_ * 32 + ((k4a ^ g) << 2) + q];
                uint32_t a1 = PSu[(r_ + 8) * 32 + ((k4a ^ g) << 2) + q];
                uint32_t a2 = PSu[r_ * 32 + ((k4b ^ g) << 2) + q];
                uint32_t a3 = PSu[(r_ + 8) * 32 + ((k4b ^ g) << 2) + q];
#pragma unroll
                for (int nf = 0; nf < 8; ++nf)
                    mma_tf32(dacc[mf][nf], a0, a1, a2, a3, bf0[nf], bf1[nf]);
            }
        }

        if (t < 15) CP_WAIT0();
        __syncthreads();
    }

#pragma unroll
    for (int qq = 0; qq < 4; ++qq) zpartS[(srow + qq * 32) * 8 + jq] = zl[qq];
    __syncthreads();
    if (tid < 128) {
        float z = 0.f;
#pragma unroll
        for (int k = 0; k < 8; ++k) z += zpartS[tid * 8 + k];
        rZS[tid] = 1.f / z;
    }
    __syncthreads();

#pragma unroll
    for (int mf = 0; mf < 2; ++mf) {
#pragma unroll
        for (int h = 0; h < 2; ++h) {
            int rl = wm * 32 + mf * 16 + g + h * 8;
            float rz = rZS[rl];
            float* orow = outp + ((size_t)(b << 9) + i0 + rl) * ld + col0 + wn * 64;
#pragma unroll
            for (int nf = 0; nf < 8; ++nf) {
                float2 v;
                v.x = totf32(elu1(dacc[mf][nf][2 * h]     * rz));
                v.y = totf32(elu1(dacc[mf][nf][2 * h + 1] * rz));
                *reinterpret_cast<float2*>(&orow[nf * 8 + 2 * q]) = v;
            }
        }
    }
}

// ---------------- launch ----------------
extern "C" void kernel_launch(void* const* d_in, const int* in_sizes, int n_in,
                              void* d_out, int out_size)
{
    (void)in_sizes; (void)n_in; (void)out_size;
    const float* compound = (const float*)d_in[0];   // [64,512,34]
    const int*   adj      = (const int*)d_in[1];     // [64,512,512]
    const float* Wst      = (const float*)d_in[2];   // [3,34,128]
    const float* ast      = (const float*)d_in[3];   // [3,256,1]
    const float* Wout     = (const float*)d_in[4];   // [384,128]
    const float* aout     = (const float*)d_in[5];   // [256,1]
    const float* Wc       = (const float*)d_in[6];   // [128,256]
    const float* bc       = (const float*)d_in[7];   // [256]
    float* out = (float*)d_out;                      // [64,512,256]

    float* g_WhT_p;   cudaGetSymbolAddress((void**)&g_WhT_p,  g_WhT);
    float* g_heads_p; cudaGetSymbolAddress((void**)&g_heads_p, g_heads);
    float* g_x_p;     cudaGetSymbolAddress((void**)&g_x_p,    g_x);
    float* g_src_p;   cudaGetSymbolAddress((void**)&g_src_p,  g_src3);
    float* g_dst_p;   cudaGetSymbolAddress((void**)&g_dst_p,  g_dst3);
    uint32_t* g_mask_p; cudaGetSymbolAddress((void**)&g_mask_p, g_adjmask);
    float* g_WoutT_p; cudaGetSymbolAddress((void**)&g_WoutT_p, g_WoutT);
    float* g_WcT_p;   cudaGetSymbolAddress((void**)&g_WcT_p,   g_WcT);

    cudaFuncSetAttribute(k_agg_mma, cudaFuncAttributeMaxDynamicSharedMemorySize,
                         AGG_SMEM_BYTES);
    cudaFuncSetAttribute(k_mma<384, 384, 0>,
                         cudaFuncAttributeMaxDynamicSharedMemorySize, GEMM_SMEM_BYTES);
    cudaFuncSetAttribute(k_mma<128, 128, 1>,
                         cudaFuncAttributeMaxDynamicSharedMemorySize, GEMM_SMEM_BYTES);

    k_pack<<<(R * 128) / 256, 256>>>(adj, g_mask_p);
    k_prepT<<<(128 * 384 + 256 * 128 + 255) / 256, 256>>>(Wout, Wc, g_WoutT_p, g_WcT_p);

    // 3 input-layer projections
    k_proj<34, 34><<<dim3(N / 64, B, 3), 256>>>(
        compound, 34, Wst, ast, g_WhT_p, g_src_p, g_dst_p);

    // 3 head aggregations
    k_agg_mma<<<dim3(N / 128, B, 3), 256, AGG_SMEM_BYTES>>>(
        g_mask_p, g_WhT_p, g_src_p, g_dst_p, g_heads_p, 384);

    // out-layer projection (mma GEMM, fused src/dst + transposed WhT store)
    k_mma<384, 384, 0><<<dim3(R / 128, 1), 256, GEMM_SMEM_BYTES>>>(
        g_heads_p, g_WoutT_p, aout,
        g_WhT_p + (size_t)3 * R * 128, g_src_p + (size_t)3 * R, g_dst_p + (size_t)3 * R);

    // out-layer aggregation
    k_agg_mma<<<dim3(N / 128, B, 1), 256, AGG_SMEM_BYTES>>>(
        g_mask_p, g_WhT_p + (size_t)3 * R * 128,
        g_src_p + (size_t)3 * R, g_dst_p + (size_t)3 * R, g_x_p, 128);

    // final dense layer
    k_mma<128, 128, 1><<<dim3(R / 128, 2), 256, GEMM_SMEM_BYTES>>>(
        g_x_p, g_WcT_p, bc, out, nullptr, nullptr);
}

// round 14
// speedup vs baseline: 5.4942x; 1.0511x over previous
#include <cuda_runtime.h>
#include <cstdint>

typedef unsigned long long ull;

// ---------------- problem constants ----------------
constexpr int B = 64;
constexpr int N = 512;
constexpr int R = B * N;      // 32768 rows

// ---------------- device scratch ----------------
__device__ float g_WhT[(size_t)4 * R * 128];   // per layer, per batch, [f][j], tf32
__device__ float g_heads[(size_t)R * 384];     // tf32-rounded values (elu out)
__device__ float g_x[(size_t)R * 128];         // tf32-rounded values
__device__ float g_src3[4 * R];
__device__ float g_dst3[4 * R];
__device__ uint32_t g_adjmask[(size_t)R * 128]; // per-element byte masks, 4 j per word
__device__ float g_WoutT[128 * 384];           // tf32-rounded, [f][k]
__device__ float g_WcT[256 * 128];             // tf32-rounded, [c][k]

__device__ __forceinline__ float lrelu02(float x) { return x > 0.f ? x : 0.2f * x; }
__device__ __forceinline__ float elu1(float x)    { return x > 0.f ? x : expm1f(x); }

__device__ __forceinline__ void fma2(ull& d, ull a, ull b) {
    asm("fma.rn.f32x2 %0, %1, %2, %3;" : "=l"(d) : "l"(a), "l"(b), "l"(d));
}
__device__ __forceinline__ ull pack2(float x) {
    ull r; asm("mov.b64 %0, {%1, %1};" : "=l"(r) : "f"(x)); return r;
}
__device__ __forceinline__ void unpack2(ull v, float& lo, float& hi) {
    asm("mov.b64 {%0, %1}, %2;" : "=f"(lo), "=f"(hi) : "l"(v));
}
__device__ __forceinline__ float totf32(float x) {
    float r; asm("cvt.rna.tf32.f32 %0, %1;" : "=f"(r) : "f"(x)); return r;
}
__device__ __forceinline__ uint32_t smem_u32(const void* p) {
    uint32_t a;
    asm("{ .reg .u64 t; cvta.to.shared.u64 t, %1; cvt.u32.u64 %0, t; }" : "=r"(a) : "l"(p));
    return a;
}
__device__ __forceinline__ void cp16(uint32_t dst, const void* src) {
    asm volatile("cp.async.cg.shared.global [%0], [%1], 16;" :: "r"(dst), "l"(src));
}
#define CP_COMMIT() asm volatile("cp.async.commit_group;" ::: "memory")
#define CP_WAIT0()  asm volatile("cp.async.wait_group 0;" ::: "memory")

// masked tf32-truncate: bits(p) & bytemask & 0xffffe000  (single LOP3)
__device__ __forceinline__ float mask_trunc(float p, uint32_t u) {
    return __uint_as_float(__float_as_uint(p) & u & 0xffffe000u);
}

// XOR swizzle float4-group offset within a 32-float row
__device__ __forceinline__ int swz4(int row, int c4) {
    return ((c4 ^ (row & 7)) << 2);
}

union F4U { float4 f; ull u[2]; };

__device__ __forceinline__ void mma_tf32(float* d,
    uint32_t a0, uint32_t a1, uint32_t a2, uint32_t a3,
    uint32_t b0, uint32_t b1)
{
    asm volatile(
        "mma.sync.aligned.m16n8k8.row.col.f32.tf32.tf32.f32 "
        "{%0,%1,%2,%3}, {%4,%5,%6,%7}, {%8,%9}, {%0,%1,%2,%3};"
        : "+f"(d[0]), "+f"(d[1]), "+f"(d[2]), "+f"(d[3])
        : "r"(a0), "r"(a1), "r"(a2), "r"(a3), "r"(b0), "r"(b1));
}

// ============ K0a: pack adj into byte masks ============
__global__ __launch_bounds__(256) void k_pack(const int* __restrict__ adj,
                                              uint32_t* __restrict__ mask)
{
    int gid = blockIdx.x * 256 + threadIdx.x;
    int4 v = reinterpret_cast<const int4*>(adj)[gid];
    uint32_t m = (v.x > 0 ? 0x000000FFu : 0u)
               | (v.y > 0 ? 0x0000FF00u : 0u)
               | (v.z > 0 ? 0x00FF0000u : 0u)
               | (v.w > 0 ? 0xFF000000u : 0u);
    mask[gid] = m;
}

// ============ K0b: transpose+round weights ============
__global__ __launch_bounds__(256) void k_prepT(const float* __restrict__ Wout,
                                               const float* __restrict__ Wc,
                                               float* __restrict__ WoutT,
                                               float* __restrict__ WcT)
{
    int idx = blockIdx.x * 256 + threadIdx.x;
    if (idx < 128 * 384) {
        int f = idx / 384, k = idx % 384;
        WoutT[idx] = totf32(Wout[(size_t)k * 128 + f]);
    } else {
        int j = idx - 128 * 384;
        if (j < 256 * 128) {
            int c = j / 128, k = j % 128;
            WcT[j] = totf32(Wc[(size_t)k * 256 + c]);
        }
    }
}

// ============ K1: blocked GEMM Wh = X @ W (fused src/dst); stores WhT tf32 ============
template<int FIN, int TK>
__global__ __launch_bounds__(256) void k_proj(
    const float* __restrict__ X, int ldx,
    const float* __restrict__ Wbase, const float* __restrict__ abase,
    float* __restrict__ WhTout, float* __restrict__ srcout, float* __restrict__ dstout)
{
    __shared__ __align__(16) float WtS[TK][128];
    __shared__ __align__(16) float htT[TK][68];
    __shared__ float aS[256];

    const int l   = blockIdx.z;
    const float* W = Wbase + (size_t)l * FIN * 128;
    const float* a = abase + l * 256;
    float* srcp = srcout + (size_t)l * R;
    float* dstp = dstout + (size_t)l * R;

    const int r0  = blockIdx.y * 512 + blockIdx.x * 64;
    const int tid = threadIdx.x;
    const int fg  = tid & 31;
    const int ig  = tid >> 5;

    aS[tid] = a[tid];

    ull acc2[4][4];
#pragma unroll
    for (int rp = 0; rp < 4; ++rp)
#pragma unroll
        for (int c = 0; c < 4; ++c) acc2[rp][c] = 0ull;

    for (int k0 = 0; k0 < FIN; k0 += TK) {
        __syncthreads();
        for (int e = tid; e < TK * 32; e += 256) {
            int k = e >> 5, c = e & 31;
            *reinterpret_cast<float4*>(&WtS[k][c * 4]) =
                *reinterpret_cast<const float4*>(&W[(size_t)(k0 + k) * 128 + c * 4]);
        }
        for (int e = tid; e < 64 * TK; e += 256) {
            int ii = e / TK, k = e - ii * TK;
            htT[k][ii] = X[(size_t)(r0 + ii) * ldx + k0 + k];
        }
        __syncthreads();

#pragma unroll 8
        for (int k = 0; k < TK; ++k) {
            float4 w = *reinterpret_cast<const float4*>(&WtS[k][fg * 4]);
            ull w0 = pack2(w.x), w1 = pack2(w.y), w2 = pack2(w.z), w3 = pack2(w.w);
            F4U p0, p1;
            p0.f = *reinterpret_cast<const float4*>(&htT[k][ig * 8]);
            p1.f = *reinterpret_cast<const float4*>(&htT[k][ig * 8 + 4]);
            ull pr[4] = {p0.u[0], p0.u[1], p1.u[0], p1.u[1]};
#pragma unroll
            for (int rp = 0; rp < 4; ++rp) {
                fma2(acc2[rp][0], pr[rp], w0);
                fma2(acc2[rp][1], pr[rp], w1);
                fma2(acc2[rp][2], pr[rp], w2);
                fma2(acc2[rp][3], pr[rp], w3);
            }
        }
    }

    float val[8][4];
#pragma unroll
    for (int rp = 0; rp < 4; ++rp)
#pragma unroll
        for (int c = 0; c < 4; ++c)
            unpack2(acc2[rp][c], val[2 * rp][c], val[2 * rp + 1][c]);

    {
        float* WT = WhTout + (size_t)l * R * 128 + (size_t)blockIdx.y * 128 * 512;
        const int il0 = blockIdx.x * 64 + ig * 8;
#pragma unroll
        for (int c = 0; c < 4; ++c) {
            int f = fg * 4 + c;
            float4 lo = make_float4(totf32(val[0][c]), totf32(val[1][c]),
                                    totf32(val[2][c]), totf32(val[3][c]));
            float4 hi = make_float4(totf32(val[4][c]), totf32(val[5][c]),
                                    totf32(val[6][c]), totf32(val[7][c]));
            *reinterpret_cast<float4*>(&WT[(size_t)f * 512 + il0])     = lo;
            *reinterpret_cast<float4*>(&WT[(size_t)f * 512 + il0 + 4]) = hi;
        }
    }

    float a1v[4], a2v[4];
#pragma unroll
    for (int c = 0; c < 4; ++c) { a1v[c] = aS[fg * 4 + c]; a2v[c] = aS[128 + fg * 4 + c]; }

#pragma unroll
    for (int rr = 0; rr < 8; ++rr) {
        int i = r0 + ig * 8 + rr;
        float v1 = val[rr][0] * a1v[0] + val[rr][1] * a1v[1] + val[rr][2] * a1v[2] + val[rr][3] * a1v[3];
        float v2 = val[rr][0] * a2v[0] + val[rr][1] * a2v[1] + val[rr][2] * a2v[2] + val[rr][3] * a2v[3];
#pragma unroll
        for (int o2 = 16; o2; o2 >>= 1) {
            v1 += __shfl_xor_sync(0xffffffffu, v1, o2);
            v2 += __shfl_xor_sync(0xffffffffu, v2, o2);
        }
        if (fg == 0) { srcp[i] = v1; dstp[i] = v2; }
    }
}

// ============ K2: generic pipelined mma.sync tf32 GEMM (swizzled tiles) ============
constexpr int TILE_F = 128 * 32;
constexpr int GEMM_SMEM_BYTES = 128 * 132 * 4;

template<int K, int LDX, int EPI>
__global__ __launch_bounds__(256, 2) void k_mma(
    const float* __restrict__ X, const float* __restrict__ WT,
    const float* __restrict__ vec,
    float* __restrict__ O,
    float* __restrict__ srcp, float* __restrict__ dstp)
{
    extern __shared__ __align__(16) float dyn[];
    float* XS = dyn;
    float* WS = dyn + 2 * TILE_F;
    __shared__ float vS[256];
    __shared__ float2 sred[128][2];

    const uint32_t xs_base = smem_u32(XS);
    const uint32_t ws_base = smem_u32(WS);

    const int r0   = blockIdx.x * 128;
    const int col0 = blockIdx.y * 128;
    const int tid  = threadIdx.x;
    const int w    = tid >> 5;
    const int lane = tid & 31;

    const float* WTb = WT + (size_t)col0 * K;

    if (EPI == 0) vS[tid] = vec[tid];
    else if (tid < 128) vS[tid] = vec[col0 + tid];

    const int wm = w & 3;
    const int wn = w >> 2;
    const int g  = lane >> 2;
    const int q  = lane & 3;

    const int sr = tid >> 3, c4 = tid & 7;

    float dacc[2][8][4];
#pragma unroll
    for (int mf = 0; mf < 2; ++mf)
#pragma unroll
        for (int nf = 0; nf < 8; ++nf)
#pragma unroll
            for (int c = 0; c < 4; ++c) dacc[mf][nf][c] = 0.f;

#pragma unroll
    for (int k = 0; k < 4; ++k) {
        int row = sr + k * 32;
        int so = row * 32 + swz4(row, c4);
        cp16(xs_base + (uint32_t)so * 4, X + (size_t)(r0 + row) * LDX + c4 * 4);
        cp16(ws_base + (uint32_t)so * 4, WTb + (size_t)row * K + c4 * 4);
    }
    CP_COMMIT();
    CP_WAIT0();
    __syncthreads();

    constexpr int NT = K / 32;
#pragma unroll 1
    for (int t = 0; t < NT; ++t) {
        const int cur = t & 1, nxt = cur ^ 1;
        if (t < NT - 1) {
            const int tj1 = (t + 1) * 32;
#pragma unroll
            for (int k = 0; k < 4; ++k) {
                int row = sr + k * 32;
                int so = row * 32 + swz4(row, c4);
                cp16(xs_base + (uint32_t)(nxt * TILE_F + so) * 4,
                     X + (size_t)(r0 + row) * LDX + tj1 + c4 * 4);
                cp16(ws_base + (uint32_t)(nxt * TILE_F + so) * 4,
                     WTb + (size_t)row * K + tj1 + c4 * 4);
            }
            CP_COMMIT();
        }

        const uint32_t* XSu = reinterpret_cast<const uint32_t*>(XS + cur * TILE_F);
        const uint32_t* WSu = reinterpret_cast<const uint32_t*>(WS + cur * TILE_F);
#pragma unroll
        for (int kk = 0; kk < 32; kk += 8) {
            const int k4a = kk >> 2, k4b = (kk >> 2) + 1;
            uint32_t bf0[8], bf1[8];
#pragma unroll
            for (int nf = 0; nf < 8; ++nf) {
                int f = wn * 64 + nf * 8 + g;
                bf0[nf] = WSu[f * 32 + ((k4a ^ g) << 2) + q];
                bf1[nf] = WSu[f * 32 + ((k4b ^ g) << 2) + q];
            }
#pragma unroll
            for (int mf = 0; mf < 2; ++mf) {
                int r_ = wm * 32 + mf * 16 + g;
                uint32_t a0 = XSu[r_ * 32 + ((k4a ^ g) << 2) + q];
                uint32_t a1 = XSu[(r_ + 8) * 32 + ((k4a ^ g) << 2) + q];
                uint32_t a2 = XSu[r_ * 32 + ((k4b ^ g) << 2) + q];
                uint32_t a3 = XSu[(r_ + 8) * 32 + ((k4b ^ g) << 2) + q];
#pragma unroll
                for (int nf = 0; nf < 8; ++nf)
                    mma_tf32(dacc[mf][nf], a0, a1, a2, a3, bf0[nf], bf1[nf]);
            }
        }

        if (t < NT - 1) CP_WAIT0();
        __syncthreads();
    }

    if (EPI == 1) {
#pragma unroll
        for (int mf = 0; mf < 2; ++mf) {
#pragma unroll
            for (int h = 0; h < 2; ++h) {
                int rl = wm * 32 + mf * 16 + g + h * 8;
                float* orow = O + (size_t)(r0 + rl) * 256 + col0 + wn * 64;
#pragma unroll
                for (int nf = 0; nf < 8; ++nf) {
                    int c0 = nf * 8 + 2 * q;
                    float2 v;
                    v.x = lrelu02(dacc[mf][nf][2 * h]     + vS[wn * 64 + c0]);
                    v.y = lrelu02(dacc[mf][nf][2 * h + 1] + vS[wn * 64 + c0 + 1]);
                    *reinterpret_cast<float2*>(&orow[c0]) = v;
                }
            }
        }
        return;
    }

    // EPI 0: fused src/dst
#pragma unroll
    for (int mf = 0; mf < 2; ++mf) {
#pragma unroll
        for (int h = 0; h < 2; ++h) {
            int rl = wm * 32 + mf * 16 + g + h * 8;
            float s1 = 0.f, s2 = 0.f;
#pragma unroll
            for (int nf = 0; nf < 8; ++nf) {
                int c0 = wn * 64 + nf * 8 + 2 * q;
                float v0 = dacc[mf][nf][2 * h], v1 = dacc[mf][nf][2 * h + 1];
                s1 += v0 * vS[c0] + v1 * vS[c0 + 1];
                s2 += v0 * vS[128 + c0] + v1 * vS[128 + c0 + 1];
            }
            s1 += __shfl_xor_sync(0xffffffffu, s1, 1);
            s1 += __shfl_xor_sync(0xffffffffu, s1, 2);
            s2 += __shfl_xor_sync(0xffffffffu, s2, 1);
            s2 += __shfl_xor_sync(0xffffffffu, s2, 2);
            if (q == 0) sred[rl][wn] = make_float2(s1, s2);
        }
    }
    __syncthreads();
    if (tid < 128) {
        float2 u = sred[tid][0], v = sred[tid][1];
        srcp[r0 + tid] = u.x + v.x;
        dstp[r0 + tid] = u.y + v.y;
    }

    float* WhS = dyn;   // 128 x 132
#pragma unroll
    for (int mf = 0; mf < 2; ++mf) {
#pragma unroll
        for (int h = 0; h < 2; ++h) {
            int rl = wm * 32 + mf * 16 + g + h * 8;
#pragma unroll
            for (int nf = 0; nf < 8; ++nf) {
                int c0 = wn * 64 + nf * 8 + 2 * q;
                *reinterpret_cast<float2*>(&WhS[rl * 132 + c0]) =
                    make_float2(dacc[mf][nf][2 * h], dacc[mf][nf][2 * h + 1]);
            }
        }
    }
    __syncthreads();
    {
        const int f = tid >> 1, ih = tid & 1;
        float* WTo = O + (size_t)(r0 >> 9) * (128 * 512)
                       + (size_t)f * 512 + (r0 & 511) + ih * 64;
#pragma unroll
        for (int v = 0; v < 16; ++v) {
            int i = ih * 64 + v * 4;
            float4 o = make_float4(totf32(WhS[(i + 0) * 132 + f]),
                                   totf32(WhS[(i + 1) * 132 + f]),
                                   totf32(WhS[(i + 2) * 132 + f]),
                                   totf32(WhS[(i + 3) * 132 + f]));
            *reinterpret_cast<float4*>(&WTo[v * 4]) = o;
        }
    }
}

// ============ K3: pipelined mma.sync tf32 fused softmax + aggregate ============
// CTA = 64 i-rows x 128 f, 128 threads (4 warps) -> 4 CTAs/SM.
constexpr int PS_F   = 64 * 32;                  // 2048 floats per PS buffer
constexpr int WS_OFF  = 0;                       // 2 x 128 x 32 = 8192
constexpr int PS_OFF  = WS_OFF + 2 * TILE_F;     // 8192
constexpr int DST_OFF = PS_OFF + 2 * PS_F;       // 12288
constexpr int FS_OFF  = DST_OFF + 512;           // float2[512]
constexpr int SRC_OFF = FS_OFF + 1024;
constexpr int E1_OFF  = SRC_OFF + 64;
constexpr int E2_OFF  = E1_OFF + 64;
constexpr int RZ_OFF  = E2_OFF + 64;
constexpr int RED_OFF = RZ_OFF + 64;
constexpr int MD_OFF  = RED_OFF + 4;
constexpr int AGG_SMEM_BYTES = (MD_OFF + 4) * 4;  // ~56.4 KB

__global__ __launch_bounds__(128, 4) void k_agg_mma(
    const uint32_t* __restrict__ amask, const float* __restrict__ WhT0,
    const float* __restrict__ src0, const float* __restrict__ dst0,
    float* __restrict__ outp, int ld)
{
    extern __shared__ __align__(16) float dyn[];
    float* WSf  = dyn + WS_OFF;
    float* PSf  = dyn + PS_OFF;
    float* dstS = dyn + DST_OFF;
    float2* FS2 = reinterpret_cast<float2*>(dyn + FS_OFF);
    float* srcS = dyn + SRC_OFF;
    float* e1S  = dyn + E1_OFF;
    float* e2S  = dyn + E2_OFF;
    float* rZS  = dyn + RZ_OFF;
    float* red  = dyn + RED_OFF;
    float* mdstS = dyn + MD_OFF;

    const uint32_t ws_base = smem_u32(WSf);

    const int l    = blockIdx.z;
    const int b    = blockIdx.y;
    const int i0   = blockIdx.x * 64;
    const int tid  = threadIdx.x;
    const int w    = tid >> 5;
    const int lane = tid & 31;
    const int col0 = l * 128;

    const float* WhTl = WhT0 + (size_t)l * R * 128 + (size_t)b * 128 * 512;
    const float* srcp = src0 + (size_t)l * R;
    const float* dstp = dst0 + (size_t)l * R;
    const uint32_t* maskb = amask + ((size_t)(b << 9) + i0) * 128;

    for (int k = tid; k < 512; k += 128) dstS[k] = dstp[(b << 9) + k];
    if (tid < 64) srcS[tid] = srcp[(b << 9) + i0 + tid];
    __syncthreads();

    {
        float v = fmaxf(fmaxf(dstS[tid], dstS[tid + 128]),
                        fmaxf(dstS[tid + 256], dstS[tid + 384]));
#pragma unroll
        for (int o = 16; o; o >>= 1) v = fmaxf(v, __shfl_xor_sync(0xffffffffu, v, o));
        if (lane == 0) red[w] = v;
        __syncthreads();
        if (tid == 0) {
            float m = fmaxf(fmaxf(red[0], red[1]), fmaxf(red[2], red[3]));
            mdstS[0] = m;
        }
        __syncthreads();
    }
    const float mdst = mdstS[0];

    for (int k = tid; k < 512; k += 128) {
        float d = dstS[k] - mdst;
        FS2[k] = make_float2(__expf(d), __expf(0.2f * d));
    }
    if (tid < 64) {
        float t2 = srcS[tid] + mdst;
        float m  = fmaxf(t2, 0.2f * t2);
        e1S[tid] = __expf(t2 - m);
        e2S[tid] = __expf(0.2f * t2 - m);
    }
    __syncthreads();

    // frag mapping: warp tile 32i x 64f
    const int wm = w & 1;
    const int wn = w >> 1;
    const int g  = lane >> 2;
    const int q  = lane & 3;

    // P-phase mapping: rows srow + 16*qq (qq=0..3), jq = float4 group
    const int srow = tid >> 3;   // 0..15
    const int jq   = tid & 7;

    float E1r[4], E2r[4];
#pragma unroll
    for (int qq = 0; qq < 4; ++qq) {
        E1r[qq] = e1S[srow + qq * 16];
        E2r[qq] = e2S[srow + qq * 16];
    }

    float dacc[2][8][4];
#pragma unroll
    for (int mf = 0; mf < 2; ++mf)
#pragma unroll
        for (int nf = 0; nf < 8; ++nf)
#pragma unroll
            for (int c = 0; c < 4; ++c) dacc[mf][nf][c] = 0.f;

    float zl[4] = {0.f, 0.f, 0.f, 0.f};

    // WS staging: 8 float4 per thread (rows srow + 16k)
#pragma unroll
    for (int k = 0; k < 8; ++k) {
        int row = srow + k * 16;
        int so = row * 32 + swz4(row, jq);
        cp16(ws_base + (uint32_t)so * 4, WhTl + (size_t)row * 512 + jq * 4);
    }
    CP_COMMIT();
    {
        const float4* fsp = reinterpret_cast<const float4*>(&FS2[jq * 4]);
        float4 f01 = fsp[0], f23 = fsp[1];
#pragma unroll
        for (int qq = 0; qq < 4; ++qq) {
            int r_ = srow + qq * 16;
            uint32_t mw = maskb[r_ * 128 + jq];
            float E1 = E1r[qq], E2 = E2r[qq];
            float p0 = mask_trunc(fmaxf(E1 * f01.x, E2 * f01.y), __byte_perm(mw, 0, 0x0000));
            float p1 = mask_trunc(fmaxf(E1 * f01.z, E2 * f01.w), __byte_perm(mw, 0, 0x1111));
            float p2 = mask_trunc(fmaxf(E1 * f23.x, E2 * f23.y), __byte_perm(mw, 0, 0x2222));
            float p3 = mask_trunc(fmaxf(E1 * f23.z, E2 * f23.w), __byte_perm(mw, 0, 0x3333));
            zl[qq] += (p0 + p1) + (p2 + p3);
            *reinterpret_cast<float4*>(&PSf[r_ * 32 + swz4(r_, jq)]) =
                make_float4(p0, p1, p2, p3);
        }
    }
    CP_WAIT0();
    __syncthreads();

#pragma unroll 1
    for (int t = 0; t < 16; ++t) {
        const int cur = t & 1, nxt = cur ^ 1;

        if (t < 15) {
            const int tj1 = (t + 1) * 32;
#pragma unroll
            for (int k = 0; k < 8; ++k) {
                int row = srow + k * 16;
                int so = row * 32 + swz4(row, jq);
                cp16(ws_base + (uint32_t)(nxt * TILE_F + so) * 4,
                     WhTl + (size_t)row * 512 + tj1 + jq * 4);
            }
            CP_COMMIT();

            const float4* fsp = reinterpret_cast<const float4*>(&FS2[tj1 + jq * 4]);
            float4 f01 = fsp[0], f23 = fsp[1];
            float* PSb = PSf + nxt * PS_F;
            const int wofs = (t + 1) * 8 + jq;
#pragma unroll
            for (int qq = 0; qq < 4; ++qq) {
                int r_ = srow + qq * 16;
                uint32_t mw = maskb[r_ * 128 + wofs];
                float E1 = E1r[qq], E2 = E2r[qq];
                float p0 = mask_trunc(fmaxf(E1 * f01.x, E2 * f01.y), __byte_perm(mw, 0, 0x0000));
                float p1 = mask_trunc(fmaxf(E1 * f01.z, E2 * f01.w), __byte_perm(mw, 0, 0x1111));
                float p2 = mask_trunc(fmaxf(E1 * f23.x, E2 * f23.y), __byte_perm(mw, 0, 0x2222));
                float p3 = mask_trunc(fmaxf(E1 * f23.z, E2 * f23.w), __byte_perm(mw, 0, 0x3333));
                zl[qq] += (p0 + p1) + (p2 + p3);
                *reinterpret_cast<float4*>(&PSb[r_ * 32 + swz4(r_, jq)]) =
                    make_float4(p0, p1, p2, p3);
            }
        }

        const uint32_t* PSu = reinterpret_cast<const uint32_t*>(PSf + cur * PS_F);
        const uint32_t* WSu = reinterpret_cast<const uint32_t*>(WSf + cur * TILE_F);
#pragma unroll
        for (int kk = 0; kk < 32; kk += 8) {
            const int k4a = kk >> 2, k4b = (kk >> 2) + 1;
            uint32_t bf0[8], bf1[8];
#pragma unroll
            for (int nf = 0; nf < 8; ++nf) {
                int f = wn * 64 + nf * 8 + g;
                bf0[nf] = WSu[f * 32 + ((k4a ^ g) << 2) + q];
                bf1[nf] = WSu[f * 32 + ((k4b ^ g) << 2) + q];
            }
#pragma unroll
            for (int mf = 0; mf < 2; ++mf) {
                int r_ = wm * 32 + mf * 16 + g;
                uint32_t a0 = PSu[r_ * 32 + ((k4a ^ g) << 2) + q];
                uint32_t a1 = PSu[(r_ + 8) * 32 + ((k4a ^ g) << 2) + q];
                uint32_t a2 = PSu[r_ * 32 + ((k4b ^ g) << 2) + q];
                uint32_t a3 = PSu[(r_ + 8) * 32 + ((k4b ^ g) << 2) + q];
#pragma unroll
                for (int nf = 0; nf < 8; ++nf)
                    mma_tf32(dacc[mf][nf], a0, a1, a2, a3, bf0[nf], bf1[nf]);
            }
        }

        if (t < 15) CP_WAIT0();
        __syncthreads();
    }

    // Z reduction — zpart aliases the (now dead) WS region
    float* zpartS = dyn + WS_OFF;   // 64 x 8
#pragma unroll
    for (int qq = 0; qq < 4; ++qq) zpartS[(srow + qq * 16) * 8 + jq] = zl[qq];
    __syncthreads();
    if (tid < 64) {
        float z = 0.f;
#pragma unroll
        for (int k = 0; k < 8; ++k) z += zpartS[tid * 8 + k];
        rZS[tid] = 1.f / z;
    }
    __syncthreads();

#pragma unroll
    for (int mf = 0; mf < 2; ++mf) {
#pragma unroll
        for (int h = 0; h < 2; ++h) {
            int rl = wm * 32 + mf * 16 + g + h * 8;
            float rz = rZS[rl];
            float* orow = outp + ((size_t)(b << 9) + i0 + rl) * ld + col0 + wn * 64;
#pragma unroll
            for (int nf = 0; nf < 8; ++nf) {
                float2 v;
                v.x = totf32(elu1(dacc[mf][nf][2 * h]     * rz));
                v.y = totf32(elu1(dacc[mf][nf][2 * h + 1] * rz));
                *reinterpret_cast<float2*>(&orow[nf * 8 + 2 * q]) = v;
            }
        }
    }
}

// ---------------- launch ----------------
extern "C" void kernel_launch(void* const* d_in, const int* in_sizes, int n_in,
                              void* d_out, int out_size)
{
    (void)in_sizes; (void)n_in; (void)out_size;
    const float* compound = (const float*)d_in[0];   // [64,512,34]
    const int*   adj      = (const int*)d_in[1];     // [64,512,512]
    const float* Wst      = (const float*)d_in[2];   // [3,34,128]
    const float* ast      = (const float*)d_in[3];   // [3,256,1]
    const float* Wout     = (const float*)d_in[4];   // [384,128]
    const float* aout     = (const float*)d_in[5];   // [256,1]
    const float* Wc       = (const float*)d_in[6];   // [128,256]
    const float* bc       = (const float*)d_in[7];   // [256]
    float* out = (float*)d_out;                      // [64,512,256]

    float* g_WhT_p;   cudaGetSymbolAddress((void**)&g_WhT_p,  g_WhT);
    float* g_heads_p; cudaGetSymbolAddress((void**)&g_heads_p, g_heads);
    float* g_x_p;     cudaGetSymbolAddress((void**)&g_x_p,    g_x);
    float* g_src_p;   cudaGetSymbolAddress((void**)&g_src_p,  g_src3);
    float* g_dst_p;   cudaGetSymbolAddress((void**)&g_dst_p,  g_dst3);
    uint32_t* g_mask_p; cudaGetSymbolAddress((void**)&g_mask_p, g_adjmask);
    float* g_WoutT_p; cudaGetSymbolAddress((void**)&g_WoutT_p, g_WoutT);
    float* g_WcT_p;   cudaGetSymbolAddress((void**)&g_WcT_p,   g_WcT);

    cudaFuncSetAttribute(k_agg_mma, cudaFuncAttributeMaxDynamicSharedMemorySize,
                         AGG_SMEM_BYTES);
    cudaFuncSetAttribute(k_mma<384, 384, 0>,
                         cudaFuncAttributeMaxDynamicSharedMemorySize, GEMM_SMEM_BYTES);
    cudaFuncSetAttribute(k_mma<128, 128, 1>,
                         cudaFuncAttributeMaxDynamicSharedMemorySize, GEMM_SMEM_BYTES);

    k_pack<<<(R * 128) / 256, 256>>>(adj, g_mask_p);
    k_prepT<<<(128 * 384 + 256 * 128 + 255) / 256, 256>>>(Wout, Wc, g_WoutT_p, g_WcT_p);

    // 3 input-layer projections
    k_proj<34, 34><<<dim3(N / 64, B, 3), 256>>>(
        compound, 34, Wst, ast, g_WhT_p, g_src_p, g_dst_p);

    // 3 head aggregations (64-row CTAs, 4 CTAs/SM)
    k_agg_mma<<<dim3(N / 64, B, 3), 128, AGG_SMEM_BYTES>>>(
        g_mask_p, g_WhT_p, g_src_p, g_dst_p, g_heads_p, 384);

    // out-layer projection (mma GEMM, fused src/dst + transposed WhT store)
    k_mma<384, 384, 0><<<dim3(R / 128, 1), 256, GEMM_SMEM_BYTES>>>(
        g_heads_p, g_WoutT_p, aout,
        g_WhT_p + (size_t)3 * R * 128, g_src_p + (size_t)3 * R, g_dst_p + (size_t)3 * R);

    // out-layer aggregation
    k_agg_mma<<<dim3(N / 64, B, 1), 128, AGG_SMEM_BYTES>>>(
        g_mask_p, g_WhT_p + (size_t)3 * R * 128,
        g_src_p + (size_t)3 * R, g_dst_p + (size_t)3 * R, g_x_p, 128);

    // final dense layer
    k_mma<128, 128, 1><<<dim3(R / 128, 2), 256, GEMM_SMEM_BYTES>>>(
        g_x_p, g_WcT_p, bc, out, nullptr, nullptr);
}